// round 8
// baseline (speedup 1.0000x reference)
#include <cuda_runtime.h>
#include <cuda_bf16.h>
#include <cstdint>
#include <math.h>

// ---------------- problem constants ----------------
#define D_MODEL  2048
#define N_HEADS  16
#define HEAD_DIM 128
#define BATCH    2
#define SEQ      2048
#define M_TOT    (BATCH * SEQ)      // 4096 rows
#define N_QKV    (3 * D_MODEL)      // 6144 fused QKV width

// ---------------- scratch (alloc-free rule: __device__ globals) ----------------
__device__ float g_QKV[M_TOT * N_QKV];     // [token][Q(2048) | K(2048) | V(2048)]
__device__ float g_C[M_TOT * D_MODEL];     // attention context

__device__ __nv_bfloat16 g_xh[M_TOT * D_MODEL];
__device__ __nv_bfloat16 g_xl[M_TOT * D_MODEL];
__device__ __nv_bfloat16 g_ch[M_TOT * D_MODEL];
__device__ __nv_bfloat16 g_cl[M_TOT * D_MODEL];
__device__ __nv_bfloat16 g_Wh[4 * D_MODEL * D_MODEL];   // Wq,Wk,Wv,Wo packed
__device__ __nv_bfloat16 g_Wl[4 * D_MODEL * D_MODEL];

// ============================================================================
// PTX helpers (compute_103-safe: mma.sync / ldmatrix / cp.async only)
// ============================================================================
__device__ __forceinline__ uint32_t smem_u32(const void* p) {
    uint32_t a;
    asm("{ .reg .u64 t; cvta.to.shared.u64 t, %1; cvt.u32.u64 %0, t; }" : "=r"(a) : "l"(p));
    return a;
}
__device__ __forceinline__ void ldmatrix_x4(uint32_t* r, uint32_t addr) {
    asm volatile("ldmatrix.sync.aligned.m8n8.x4.shared.b16 {%0,%1,%2,%3}, [%4];"
                 : "=r"(r[0]), "=r"(r[1]), "=r"(r[2]), "=r"(r[3]) : "r"(addr));
}
__device__ __forceinline__ void mma_bf16(float* c, const uint32_t* a, const uint32_t* b) {
    asm volatile(
        "mma.sync.aligned.m16n8k16.row.col.f32.bf16.bf16.f32 "
        "{%0,%1,%2,%3}, {%4,%5,%6,%7}, {%8,%9}, {%0,%1,%2,%3};"
        : "+f"(c[0]), "+f"(c[1]), "+f"(c[2]), "+f"(c[3])
        : "r"(a[0]), "r"(a[1]), "r"(a[2]), "r"(a[3]), "r"(b[0]), "r"(b[1]));
}
__device__ __forceinline__ void cp16(uint32_t s, const void* g) {
    asm volatile("cp.async.cg.shared.global [%0], [%1], 16;" :: "r"(s), "l"(g));
}
__device__ __forceinline__ void cp_commit() {
    asm volatile("cp.async.commit_group;" ::: "memory");
}
__device__ __forceinline__ void cp_wait_1() {
    asm volatile("cp.async.wait_group 1;" ::: "memory");
}

// ============================================================================
// fp32 -> bf16 hi/lo split conversion (vectorized)
// ============================================================================
__device__ __forceinline__ void cvt_one(const float* __restrict__ in,
                                        __nv_bfloat16* __restrict__ hi,
                                        __nv_bfloat16* __restrict__ lo,
                                        size_t i /* float4 index */)
{
    float4 v = ((const float4*)in)[i];
    __nv_bfloat16 h0 = __float2bfloat16(v.x), h1 = __float2bfloat16(v.y);
    __nv_bfloat16 h2 = __float2bfloat16(v.z), h3 = __float2bfloat16(v.w);
    __nv_bfloat16 l0 = __float2bfloat16(v.x - __bfloat162float(h0));
    __nv_bfloat16 l1 = __float2bfloat16(v.y - __bfloat162float(h1));
    __nv_bfloat16 l2 = __float2bfloat16(v.z - __bfloat162float(h2));
    __nv_bfloat16 l3 = __float2bfloat16(v.w - __bfloat162float(h3));
    __nv_bfloat162* hp = (__nv_bfloat162*)hi;
    __nv_bfloat162* lp = (__nv_bfloat162*)lo;
    __nv_bfloat162 a; a.x = h0; a.y = h1; hp[2*i] = a;
    __nv_bfloat162 b; b.x = h2; b.y = h3; hp[2*i+1] = b;
    __nv_bfloat162 c; c.x = l0; c.y = l1; lp[2*i] = c;
    __nv_bfloat162 d; d.x = l2; d.y = l3; lp[2*i+1] = d;
}

__global__ void cvt_kernel(const float* __restrict__ in,
                           __nv_bfloat16* __restrict__ hi,
                           __nv_bfloat16* __restrict__ lo, int n4)
{
    int i = blockIdx.x * blockDim.x + threadIdx.x;
    if (i >= n4) return;
    cvt_one(in, hi, lo, (size_t)i);
}

// all 4 weight matrices in one launch; outputs packed into g_Wh/g_Wl
__global__ void cvt4_kernel(const float* __restrict__ w0, const float* __restrict__ w1,
                            const float* __restrict__ w2, const float* __restrict__ w3,
                            __nv_bfloat16* __restrict__ hi,
                            __nv_bfloat16* __restrict__ lo, int n4each)
{
    int i = blockIdx.x * blockDim.x + threadIdx.x;
    if (i >= n4each) return;
    const float* in = (blockIdx.y == 0) ? w0 : (blockIdx.y == 1) ? w1
                    : (blockIdx.y == 2) ? w2 : w3;
    size_t base4 = (size_t)blockIdx.y * n4each;     // float4 units
    cvt_one(in, hi + base4 * 4, lo + base4 * 4, (size_t)i);
}

// ============================================================================
// bf16x3 GEMM via mma.sync: C[m,n] = sum_k A[m,k]*B[n,k]
// CTA 128x128, 256 threads (8 warps, warp tile 64x32 = 4 SMSP-pairs).
// BK=32, 3-stage pipeline (32KB/stage, 96KB smem), 2 CTAs/SM -> 4 warps/SMSP.
// ONE __syncthreads per iteration:
//   wait_group(1) -> sync -> issue stage c+2 into buf (c-1)%3 -> compute c.
// ============================================================================
#define BK        32
#define NITER     (D_MODEL / BK)          // 64
#define OFF_AH    0
#define OFF_AL    8192
#define OFF_BH    16384
#define OFF_BL    24576
#define STAGE_B3  32768                   // 32 KB per stage
#define SMEM_GEMM (3 * STAGE_B3 + 128)

__device__ __forceinline__ uint32_t sw_off(int row, int chunk) {
    return (uint32_t)(row * 64 + ((chunk ^ ((row >> 1) & 3)) << 4));
}

__device__ __forceinline__ void issue_stage(
    uint32_t stage,
    const __nv_bfloat16* __restrict__ Ah, const __nv_bfloat16* __restrict__ Al,
    const __nv_bfloat16* __restrict__ Bh, const __nv_bfloat16* __restrict__ Bl,
    int bm, int bn, int k0, int tid)
{
#pragma unroll
    for (int j = 0; j < 2; j++) {
        int idx = tid + 256 * j;            // 0..511
        int row = idx >> 2;                 // 0..127
        int ch  = idx & 3;
        uint32_t so = sw_off(row, ch);
        size_t ga = (size_t)(bm + row) * D_MODEL + k0 + ch * 8;
        size_t gb = (size_t)(bn + row) * D_MODEL + k0 + ch * 8;
        cp16(stage + OFF_AH + so, Ah + ga);
        cp16(stage + OFF_AL + so, Al + ga);
        cp16(stage + OFF_BH + so, Bh + gb);
        cp16(stage + OFF_BL + so, Bl + gb);
    }
}

__global__ void __launch_bounds__(256, 2) mma_gemm_kernel(
    const __nv_bfloat16* __restrict__ Ah, const __nv_bfloat16* __restrict__ Al,
    const __nv_bfloat16* __restrict__ Bh, const __nv_bfloat16* __restrict__ Bl,
    float* __restrict__ C, int ldc)
{
    extern __shared__ char sm_raw[];
    const uint32_t sbase = (smem_u32(sm_raw) + 127u) & ~127u;

    const int tid  = threadIdx.x;
    const int lane = tid & 31;
    const int w    = tid >> 5;
    const int wm   = (w & 1) * 64;      // warp m offset (0/64)
    const int wn   = (w >> 1) * 32;     // warp n offset (0/32/64/96)
    const int bm   = blockIdx.y * 128;
    const int bn   = blockIdx.x * 128;

    // ldmatrix lane addressing (verified R5/R7)
    const int g  = lane >> 3;
    const int li = lane & 7;
    const int aRowL = li + ((g & 1) << 3);
    const int aChL  = g >> 1;
    const int bRowL = li + ((g >> 1) << 3);
    const int bChL  = g & 1;

    float acc[4][4][4];
#pragma unroll
    for (int mi = 0; mi < 4; mi++)
#pragma unroll
        for (int ni = 0; ni < 4; ni++)
#pragma unroll
            for (int r = 0; r < 4; r++) acc[mi][ni][r] = 0.f;

    // prologue: stages 0,1
    issue_stage(sbase + 0 * STAGE_B3, Ah, Al, Bh, Bl, bm, bn, 0, tid);
    cp_commit();
    issue_stage(sbase + 1 * STAGE_B3, Ah, Al, Bh, Bl, bm, bn, BK, tid);
    cp_commit();

    int buf = 0;                  // c % 3
    int ibuf = 2;                 // (c+2) % 3  == (c-1)%3, free after the sync
    for (int c = 0; c < NITER; c++) {
        cp_wait_1();              // stage c resident (c+1 may still fly)
        __syncthreads();          // copies visible + all warps done with iter c-1

        if (c + 2 < NITER) {      // refill the buffer freed by iter c-1
            issue_stage(sbase + (uint32_t)ibuf * STAGE_B3, Ah, Al, Bh, Bl,
                        bm, bn, (c + 2) * BK, tid);
        }
        cp_commit();

        const uint32_t st  = sbase + (uint32_t)buf * STAGE_B3;
        const uint32_t tAh = st + OFF_AH;
        const uint32_t tAl = st + OFF_AL;
        const uint32_t tBh = st + OFF_BH;
        const uint32_t tBl = st + OFF_BL;

#pragma unroll
        for (int ks = 0; ks < 2; ks++) {
            const int aCh = 2 * ks + aChL;
            const int bCh = 2 * ks + bChL;

            uint32_t ah[4][4], bh[4][2], bl[4][2];
#pragma unroll
            for (int mi = 0; mi < 4; mi++)
                ldmatrix_x4(ah[mi], tAh + sw_off(wm + mi * 16 + aRowL, aCh));
#pragma unroll
            for (int p = 0; p < 2; p++) {
                uint32_t t4[4];
                ldmatrix_x4(t4, tBh + sw_off(wn + p * 16 + bRowL, bCh));
                bh[2 * p][0] = t4[0]; bh[2 * p][1] = t4[1];
                bh[2 * p + 1][0] = t4[2]; bh[2 * p + 1][1] = t4[3];
                ldmatrix_x4(t4, tBl + sw_off(wn + p * 16 + bRowL, bCh));
                bl[2 * p][0] = t4[0]; bl[2 * p][1] = t4[1];
                bl[2 * p + 1][0] = t4[2]; bl[2 * p + 1][1] = t4[3];
            }

#pragma unroll
            for (int mi = 0; mi < 4; mi++)
#pragma unroll
                for (int ni = 0; ni < 4; ni++)
                    mma_bf16(acc[mi][ni], ah[mi], bh[ni]);
#pragma unroll
            for (int mi = 0; mi < 4; mi++)
#pragma unroll
                for (int ni = 0; ni < 4; ni++)
                    mma_bf16(acc[mi][ni], ah[mi], bl[ni]);

            uint32_t al[4][4];
#pragma unroll
            for (int mi = 0; mi < 4; mi++)
                ldmatrix_x4(al[mi], tAl + sw_off(wm + mi * 16 + aRowL, aCh));
#pragma unroll
            for (int mi = 0; mi < 4; mi++)
#pragma unroll
                for (int ni = 0; ni < 4; ni++)
                    mma_bf16(acc[mi][ni], al[mi], bh[ni]);
        }

        buf  = (buf == 2)  ? 0 : buf + 1;
        ibuf = (ibuf == 2) ? 0 : ibuf + 1;
    }

    // epilogue: direct float2 stores
    const int gid = lane >> 2;
    const int tig = lane & 3;
#pragma unroll
    for (int mi = 0; mi < 4; mi++) {
#pragma unroll
        for (int ni = 0; ni < 4; ni++) {
            int row = bm + wm + mi * 16 + gid;
            int col = bn + wn + ni * 8 + tig * 2;
            float2 v0 = make_float2(acc[mi][ni][0], acc[mi][ni][1]);
            float2 v1 = make_float2(acc[mi][ni][2], acc[mi][ni][3]);
            *(float2*)(C + (size_t)row * ldc + col) = v0;
            *(float2*)(C + (size_t)(row + 8) * ldc + col) = v1;
        }
    }
}

// ============================================================================
// RoPE in-place on the fused QKV buffer (Q at col 0, K at col 2048; stride 6144)
// ============================================================================
__global__ void rope_kernel(float* __restrict__ QKV, const int* __restrict__ pos)
{
    int idx = blockIdx.x * blockDim.x + threadIdx.x;
    const int total = BATCH * SEQ * N_HEADS * (HEAD_DIM / 2);
    if (idx >= total) return;

    int i  = idx & 63;
    int h  = (idx >> 6) & (N_HEADS - 1);
    int ss = (idx >> 10) & (SEQ - 1);
    int b  = idx >> 21;

    int p = pos[b * SEQ + ss];
    float inv_freq = powf(10000.0f, -(2.0f * (float)i) / 128.0f);
    float ang = (float)p * inv_freq;
    float s, c;
    sincosf(ang, &s, &c);

    size_t base = ((size_t)(b * SEQ + ss)) * N_QKV + h * HEAD_DIM + 2 * i;
    float qe = QKV[base], qo = QKV[base + 1];
    QKV[base]     = qe * c - qo * s;
    QKV[base + 1] = qe * s + qo * c;
    size_t kb = base + D_MODEL;
    float ke = QKV[kb], ko = QKV[kb + 1];
    QKV[kb]     = ke * c - ko * s;
    QKV[kb + 1] = ke * s + ko * c;
}

// ============================================================================
// Causal flash attention, fp32 (unchanged; Q/K/V strided 6144 in fused buffer).
// ============================================================================
#define BQ 64
#define BKF 32

__global__ __launch_bounds__(256) void flash_kernel(const float* __restrict__ Q,
                                                    const float* __restrict__ K,
                                                    const float* __restrict__ V,
                                                    float* __restrict__ O)
{
    __shared__ float Ks[BKF][HEAD_DIM];
    __shared__ float Vs[BKF][HEAD_DIM];
    __shared__ float Ps[BQ][BKF];

    const int bh = blockIdx.y;
    const int b  = bh / N_HEADS;
    const int h  = bh % N_HEADS;
    const int q0 = blockIdx.x * BQ;

    const int tid  = threadIdx.x;
    const int row  = tid >> 2;
    const int part = tid & 3;
    const int qg   = q0 + row;

    const float scale = 0.08838834764831845f;

    float qf[32];
    const float* qp = Q + ((size_t)(b * SEQ + qg)) * N_QKV + h * HEAD_DIM + part * 32;
#pragma unroll
    for (int i = 0; i < 32; i += 4)
        *(float4*)(qf + i) = *(const float4*)(qp + i);

    float acc[32];
#pragma unroll
    for (int i = 0; i < 32; i++) acc[i] = 0.f;
    float m = -1e30f, l = 0.f;

    const int kend = q0 + BQ;
    for (int k0 = 0; k0 < kend; k0 += BKF) {
        __syncthreads();
        {
            const size_t rbase = (size_t)(b * SEQ + k0) * N_QKV + h * HEAD_DIM;
            for (int idx = tid; idx < BKF * (HEAD_DIM / 4); idx += 256) {
                int r = idx >> 5;
                int c = (idx & 31) * 4;
                ((float4*)Ks)[idx] = *(const float4*)(K + rbase + (size_t)r * N_QKV + c);
                ((float4*)Vs)[idx] = *(const float4*)(V + rbase + (size_t)r * N_QKV + c);
            }
        }
        __syncthreads();

        float sv[BKF / 4];
        float mblk = -1e30f;
#pragma unroll
        for (int j = 0; j < BKF; j++) {
            const float* kr = &Ks[j][part * 32];
            float d = 0.f;
#pragma unroll
            for (int i = 0; i < 32; i++) d = fmaf(qf[i], kr[i], d);
            d += __shfl_xor_sync(0xffffffffu, d, 1);
            d += __shfl_xor_sync(0xffffffffu, d, 2);
            d *= scale;
            int kg = k0 + j;
            d = (kg <= qg) ? d : -1e30f;
            if ((j & 3) == part) sv[j >> 2] = d;
            mblk = fmaxf(mblk, d);
        }

        float mnew  = fmaxf(m, mblk);
        float alpha = __expf(m - mnew);
        float ladd  = 0.f;
#pragma unroll
        for (int jj = 0; jj < BKF / 4; jj++) {
            float p = __expf(sv[jj] - mnew);
            ladd += p;
            Ps[row][jj * 4 + part] = p;
        }
        ladd += __shfl_xor_sync(0xffffffffu, ladd, 1);
        ladd += __shfl_xor_sync(0xffffffffu, ladd, 2);
        l = l * alpha + ladd;
        m = mnew;
#pragma unroll
        for (int i = 0; i < 32; i++) acc[i] *= alpha;
        __syncwarp();

#pragma unroll 4
        for (int j = 0; j < BKF; j++) {
            float p = Ps[row][j];
            const float* vr = &Vs[j][part * 32];
#pragma unroll
            for (int i = 0; i < 32; i++) acc[i] = fmaf(p, vr[i], acc[i]);
        }
    }

    float inv_l = 1.0f / l;
    float* op = O + ((size_t)(b * SEQ + qg)) * D_MODEL + h * HEAD_DIM + part * 32;
#pragma unroll
    for (int i = 0; i < 32; i++) op[i] = acc[i] * inv_l;
}

// ============================================================================
// launch
// ============================================================================
extern "C" void kernel_launch(void* const* d_in, const int* in_sizes, int n_in,
                              void* d_out, int out_size)
{
    const float* x   = (const float*)d_in[0];
    const int*   pos = (const int*)  d_in[1];
    const float* Wq  = (const float*)d_in[2];
    const float* Wk  = (const float*)d_in[3];
    const float* Wv  = (const float*)d_in[4];
    const float* Wo  = (const float*)d_in[5];
    float* out = (float*)d_out;

    float *QKVb, *Cb;
    __nv_bfloat16 *xh, *xl, *ch, *cl, *Wh, *Wl;
    cudaGetSymbolAddress((void**)&QKVb, g_QKV);
    cudaGetSymbolAddress((void**)&Cb, g_C);
    cudaGetSymbolAddress((void**)&xh, g_xh);
    cudaGetSymbolAddress((void**)&xl, g_xl);
    cudaGetSymbolAddress((void**)&ch, g_ch);
    cudaGetSymbolAddress((void**)&cl, g_cl);
    cudaGetSymbolAddress((void**)&Wh, g_Wh);
    cudaGetSymbolAddress((void**)&Wl, g_Wl);

    cudaFuncSetAttribute(mma_gemm_kernel,
                         cudaFuncAttributeMaxDynamicSharedMemorySize, SMEM_GEMM);

    const int x_n4 = (M_TOT * D_MODEL) / 4;
    const int w_n4 = (D_MODEL * D_MODEL) / 4;

    // split conversions (2 launches)
    cvt_kernel<<<(x_n4 + 255) / 256, 256>>>(x, xh, xl, x_n4);
    dim3 wGrid((w_n4 + 255) / 256, 4);
    cvt4_kernel<<<wGrid, 256>>>(Wq, Wk, Wv, Wo, Wh, Wl, w_n4);

    // fused QKV projection: B rows 0..6143 = [Wq;Wk;Wv]
    dim3 qkvGrid(N_QKV / 128, M_TOT / 128);     // (48, 32)
    mma_gemm_kernel<<<qkvGrid, 256, SMEM_GEMM>>>(xh, xl, Wh, Wl, QKVb, N_QKV);

    int ropeTotal = BATCH * SEQ * N_HEADS * (HEAD_DIM / 2);
    rope_kernel<<<(ropeTotal + 255) / 256, 256>>>(QKVb, pos);

    dim3 flashGrid(SEQ / BQ, BATCH * N_HEADS);   // (32, 32)
    flash_kernel<<<flashGrid, 256>>>(QKVb, QKVb + D_MODEL, QKVb + 2 * D_MODEL, Cb);

    // output projection
    cvt_kernel<<<(x_n4 + 255) / 256, 256>>>(Cb, ch, cl, x_n4);
    dim3 oGrid(D_MODEL / 128, M_TOT / 128);      // (16, 32)
    mma_gemm_kernel<<<oGrid, 256, SMEM_GEMM>>>(ch, cl,
        Wh + 3 * (size_t)D_MODEL * D_MODEL, Wl + 3 * (size_t)D_MODEL * D_MODEL,
        out, D_MODEL);
}

// round 9
// speedup vs baseline: 1.0312x; 1.0312x over previous
#include <cuda_runtime.h>
#include <cuda_bf16.h>
#include <cuda_fp16.h>
#include <cstdint>
#include <math.h>

// ---------------- problem constants ----------------
#define D_MODEL  2048
#define N_HEADS  16
#define HEAD_DIM 128
#define BATCH    2
#define SEQ      2048
#define M_TOT    (BATCH * SEQ)      // 4096 rows
#define N_QKV    (3 * D_MODEL)      // 6144 fused QKV width
#define N_QK     (2 * D_MODEL)      // 4096 fused QK width

// ---------------- scratch (alloc-free rule: __device__ globals) ----------------
__device__ float g_QKV[M_TOT * N_QKV];     // [token][Q(2048) | K(2048) | V(2048)]
__device__ float g_C[M_TOT * D_MODEL];     // attention context

// bf16 split operands (high-precision path: Q,K projections)
__device__ __nv_bfloat16 g_xh[M_TOT * D_MODEL];
__device__ __nv_bfloat16 g_xl[M_TOT * D_MODEL];
__device__ __nv_bfloat16 g_Wh[2 * D_MODEL * D_MODEL];   // [Wq;Wk]
__device__ __nv_bfloat16 g_Wl[2 * D_MODEL * D_MODEL];

// fp16 single-pass operands (V projection, output projection)
__device__ __half g_xf [M_TOT * D_MODEL];
__device__ __half g_cf [M_TOT * D_MODEL];
__device__ __half g_Wvf[D_MODEL * D_MODEL];
__device__ __half g_Wof[D_MODEL * D_MODEL];

// ============================================================================
// PTX helpers (compute_103-safe: mma.sync / ldmatrix / cp.async only)
// ============================================================================
__device__ __forceinline__ uint32_t smem_u32(const void* p) {
    uint32_t a;
    asm("{ .reg .u64 t; cvta.to.shared.u64 t, %1; cvt.u32.u64 %0, t; }" : "=r"(a) : "l"(p));
    return a;
}
__device__ __forceinline__ void ldmatrix_x4(uint32_t* r, uint32_t addr) {
    asm volatile("ldmatrix.sync.aligned.m8n8.x4.shared.b16 {%0,%1,%2,%3}, [%4];"
                 : "=r"(r[0]), "=r"(r[1]), "=r"(r[2]), "=r"(r[3]) : "r"(addr));
}
__device__ __forceinline__ void mma_bf16(float* c, const uint32_t* a, const uint32_t* b) {
    asm volatile(
        "mma.sync.aligned.m16n8k16.row.col.f32.bf16.bf16.f32 "
        "{%0,%1,%2,%3}, {%4,%5,%6,%7}, {%8,%9}, {%0,%1,%2,%3};"
        : "+f"(c[0]), "+f"(c[1]), "+f"(c[2]), "+f"(c[3])
        : "r"(a[0]), "r"(a[1]), "r"(a[2]), "r"(a[3]), "r"(b[0]), "r"(b[1]));
}
__device__ __forceinline__ void mma_f16(float* c, const uint32_t* a, const uint32_t* b) {
    asm volatile(
        "mma.sync.aligned.m16n8k16.row.col.f32.f16.f16.f32 "
        "{%0,%1,%2,%3}, {%4,%5,%6,%7}, {%8,%9}, {%0,%1,%2,%3};"
        : "+f"(c[0]), "+f"(c[1]), "+f"(c[2]), "+f"(c[3])
        : "r"(a[0]), "r"(a[1]), "r"(a[2]), "r"(a[3]), "r"(b[0]), "r"(b[1]));
}
__device__ __forceinline__ void cp16(uint32_t s, const void* g) {
    asm volatile("cp.async.cg.shared.global [%0], [%1], 16;" :: "r"(s), "l"(g));
}
__device__ __forceinline__ void cp_commit() {
    asm volatile("cp.async.commit_group;" ::: "memory");
}
__device__ __forceinline__ void cp_wait_1() {
    asm volatile("cp.async.wait_group 1;" ::: "memory");
}

// ============================================================================
// conversions
// ============================================================================
__device__ __forceinline__ void cvt_one(const float* __restrict__ in,
                                        __nv_bfloat16* __restrict__ hi,
                                        __nv_bfloat16* __restrict__ lo,
                                        size_t i)
{
    float4 v = ((const float4*)in)[i];
    __nv_bfloat16 h0 = __float2bfloat16(v.x), h1 = __float2bfloat16(v.y);
    __nv_bfloat16 h2 = __float2bfloat16(v.z), h3 = __float2bfloat16(v.w);
    __nv_bfloat16 l0 = __float2bfloat16(v.x - __bfloat162float(h0));
    __nv_bfloat16 l1 = __float2bfloat16(v.y - __bfloat162float(h1));
    __nv_bfloat16 l2 = __float2bfloat16(v.z - __bfloat162float(h2));
    __nv_bfloat16 l3 = __float2bfloat16(v.w - __bfloat162float(h3));
    __nv_bfloat162* hp = (__nv_bfloat162*)hi;
    __nv_bfloat162* lp = (__nv_bfloat162*)lo;
    __nv_bfloat162 a; a.x = h0; a.y = h1; hp[2*i] = a;
    __nv_bfloat162 b; b.x = h2; b.y = h3; hp[2*i+1] = b;
    __nv_bfloat162 c; c.x = l0; c.y = l1; lp[2*i] = c;
    __nv_bfloat162 d; d.x = l2; d.y = l3; lp[2*i+1] = d;
}

__global__ void cvt_kernel(const float* __restrict__ in,
                           __nv_bfloat16* __restrict__ hi,
                           __nv_bfloat16* __restrict__ lo, int n4)
{
    int i = blockIdx.x * blockDim.x + threadIdx.x;
    if (i >= n4) return;
    cvt_one(in, hi, lo, (size_t)i);
}

// Wq,Wk bf16 split into packed buffer (2 slices)
__global__ void cvt2_kernel(const float* __restrict__ w0, const float* __restrict__ w1,
                            __nv_bfloat16* __restrict__ hi,
                            __nv_bfloat16* __restrict__ lo, int n4each)
{
    int i = blockIdx.x * blockDim.x + threadIdx.x;
    if (i >= n4each) return;
    const float* in = (blockIdx.y == 0) ? w0 : w1;
    size_t base4 = (size_t)blockIdx.y * n4each;
    cvt_one(in, hi + base4 * 4, lo + base4 * 4, (size_t)i);
}

// fp32 -> fp16 (round-nearest)
__global__ void cvt_h_kernel(const float* __restrict__ in,
                             __half* __restrict__ out, int n4)
{
    int i = blockIdx.x * blockDim.x + threadIdx.x;
    if (i >= n4) return;
    float4 v = ((const float4*)in)[i];
    __half2* op = (__half2*)out;
    op[2*i]   = __floats2half2_rn(v.x, v.y);
    op[2*i+1] = __floats2half2_rn(v.z, v.w);
}

// ============================================================================
// shared GEMM geometry:
// CTA 128x128, 256 threads (8 warps, warp tile 64x32), BK=32, 3-stage cp.async.
// SMEM tile: [128 rows][4 x 16B chunks], chunk ^= (row>>1)&3 (conflict-free).
// ============================================================================
#define BK        32
#define NITER     (D_MODEL / BK)          // 64

__device__ __forceinline__ uint32_t sw_off(int row, int chunk) {
    return (uint32_t)(row * 64 + ((chunk ^ ((row >> 1) & 3)) << 4));
}

// ---------------------------------------------------------------------------
// bf16x3 GEMM (AhBh + AhBl + AlBh): Q,K projections
// ---------------------------------------------------------------------------
#define OFF_AH    0
#define OFF_AL    8192
#define OFF_BH    16384
#define OFF_BL    24576
#define STAGE_B3  32768
#define SMEM_G3   (3 * STAGE_B3 + 128)

__device__ __forceinline__ void issue_stage3(
    uint32_t stage,
    const __nv_bfloat16* __restrict__ Ah, const __nv_bfloat16* __restrict__ Al,
    const __nv_bfloat16* __restrict__ Bh, const __nv_bfloat16* __restrict__ Bl,
    int bm, int bn, int k0, int tid)
{
#pragma unroll
    for (int j = 0; j < 2; j++) {
        int idx = tid + 256 * j;
        int row = idx >> 2;
        int ch  = idx & 3;
        uint32_t so = sw_off(row, ch);
        size_t ga = (size_t)(bm + row) * D_MODEL + k0 + ch * 8;
        size_t gb = (size_t)(bn + row) * D_MODEL + k0 + ch * 8;
        cp16(stage + OFF_AH + so, Ah + ga);
        cp16(stage + OFF_AL + so, Al + ga);
        cp16(stage + OFF_BH + so, Bh + gb);
        cp16(stage + OFF_BL + so, Bl + gb);
    }
}

__global__ void __launch_bounds__(256, 2) mma_gemm3_kernel(
    const __nv_bfloat16* __restrict__ Ah, const __nv_bfloat16* __restrict__ Al,
    const __nv_bfloat16* __restrict__ Bh, const __nv_bfloat16* __restrict__ Bl,
    float* __restrict__ C, int ldc)
{
    extern __shared__ char sm_raw[];
    const uint32_t sbase = (smem_u32(sm_raw) + 127u) & ~127u;

    const int tid  = threadIdx.x;
    const int lane = tid & 31;
    const int w    = tid >> 5;
    const int wm   = (w & 1) * 64;
    const int wn   = (w >> 1) * 32;
    const int bm   = blockIdx.y * 128;
    const int bn   = blockIdx.x * 128;

    const int g  = lane >> 3;
    const int li = lane & 7;
    const int aRowL = li + ((g & 1) << 3);
    const int aChL  = g >> 1;
    const int bRowL = li + ((g >> 1) << 3);
    const int bChL  = g & 1;

    float acc[4][4][4];
#pragma unroll
    for (int mi = 0; mi < 4; mi++)
#pragma unroll
        for (int ni = 0; ni < 4; ni++)
#pragma unroll
            for (int r = 0; r < 4; r++) acc[mi][ni][r] = 0.f;

    issue_stage3(sbase + 0 * STAGE_B3, Ah, Al, Bh, Bl, bm, bn, 0, tid);
    cp_commit();
    issue_stage3(sbase + 1 * STAGE_B3, Ah, Al, Bh, Bl, bm, bn, BK, tid);
    cp_commit();

    int buf = 0, ibuf = 2;
    for (int c = 0; c < NITER; c++) {
        cp_wait_1();
        __syncthreads();
        if (c + 2 < NITER)
            issue_stage3(sbase + (uint32_t)ibuf * STAGE_B3, Ah, Al, Bh, Bl,
                         bm, bn, (c + 2) * BK, tid);
        cp_commit();

        const uint32_t st  = sbase + (uint32_t)buf * STAGE_B3;
        const uint32_t tAh = st + OFF_AH;
        const uint32_t tAl = st + OFF_AL;
        const uint32_t tBh = st + OFF_BH;
        const uint32_t tBl = st + OFF_BL;

#pragma unroll
        for (int ks = 0; ks < 2; ks++) {
            const int aCh = 2 * ks + aChL;
            const int bCh = 2 * ks + bChL;

            uint32_t ah[4][4], bh[4][2], bl[4][2];
#pragma unroll
            for (int mi = 0; mi < 4; mi++)
                ldmatrix_x4(ah[mi], tAh + sw_off(wm + mi * 16 + aRowL, aCh));
#pragma unroll
            for (int p = 0; p < 2; p++) {
                uint32_t t4[4];
                ldmatrix_x4(t4, tBh + sw_off(wn + p * 16 + bRowL, bCh));
                bh[2 * p][0] = t4[0]; bh[2 * p][1] = t4[1];
                bh[2 * p + 1][0] = t4[2]; bh[2 * p + 1][1] = t4[3];
                ldmatrix_x4(t4, tBl + sw_off(wn + p * 16 + bRowL, bCh));
                bl[2 * p][0] = t4[0]; bl[2 * p][1] = t4[1];
                bl[2 * p + 1][0] = t4[2]; bl[2 * p + 1][1] = t4[3];
            }

#pragma unroll
            for (int mi = 0; mi < 4; mi++)
#pragma unroll
                for (int ni = 0; ni < 4; ni++)
                    mma_bf16(acc[mi][ni], ah[mi], bh[ni]);
#pragma unroll
            for (int mi = 0; mi < 4; mi++)
#pragma unroll
                for (int ni = 0; ni < 4; ni++)
                    mma_bf16(acc[mi][ni], ah[mi], bl[ni]);

            uint32_t al[4][4];
#pragma unroll
            for (int mi = 0; mi < 4; mi++)
                ldmatrix_x4(al[mi], tAl + sw_off(wm + mi * 16 + aRowL, aCh));
#pragma unroll
            for (int mi = 0; mi < 4; mi++)
#pragma unroll
                for (int ni = 0; ni < 4; ni++)
                    mma_bf16(acc[mi][ni], al[mi], bh[ni]);
        }
        buf  = (buf == 2)  ? 0 : buf + 1;
        ibuf = (ibuf == 2) ? 0 : ibuf + 1;
    }

    const int gid = lane >> 2;
    const int tig = lane & 3;
#pragma unroll
    for (int mi = 0; mi < 4; mi++) {
#pragma unroll
        for (int ni = 0; ni < 4; ni++) {
            int row = bm + wm + mi * 16 + gid;
            int col = bn + wn + ni * 8 + tig * 2;
            float2 v0 = make_float2(acc[mi][ni][0], acc[mi][ni][1]);
            float2 v1 = make_float2(acc[mi][ni][2], acc[mi][ni][3]);
            *(float2*)(C + (size_t)row * ldc + col) = v0;
            *(float2*)(C + (size_t)(row + 8) * ldc + col) = v1;
        }
    }
}

// ---------------------------------------------------------------------------
// fp16 single-pass GEMM: V projection + output projection
// ---------------------------------------------------------------------------
#define OFF_A1    0
#define OFF_B1    8192
#define STAGE_B1  16384
#define SMEM_G1   (3 * STAGE_B1 + 128)

__device__ __forceinline__ void issue_stage1(
    uint32_t stage,
    const __half* __restrict__ A, const __half* __restrict__ B,
    int bm, int bn, int k0, int tid)
{
#pragma unroll
    for (int j = 0; j < 2; j++) {
        int idx = tid + 256 * j;
        int row = idx >> 2;
        int ch  = idx & 3;
        uint32_t so = sw_off(row, ch);
        cp16(stage + OFF_A1 + so, A + (size_t)(bm + row) * D_MODEL + k0 + ch * 8);
        cp16(stage + OFF_B1 + so, B + (size_t)(bn + row) * D_MODEL + k0 + ch * 8);
    }
}

__global__ void __launch_bounds__(256, 2) mma_gemm1_kernel(
    const __half* __restrict__ A, const __half* __restrict__ B,
    float* __restrict__ C, int ldc)
{
    extern __shared__ char sm_raw[];
    const uint32_t sbase = (smem_u32(sm_raw) + 127u) & ~127u;

    const int tid  = threadIdx.x;
    const int lane = tid & 31;
    const int w    = tid >> 5;
    const int wm   = (w & 1) * 64;
    const int wn   = (w >> 1) * 32;
    const int bm   = blockIdx.y * 128;
    const int bn   = blockIdx.x * 128;

    const int g  = lane >> 3;
    const int li = lane & 7;
    const int aRowL = li + ((g & 1) << 3);
    const int aChL  = g >> 1;
    const int bRowL = li + ((g >> 1) << 3);
    const int bChL  = g & 1;

    float acc[4][4][4];
#pragma unroll
    for (int mi = 0; mi < 4; mi++)
#pragma unroll
        for (int ni = 0; ni < 4; ni++)
#pragma unroll
            for (int r = 0; r < 4; r++) acc[mi][ni][r] = 0.f;

    issue_stage1(sbase + 0 * STAGE_B1, A, B, bm, bn, 0, tid);
    cp_commit();
    issue_stage1(sbase + 1 * STAGE_B1, A, B, bm, bn, BK, tid);
    cp_commit();

    int buf = 0, ibuf = 2;
    for (int c = 0; c < NITER; c++) {
        cp_wait_1();
        __syncthreads();
        if (c + 2 < NITER)
            issue_stage1(sbase + (uint32_t)ibuf * STAGE_B1, A, B,
                         bm, bn, (c + 2) * BK, tid);
        cp_commit();

        const uint32_t st = sbase + (uint32_t)buf * STAGE_B1;
        const uint32_t tA = st + OFF_A1;
        const uint32_t tB = st + OFF_B1;

#pragma unroll
        for (int ks = 0; ks < 2; ks++) {
            const int aCh = 2 * ks + aChL;
            const int bCh = 2 * ks + bChL;

            uint32_t a4[4][4], b2[4][2];
#pragma unroll
            for (int mi = 0; mi < 4; mi++)
                ldmatrix_x4(a4[mi], tA + sw_off(wm + mi * 16 + aRowL, aCh));
#pragma unroll
            for (int p = 0; p < 2; p++) {
                uint32_t t4[4];
                ldmatrix_x4(t4, tB + sw_off(wn + p * 16 + bRowL, bCh));
                b2[2 * p][0] = t4[0]; b2[2 * p][1] = t4[1];
                b2[2 * p + 1][0] = t4[2]; b2[2 * p + 1][1] = t4[3];
            }
#pragma unroll
            for (int mi = 0; mi < 4; mi++)
#pragma unroll
                for (int ni = 0; ni < 4; ni++)
                    mma_f16(acc[mi][ni], a4[mi], b2[ni]);
        }
        buf  = (buf == 2)  ? 0 : buf + 1;
        ibuf = (ibuf == 2) ? 0 : ibuf + 1;
    }

    const int gid = lane >> 2;
    const int tig = lane & 3;
#pragma unroll
    for (int mi = 0; mi < 4; mi++) {
#pragma unroll
        for (int ni = 0; ni < 4; ni++) {
            int row = bm + wm + mi * 16 + gid;
            int col = bn + wn + ni * 8 + tig * 2;
            float2 v0 = make_float2(acc[mi][ni][0], acc[mi][ni][1]);
            float2 v1 = make_float2(acc[mi][ni][2], acc[mi][ni][3]);
            *(float2*)(C + (size_t)row * ldc + col) = v0;
            *(float2*)(C + (size_t)(row + 8) * ldc + col) = v1;
        }
    }
}

// ============================================================================
// RoPE in-place on the fused QKV buffer (Q col 0, K col 2048; stride 6144)
// ============================================================================
__global__ void rope_kernel(float* __restrict__ QKV, const int* __restrict__ pos)
{
    int idx = blockIdx.x * blockDim.x + threadIdx.x;
    const int total = BATCH * SEQ * N_HEADS * (HEAD_DIM / 2);
    if (idx >= total) return;

    int i  = idx & 63;
    int h  = (idx >> 6) & (N_HEADS - 1);
    int ss = (idx >> 10) & (SEQ - 1);
    int b  = idx >> 21;

    int p = pos[b * SEQ + ss];
    float inv_freq = powf(10000.0f, -(2.0f * (float)i) / 128.0f);
    float ang = (float)p * inv_freq;
    float s, c;
    sincosf(ang, &s, &c);

    size_t base = ((size_t)(b * SEQ + ss)) * N_QKV + h * HEAD_DIM + 2 * i;
    float qe = QKV[base], qo = QKV[base + 1];
    QKV[base]     = qe * c - qo * s;
    QKV[base + 1] = qe * s + qo * c;
    size_t kb = base + D_MODEL;
    float ke = QKV[kb], ko = QKV[kb + 1];
    QKV[kb]     = ke * c - ko * s;
    QKV[kb + 1] = ke * s + ko * c;
}

// ============================================================================
// Causal flash attention, fp32 (Q/K/V strided 6144 in fused buffer).
// ============================================================================
#define BQ 64
#define BKF 32

__global__ __launch_bounds__(256) void flash_kernel(const float* __restrict__ Q,
                                                    const float* __restrict__ K,
                                                    const float* __restrict__ V,
                                                    float* __restrict__ O)
{
    __shared__ float Ks[BKF][HEAD_DIM];
    __shared__ float Vs[BKF][HEAD_DIM];
    __shared__ float Ps[BQ][BKF];

    const int bh = blockIdx.y;
    const int b  = bh / N_HEADS;
    const int h  = bh % N_HEADS;
    const int q0 = blockIdx.x * BQ;

    const int tid  = threadIdx.x;
    const int row  = tid >> 2;
    const int part = tid & 3;
    const int qg   = q0 + row;

    const float scale = 0.08838834764831845f;

    float qf[32];
    const float* qp = Q + ((size_t)(b * SEQ + qg)) * N_QKV + h * HEAD_DIM + part * 32;
#pragma unroll
    for (int i = 0; i < 32; i += 4)
        *(float4*)(qf + i) = *(const float4*)(qp + i);

    float acc[32];
#pragma unroll
    for (int i = 0; i < 32; i++) acc[i] = 0.f;
    float m = -1e30f, l = 0.f;

    const int kend = q0 + BQ;
    for (int k0 = 0; k0 < kend; k0 += BKF) {
        __syncthreads();
        {
            const size_t rbase = (size_t)(b * SEQ + k0) * N_QKV + h * HEAD_DIM;
            for (int idx = tid; idx < BKF * (HEAD_DIM / 4); idx += 256) {
                int r = idx >> 5;
                int c = (idx & 31) * 4;
                ((float4*)Ks)[idx] = *(const float4*)(K + rbase + (size_t)r * N_QKV + c);
                ((float4*)Vs)[idx] = *(const float4*)(V + rbase + (size_t)r * N_QKV + c);
            }
        }
        __syncthreads();

        float sv[BKF / 4];
        float mblk = -1e30f;
#pragma unroll
        for (int j = 0; j < BKF; j++) {
            const float* kr = &Ks[j][part * 32];
            float d = 0.f;
#pragma unroll
            for (int i = 0; i < 32; i++) d = fmaf(qf[i], kr[i], d);
            d += __shfl_xor_sync(0xffffffffu, d, 1);
            d += __shfl_xor_sync(0xffffffffu, d, 2);
            d *= scale;
            int kg = k0 + j;
            d = (kg <= qg) ? d : -1e30f;
            if ((j & 3) == part) sv[j >> 2] = d;
            mblk = fmaxf(mblk, d);
        }

        float mnew  = fmaxf(m, mblk);
        float alpha = __expf(m - mnew);
        float ladd  = 0.f;
#pragma unroll
        for (int jj = 0; jj < BKF / 4; jj++) {
            float p = __expf(sv[jj] - mnew);
            ladd += p;
            Ps[row][jj * 4 + part] = p;
        }
        ladd += __shfl_xor_sync(0xffffffffu, ladd, 1);
        ladd += __shfl_xor_sync(0xffffffffu, ladd, 2);
        l = l * alpha + ladd;
        m = mnew;
#pragma unroll
        for (int i = 0; i < 32; i++) acc[i] *= alpha;
        __syncwarp();

#pragma unroll 4
        for (int j = 0; j < BKF; j++) {
            float p = Ps[row][j];
            const float* vr = &Vs[j][part * 32];
#pragma unroll
            for (int i = 0; i < 32; i++) acc[i] = fmaf(p, vr[i], acc[i]);
        }
    }

    float inv_l = 1.0f / l;
    float* op = O + ((size_t)(b * SEQ + qg)) * D_MODEL + h * HEAD_DIM + part * 32;
#pragma unroll
    for (int i = 0; i < 32; i++) op[i] = acc[i] * inv_l;
}

// ============================================================================
// launch
// ============================================================================
extern "C" void kernel_launch(void* const* d_in, const int* in_sizes, int n_in,
                              void* d_out, int out_size)
{
    const float* x   = (const float*)d_in[0];
    const int*   pos = (const int*)  d_in[1];
    const float* Wq  = (const float*)d_in[2];
    const float* Wk  = (const float*)d_in[3];
    const float* Wv  = (const float*)d_in[4];
    const float* Wo  = (const float*)d_in[5];
    float* out = (float*)d_out;

    float *QKVb, *Cb;
    __nv_bfloat16 *xh, *xl, *Wh, *Wl;
    __half *xf, *cf, *Wvf, *Wof;
    cudaGetSymbolAddress((void**)&QKVb, g_QKV);
    cudaGetSymbolAddress((void**)&Cb, g_C);
    cudaGetSymbolAddress((void**)&xh, g_xh);
    cudaGetSymbolAddress((void**)&xl, g_xl);
    cudaGetSymbolAddress((void**)&Wh, g_Wh);
    cudaGetSymbolAddress((void**)&Wl, g_Wl);
    cudaGetSymbolAddress((void**)&xf, g_xf);
    cudaGetSymbolAddress((void**)&cf, g_cf);
    cudaGetSymbolAddress((void**)&Wvf, g_Wvf);
    cudaGetSymbolAddress((void**)&Wof, g_Wof);

    cudaFuncSetAttribute(mma_gemm3_kernel,
                         cudaFuncAttributeMaxDynamicSharedMemorySize, SMEM_G3);
    cudaFuncSetAttribute(mma_gemm1_kernel,
                         cudaFuncAttributeMaxDynamicSharedMemorySize, SMEM_G1);

    const int x_n4 = (M_TOT * D_MODEL) / 4;
    const int w_n4 = (D_MODEL * D_MODEL) / 4;

    // conversions
    cvt_kernel<<<(x_n4 + 255) / 256, 256>>>(x, xh, xl, x_n4);
    dim3 wGrid((w_n4 + 255) / 256, 2);
    cvt2_kernel<<<wGrid, 256>>>(Wq, Wk, Wh, Wl, w_n4);
    cvt_h_kernel<<<(x_n4 + 255) / 256, 256>>>(x, xf, x_n4);
    cvt_h_kernel<<<(w_n4 + 255) / 256, 256>>>(Wv, Wvf, w_n4);
    cvt_h_kernel<<<(w_n4 + 255) / 256, 256>>>(Wo, Wof, w_n4);

    // Q,K projection: bf16x3, fused N=4096, write cols [0,4096) of QKV
    dim3 qkGrid(N_QK / 128, M_TOT / 128);       // (32, 32)
    mma_gemm3_kernel<<<qkGrid, 256, SMEM_G3>>>(xh, xl, Wh, Wl, QKVb, N_QKV);

    // V projection: fp16 single-pass, write cols [4096,6144)
    dim3 vGrid(D_MODEL / 128, M_TOT / 128);     // (16, 32)
    mma_gemm1_kernel<<<vGrid, 256, SMEM_G1>>>(xf, Wvf, QKVb + 2 * D_MODEL, N_QKV);

    int ropeTotal = BATCH * SEQ * N_HEADS * (HEAD_DIM / 2);
    rope_kernel<<<(ropeTotal + 255) / 256, 256>>>(QKVb, pos);

    dim3 flashGrid(SEQ / BQ, BATCH * N_HEADS);   // (32, 32)
    flash_kernel<<<flashGrid, 256>>>(QKVb, QKVb + D_MODEL, QKVb + 2 * D_MODEL, Cb);

    // output projection: fp16 single-pass
    cvt_h_kernel<<<(x_n4 + 255) / 256, 256>>>(Cb, cf, x_n4);
    mma_gemm1_kernel<<<vGrid, 256, SMEM_G1>>>(cf, Wof, out, D_MODEL);
}

// round 10
// speedup vs baseline: 10.1755x; 9.8677x over previous
#include <cuda_runtime.h>
#include <cuda_bf16.h>
#include <cuda_fp16.h>
#include <cstdint>
#include <string.h>
#include <math.h>

// ---------------- problem constants ----------------
#define D_MODEL  2048
#define N_HEADS  16
#define HEAD_DIM 128
#define BATCH    2
#define SEQ      2048
#define M_TOT    (BATCH * SEQ)      // 4096 rows
#define N_QKV    (3 * D_MODEL)      // 6144 fused QKV width
#define N_QK     (2 * D_MODEL)      // 4096 fused QK width
#define N_BH     (BATCH * N_HEADS)  // 32 head-batches

// ---------------- scratch (alloc-free rule: __device__ globals) ----------------
__device__ float g_QKV[M_TOT * N_QKV];     // [token][Q(2048) | K(2048) | V(2048)] fp32

// bf16 split operands (Q,K projections)
__device__ __nv_bfloat16 g_xh[M_TOT * D_MODEL];
__device__ __nv_bfloat16 g_xl[M_TOT * D_MODEL];
__device__ __nv_bfloat16 g_Wh[2 * D_MODEL * D_MODEL];   // [Wq;Wk]
__device__ __nv_bfloat16 g_Wl[2 * D_MODEL * D_MODEL];

// fp16 single-pass operands (V projection, output projection)
__device__ __half g_xf [M_TOT * D_MODEL];
__device__ __half g_cf [M_TOT * D_MODEL];   // flash ctx output (fp16, token-major)
__device__ __half g_Wvf[D_MODEL * D_MODEL];
__device__ __half g_Wof[D_MODEL * D_MODEL];

// head-major flash operands [bh][seq][128]
__device__ __nv_bfloat16 g_fQh[N_BH * SEQ * HEAD_DIM];
__device__ __nv_bfloat16 g_fQl[N_BH * SEQ * HEAD_DIM];
__device__ __nv_bfloat16 g_fKh[N_BH * SEQ * HEAD_DIM];
__device__ __nv_bfloat16 g_fKl[N_BH * SEQ * HEAD_DIM];
__device__ __half        g_fVh[N_BH * SEQ * HEAD_DIM];
__device__ __half        g_fVl[N_BH * SEQ * HEAD_DIM];

// ============================================================================
// PTX helpers (compute_103-safe)
// ============================================================================
__device__ __forceinline__ uint32_t smem_u32(const void* p) {
    uint32_t a;
    asm("{ .reg .u64 t; cvta.to.shared.u64 t, %1; cvt.u32.u64 %0, t; }" : "=r"(a) : "l"(p));
    return a;
}
__device__ __forceinline__ void ldmatrix_x4(uint32_t* r, uint32_t addr) {
    asm volatile("ldmatrix.sync.aligned.m8n8.x4.shared.b16 {%0,%1,%2,%3}, [%4];"
                 : "=r"(r[0]), "=r"(r[1]), "=r"(r[2]), "=r"(r[3]) : "r"(addr));
}
__device__ __forceinline__ void ldmatrix_x4_t(uint32_t* r, uint32_t addr) {
    asm volatile("ldmatrix.sync.aligned.m8n8.x4.trans.shared.b16 {%0,%1,%2,%3}, [%4];"
                 : "=r"(r[0]), "=r"(r[1]), "=r"(r[2]), "=r"(r[3]) : "r"(addr));
}
__device__ __forceinline__ void mma_bf16(float* c, const uint32_t* a, const uint32_t* b) {
    asm volatile(
        "mma.sync.aligned.m16n8k16.row.col.f32.bf16.bf16.f32 "
        "{%0,%1,%2,%3}, {%4,%5,%6,%7}, {%8,%9}, {%0,%1,%2,%3};"
        : "+f"(c[0]), "+f"(c[1]), "+f"(c[2]), "+f"(c[3])
        : "r"(a[0]), "r"(a[1]), "r"(a[2]), "r"(a[3]), "r"(b[0]), "r"(b[1]));
}
__device__ __forceinline__ void mma_f16(float* c, const uint32_t* a, const uint32_t* b) {
    asm volatile(
        "mma.sync.aligned.m16n8k16.row.col.f32.f16.f16.f32 "
        "{%0,%1,%2,%3}, {%4,%5,%6,%7}, {%8,%9}, {%0,%1,%2,%3};"
        : "+f"(c[0]), "+f"(c[1]), "+f"(c[2]), "+f"(c[3])
        : "r"(a[0]), "r"(a[1]), "r"(a[2]), "r"(a[3]), "r"(b[0]), "r"(b[1]));
}
__device__ __forceinline__ void cp16(uint32_t s, const void* g) {
    asm volatile("cp.async.cg.shared.global [%0], [%1], 16;" :: "r"(s), "l"(g));
}
__device__ __forceinline__ void cp_commit() {
    asm volatile("cp.async.commit_group;" ::: "memory");
}
__device__ __forceinline__ void cp_wait_1() {
    asm volatile("cp.async.wait_group 1;" ::: "memory");
}
__device__ __forceinline__ void cp_wait_0() {
    asm volatile("cp.async.wait_group 0;" ::: "memory");
}
__device__ __forceinline__ uint32_t pack_h2(float a, float b) {
    __half2 h = __floats2half2_rn(a, b);
    uint32_t u; memcpy(&u, &h, 4);
    return u;
}

// ============================================================================
// conversions
// ============================================================================
__device__ __forceinline__ void cvt_one(const float* __restrict__ in,
                                        __nv_bfloat16* __restrict__ hi,
                                        __nv_bfloat16* __restrict__ lo,
                                        size_t i)
{
    float4 v = ((const float4*)in)[i];
    __nv_bfloat16 h0 = __float2bfloat16(v.x), h1 = __float2bfloat16(v.y);
    __nv_bfloat16 h2 = __float2bfloat16(v.z), h3 = __float2bfloat16(v.w);
    __nv_bfloat16 l0 = __float2bfloat16(v.x - __bfloat162float(h0));
    __nv_bfloat16 l1 = __float2bfloat16(v.y - __bfloat162float(h1));
    __nv_bfloat16 l2 = __float2bfloat16(v.z - __bfloat162float(h2));
    __nv_bfloat16 l3 = __float2bfloat16(v.w - __bfloat162float(h3));
    __nv_bfloat162* hp = (__nv_bfloat162*)hi;
    __nv_bfloat162* lp = (__nv_bfloat162*)lo;
    __nv_bfloat162 a; a.x = h0; a.y = h1; hp[2*i] = a;
    __nv_bfloat162 b; b.x = h2; b.y = h3; hp[2*i+1] = b;
    __nv_bfloat162 c; c.x = l0; c.y = l1; lp[2*i] = c;
    __nv_bfloat162 d; d.x = l2; d.y = l3; lp[2*i+1] = d;
}

__global__ void cvt_kernel(const float* __restrict__ in,
                           __nv_bfloat16* __restrict__ hi,
                           __nv_bfloat16* __restrict__ lo, int n4)
{
    int i = blockIdx.x * blockDim.x + threadIdx.x;
    if (i >= n4) return;
    cvt_one(in, hi, lo, (size_t)i);
}

__global__ void cvt2_kernel(const float* __restrict__ w0, const float* __restrict__ w1,
                            __nv_bfloat16* __restrict__ hi,
                            __nv_bfloat16* __restrict__ lo, int n4each)
{
    int i = blockIdx.x * blockDim.x + threadIdx.x;
    if (i >= n4each) return;
    const float* in = (blockIdx.y == 0) ? w0 : w1;
    size_t base4 = (size_t)blockIdx.y * n4each;
    cvt_one(in, hi + base4 * 4, lo + base4 * 4, (size_t)i);
}

__global__ void cvt_h_kernel(const float* __restrict__ in,
                             __half* __restrict__ out, int n4)
{
    int i = blockIdx.x * blockDim.x + threadIdx.x;
    if (i >= n4) return;
    float4 v = ((const float4*)in)[i];
    __half2* op = (__half2*)out;
    op[2*i]   = __floats2half2_rn(v.x, v.y);
    op[2*i+1] = __floats2half2_rn(v.z, v.w);
}

// ============================================================================
// GEMM kernels (unchanged, verified R9). C[m,n] = sum_k A[m,k]*B[n,k].
// ============================================================================
#define BK        32
#define NITER     (D_MODEL / BK)

__device__ __forceinline__ uint32_t sw_off(int row, int chunk) {
    return (uint32_t)(row * 64 + ((chunk ^ ((row >> 1) & 3)) << 4));
}

#define OFF_AH    0
#define OFF_AL    8192
#define OFF_BH    16384
#define OFF_BL    24576
#define STAGE_B3  32768
#define SMEM_G3   (3 * STAGE_B3 + 128)

__device__ __forceinline__ void issue_stage3(
    uint32_t stage,
    const __nv_bfloat16* __restrict__ Ah, const __nv_bfloat16* __restrict__ Al,
    const __nv_bfloat16* __restrict__ Bh, const __nv_bfloat16* __restrict__ Bl,
    int bm, int bn, int k0, int tid)
{
#pragma unroll
    for (int j = 0; j < 2; j++) {
        int idx = tid + 256 * j;
        int row = idx >> 2;
        int ch  = idx & 3;
        uint32_t so = sw_off(row, ch);
        size_t ga = (size_t)(bm + row) * D_MODEL + k0 + ch * 8;
        size_t gb = (size_t)(bn + row) * D_MODEL + k0 + ch * 8;
        cp16(stage + OFF_AH + so, Ah + ga);
        cp16(stage + OFF_AL + so, Al + ga);
        cp16(stage + OFF_BH + so, Bh + gb);
        cp16(stage + OFF_BL + so, Bl + gb);
    }
}

__global__ void __launch_bounds__(256, 2) mma_gemm3_kernel(
    const __nv_bfloat16* __restrict__ Ah, const __nv_bfloat16* __restrict__ Al,
    const __nv_bfloat16* __restrict__ Bh, const __nv_bfloat16* __restrict__ Bl,
    float* __restrict__ C, int ldc)
{
    extern __shared__ char sm_raw[];
    const uint32_t sbase = (smem_u32(sm_raw) + 127u) & ~127u;

    const int tid  = threadIdx.x;
    const int lane = tid & 31;
    const int w    = tid >> 5;
    const int wm   = (w & 1) * 64;
    const int wn   = (w >> 1) * 32;
    const int bm   = blockIdx.y * 128;
    const int bn   = blockIdx.x * 128;

    const int g  = lane >> 3;
    const int li = lane & 7;
    const int aRowL = li + ((g & 1) << 3);
    const int aChL  = g >> 1;
    const int bRowL = li + ((g >> 1) << 3);
    const int bChL  = g & 1;

    float acc[4][4][4];
#pragma unroll
    for (int mi = 0; mi < 4; mi++)
#pragma unroll
        for (int ni = 0; ni < 4; ni++)
#pragma unroll
            for (int r = 0; r < 4; r++) acc[mi][ni][r] = 0.f;

    issue_stage3(sbase + 0 * STAGE_B3, Ah, Al, Bh, Bl, bm, bn, 0, tid);
    cp_commit();
    issue_stage3(sbase + 1 * STAGE_B3, Ah, Al, Bh, Bl, bm, bn, BK, tid);
    cp_commit();

    int buf = 0, ibuf = 2;
    for (int c = 0; c < NITER; c++) {
        cp_wait_1();
        __syncthreads();
        if (c + 2 < NITER)
            issue_stage3(sbase + (uint32_t)ibuf * STAGE_B3, Ah, Al, Bh, Bl,
                         bm, bn, (c + 2) * BK, tid);
        cp_commit();

        const uint32_t st  = sbase + (uint32_t)buf * STAGE_B3;
        const uint32_t tAh = st + OFF_AH;
        const uint32_t tAl = st + OFF_AL;
        const uint32_t tBh = st + OFF_BH;
        const uint32_t tBl = st + OFF_BL;

#pragma unroll
        for (int ks = 0; ks < 2; ks++) {
            const int aCh = 2 * ks + aChL;
            const int bCh = 2 * ks + bChL;

            uint32_t ah[4][4], bh[4][2], bl[4][2];
#pragma unroll
            for (int mi = 0; mi < 4; mi++)
                ldmatrix_x4(ah[mi], tAh + sw_off(wm + mi * 16 + aRowL, aCh));
#pragma unroll
            for (int p = 0; p < 2; p++) {
                uint32_t t4[4];
                ldmatrix_x4(t4, tBh + sw_off(wn + p * 16 + bRowL, bCh));
                bh[2 * p][0] = t4[0]; bh[2 * p][1] = t4[1];
                bh[2 * p + 1][0] = t4[2]; bh[2 * p + 1][1] = t4[3];
                ldmatrix_x4(t4, tBl + sw_off(wn + p * 16 + bRowL, bCh));
                bl[2 * p][0] = t4[0]; bl[2 * p][1] = t4[1];
                bl[2 * p + 1][0] = t4[2]; bl[2 * p + 1][1] = t4[3];
            }

#pragma unroll
            for (int mi = 0; mi < 4; mi++)
#pragma unroll
                for (int ni = 0; ni < 4; ni++)
                    mma_bf16(acc[mi][ni], ah[mi], bh[ni]);
#pragma unroll
            for (int mi = 0; mi < 4; mi++)
#pragma unroll
                for (int ni = 0; ni < 4; ni++)
                    mma_bf16(acc[mi][ni], ah[mi], bl[ni]);

            uint32_t al[4][4];
#pragma unroll
            for (int mi = 0; mi < 4; mi++)
                ldmatrix_x4(al[mi], tAl + sw_off(wm + mi * 16 + aRowL, aCh));
#pragma unroll
            for (int mi = 0; mi < 4; mi++)
#pragma unroll
                for (int ni = 0; ni < 4; ni++)
                    mma_bf16(acc[mi][ni], al[mi], bh[ni]);
        }
        buf  = (buf == 2)  ? 0 : buf + 1;
        ibuf = (ibuf == 2) ? 0 : ibuf + 1;
    }

    const int gid = lane >> 2;
    const int tig = lane & 3;
#pragma unroll
    for (int mi = 0; mi < 4; mi++) {
#pragma unroll
        for (int ni = 0; ni < 4; ni++) {
            int row = bm + wm + mi * 16 + gid;
            int col = bn + wn + ni * 8 + tig * 2;
            float2 v0 = make_float2(acc[mi][ni][0], acc[mi][ni][1]);
            float2 v1 = make_float2(acc[mi][ni][2], acc[mi][ni][3]);
            *(float2*)(C + (size_t)row * ldc + col) = v0;
            *(float2*)(C + (size_t)(row + 8) * ldc + col) = v1;
        }
    }
}

#define OFF_A1    0
#define OFF_B1    8192
#define STAGE_B1  16384
#define SMEM_G1   (3 * STAGE_B1 + 128)

__device__ __forceinline__ void issue_stage1(
    uint32_t stage,
    const __half* __restrict__ A, const __half* __restrict__ B,
    int bm, int bn, int k0, int tid)
{
#pragma unroll
    for (int j = 0; j < 2; j++) {
        int idx = tid + 256 * j;
        int row = idx >> 2;
        int ch  = idx & 3;
        uint32_t so = sw_off(row, ch);
        cp16(stage + OFF_A1 + so, A + (size_t)(bm + row) * D_MODEL + k0 + ch * 8);
        cp16(stage + OFF_B1 + so, B + (size_t)(bn + row) * D_MODEL + k0 + ch * 8);
    }
}

__global__ void __launch_bounds__(256, 2) mma_gemm1_kernel(
    const __half* __restrict__ A, const __half* __restrict__ B,
    float* __restrict__ C, int ldc)
{
    extern __shared__ char sm_raw[];
    const uint32_t sbase = (smem_u32(sm_raw) + 127u) & ~127u;

    const int tid  = threadIdx.x;
    const int lane = tid & 31;
    const int w    = tid >> 5;
    const int wm   = (w & 1) * 64;
    const int wn   = (w >> 1) * 32;
    const int bm   = blockIdx.y * 128;
    const int bn   = blockIdx.x * 128;

    const int g  = lane >> 3;
    const int li = lane & 7;
    const int aRowL = li + ((g & 1) << 3);
    const int aChL  = g >> 1;
    const int bRowL = li + ((g >> 1) << 3);
    const int bChL  = g & 1;

    float acc[4][4][4];
#pragma unroll
    for (int mi = 0; mi < 4; mi++)
#pragma unroll
        for (int ni = 0; ni < 4; ni++)
#pragma unroll
            for (int r = 0; r < 4; r++) acc[mi][ni][r] = 0.f;

    issue_stage1(sbase + 0 * STAGE_B1, A, B, bm, bn, 0, tid);
    cp_commit();
    issue_stage1(sbase + 1 * STAGE_B1, A, B, bm, bn, BK, tid);
    cp_commit();

    int buf = 0, ibuf = 2;
    for (int c = 0; c < NITER; c++) {
        cp_wait_1();
        __syncthreads();
        if (c + 2 < NITER)
            issue_stage1(sbase + (uint32_t)ibuf * STAGE_B1, A, B,
                         bm, bn, (c + 2) * BK, tid);
        cp_commit();

        const uint32_t st = sbase + (uint32_t)buf * STAGE_B1;
        const uint32_t tA = st + OFF_A1;
        const uint32_t tB = st + OFF_B1;

#pragma unroll
        for (int ks = 0; ks < 2; ks++) {
            const int aCh = 2 * ks + aChL;
            const int bCh = 2 * ks + bChL;

            uint32_t a4[4][4], b2[4][2];
#pragma unroll
            for (int mi = 0; mi < 4; mi++)
                ldmatrix_x4(a4[mi], tA + sw_off(wm + mi * 16 + aRowL, aCh));
#pragma unroll
            for (int p = 0; p < 2; p++) {
                uint32_t t4[4];
                ldmatrix_x4(t4, tB + sw_off(wn + p * 16 + bRowL, bCh));
                b2[2 * p][0] = t4[0]; b2[2 * p][1] = t4[1];
                b2[2 * p + 1][0] = t4[2]; b2[2 * p + 1][1] = t4[3];
            }
#pragma unroll
            for (int mi = 0; mi < 4; mi++)
#pragma unroll
                for (int ni = 0; ni < 4; ni++)
                    mma_f16(acc[mi][ni], a4[mi], b2[ni]);
        }
        buf  = (buf == 2)  ? 0 : buf + 1;
        ibuf = (ibuf == 2) ? 0 : ibuf + 1;
    }

    const int gid = lane >> 2;
    const int tig = lane & 3;
#pragma unroll
    for (int mi = 0; mi < 4; mi++) {
#pragma unroll
        for (int ni = 0; ni < 4; ni++) {
            int row = bm + wm + mi * 16 + gid;
            int col = bn + wn + ni * 8 + tig * 2;
            float2 v0 = make_float2(acc[mi][ni][0], acc[mi][ni][1]);
            float2 v1 = make_float2(acc[mi][ni][2], acc[mi][ni][3]);
            *(float2*)(C + (size_t)row * ldc + col) = v0;
            *(float2*)(C + (size_t)(row + 8) * ldc + col) = v1;
        }
    }
}

// ============================================================================
// rope + convert: g_QKV (fp32 token-major) -> head-major bf16 Qh/Ql/Kh/Kl,
// fp16 Vh/Vl. One thread per (b, s, h, pair).
// ============================================================================
__global__ void rope_cvt_kernel(const float* __restrict__ QKV,
                                const int* __restrict__ pos,
                                __nv_bfloat16* __restrict__ Qh, __nv_bfloat16* __restrict__ Ql,
                                __nv_bfloat16* __restrict__ Kh, __nv_bfloat16* __restrict__ Kl,
                                __half* __restrict__ Vh, __half* __restrict__ Vl)
{
    int idx = blockIdx.x * blockDim.x + threadIdx.x;
    const int total = BATCH * SEQ * N_HEADS * (HEAD_DIM / 2);
    if (idx >= total) return;

    int i  = idx & 63;
    int h  = (idx >> 6) & (N_HEADS - 1);
    int ss = (idx >> 10) & (SEQ - 1);
    int b  = idx >> 21;

    int p = pos[b * SEQ + ss];
    float inv_freq = powf(10000.0f, -(2.0f * (float)i) / 128.0f);
    float ang = (float)p * inv_freq;
    float sn, cs;
    sincosf(ang, &sn, &cs);

    size_t src = (size_t)(b * SEQ + ss) * N_QKV + h * HEAD_DIM + 2 * i;
    float qe = QKV[src],            qo = QKV[src + 1];
    float ke = QKV[src + D_MODEL],  ko = QKV[src + D_MODEL + 1];
    float ve = QKV[src + 2*D_MODEL], vo = QKV[src + 2*D_MODEL + 1];

    float q0 = qe * cs - qo * sn, q1 = qe * sn + qo * cs;
    float k0 = ke * cs - ko * sn, k1 = ke * sn + ko * cs;

    size_t dst = ((size_t)((b * N_HEADS + h) * SEQ + ss)) * HEAD_DIM + 2 * i;

    __nv_bfloat16 qh0 = __float2bfloat16(q0), qh1 = __float2bfloat16(q1);
    __nv_bfloat162 qhv; qhv.x = qh0; qhv.y = qh1;
    __nv_bfloat162 qlv; qlv.x = __float2bfloat16(q0 - __bfloat162float(qh0));
                        qlv.y = __float2bfloat16(q1 - __bfloat162float(qh1));
    *(__nv_bfloat162*)(Qh + dst) = qhv;
    *(__nv_bfloat162*)(Ql + dst) = qlv;

    __nv_bfloat16 kh0 = __float2bfloat16(k0), kh1 = __float2bfloat16(k1);
    __nv_bfloat162 khv; khv.x = kh0; khv.y = kh1;
    __nv_bfloat162 klv; klv.x = __float2bfloat16(k0 - __bfloat162float(kh0));
                        klv.y = __float2bfloat16(k1 - __bfloat162float(kh1));
    *(__nv_bfloat162*)(Kh + dst) = khv;
    *(__nv_bfloat162*)(Kl + dst) = klv;

    __half vh0 = __float2half_rn(ve), vh1 = __float2half_rn(vo);
    __half2 vhv; vhv.x = vh0; vhv.y = vh1;
    __half2 vlv; vlv.x = __float2half_rn(ve - __half2float(vh0));
                 vlv.y = __float2half_rn(vo - __half2float(vh1));
    *(__half2*)(Vh + dst) = vhv;
    *(__half2*)(Vl + dst) = vlv;
}

// ============================================================================
// flash v2: tensor-core causal attention.
// CTA: 64 queries x 1 head, 128 threads (4 warps, 16 q-rows each).
// K-tiles of 64 keys. QK^T = bf16x3 mma; softmax in registers; PV = fp16 mma
// with V hi/lo two-pass. Output fp16 to token-major ctx buffer.
// smem: Qh,Ql,Kh,Kl (bf16 64x128) + Vh,Vl (fp16 64x128) = 96KB, 2 CTAs/SM.
// ============================================================================
#define FQH 0
#define FQL 16384
#define FKH 32768
#define FKL 49152
#define FVH 65536
#define FVL 81920
#define SMEM_FLASH (98304 + 128)

__device__ __forceinline__ uint32_t fsw(int row, int ch) {
    return (uint32_t)(row * 256 + ((ch ^ (row & 7)) << 4));
}

__global__ void __launch_bounds__(128, 2) flash2_kernel(
    const __nv_bfloat16* __restrict__ Qh, const __nv_bfloat16* __restrict__ Ql,
    const __nv_bfloat16* __restrict__ Kh, const __nv_bfloat16* __restrict__ Kl,
    const __half* __restrict__ Vh, const __half* __restrict__ Vl,
    __half* __restrict__ Ctx)
{
    extern __shared__ char sm_raw[];
    const uint32_t sb = (smem_u32(sm_raw) + 127u) & ~127u;

    const int tid  = threadIdx.x;
    const int lane = tid & 31;
    const int w    = tid >> 5;           // warp 0..3: q rows w*16..w*16+15
    const int bh   = blockIdx.y;
    const int q0   = blockIdx.x * 64;
    const size_t hbase = (size_t)bh * SEQ * HEAD_DIM;

    const int g2 = lane >> 3, li = lane & 7;
    const int aRow = w * 16 + ((g2 & 1) << 3) + li;   // Q A-frag row
    const int aChS = g2 >> 1;                          // + 2*kf
    const int bRowK = ((g2 >> 1) << 3) + li;           // + p*16 (K B-frag)
    const int bChK  = g2 & 1;                          // + 2*kf
    const int vRowS = ((g2 & 1) << 3) + li;            // + j*16 (V trans)
    const int vChS  = g2 >> 1;                         // + 2*p
    const int gid = lane >> 2, tig = lane & 3;

    // prologue loads: Q (both tiles) + KV tile 0
#pragma unroll
    for (int j = 0; j < 8; j++) {
        int idx = tid + 128 * j; int row = idx >> 4; int ch = idx & 15;
        uint32_t so = fsw(row, ch);
        size_t gq = hbase + (size_t)(q0 + row) * HEAD_DIM + ch * 8;
        cp16(sb + FQH + so, Qh + gq);
        cp16(sb + FQL + so, Ql + gq);
        size_t gk = hbase + (size_t)row * HEAD_DIM + ch * 8;   // k0 = 0
        cp16(sb + FKH + so, Kh + gk);
        cp16(sb + FKL + so, Kl + gk);
        cp16(sb + FVH + so, Vh + gk);
        cp16(sb + FVL + so, Vl + gk);
    }
    cp_commit();

    float o[16][4];
#pragma unroll
    for (int nb = 0; nb < 16; nb++)
#pragma unroll
        for (int r = 0; r < 4; r++) o[nb][r] = 0.f;
    float m0s = -1e30f, m1s = -1e30f, l0 = 0.f, l1 = 0.f;

    const float scale = 0.08838834764831845f;
    const int nt = q0 / 64 + 1;

    for (int kt = 0; kt < nt; kt++) {
        const int k0 = kt * 64;
        cp_wait_0();
        __syncthreads();

        // ---- S = Q K^T (bf16x3) ----
        float s[8][4];
#pragma unroll
        for (int ni = 0; ni < 8; ni++)
#pragma unroll
            for (int r = 0; r < 4; r++) s[ni][r] = 0.f;

#pragma unroll
        for (int kf = 0; kf < 8; kf++) {
            uint32_t ah[4], al4[4];
            ldmatrix_x4(ah,  sb + FQH + fsw(aRow, 2 * kf + aChS));
            ldmatrix_x4(al4, sb + FQL + fsw(aRow, 2 * kf + aChS));
            uint32_t kb[8][2];
#pragma unroll
            for (int p = 0; p < 4; p++) {
                uint32_t t4[4];
                ldmatrix_x4(t4, sb + FKH + fsw(p * 16 + bRowK, 2 * kf + bChK));
                kb[2*p][0] = t4[0]; kb[2*p][1] = t4[1];
                kb[2*p+1][0] = t4[2]; kb[2*p+1][1] = t4[3];
            }
#pragma unroll
            for (int ni = 0; ni < 8; ni++) mma_bf16(s[ni], ah, kb[ni]);
#pragma unroll
            for (int ni = 0; ni < 8; ni++) mma_bf16(s[ni], al4, kb[ni]);
#pragma unroll
            for (int p = 0; p < 4; p++) {
                uint32_t t4[4];
                ldmatrix_x4(t4, sb + FKL + fsw(p * 16 + bRowK, 2 * kf + bChK));
                kb[2*p][0] = t4[0]; kb[2*p][1] = t4[1];
                kb[2*p+1][0] = t4[2]; kb[2*p+1][1] = t4[3];
            }
#pragma unroll
            for (int ni = 0; ni < 8; ni++) mma_bf16(s[ni], ah, kb[ni]);
        }

        // prefetch next KV tile (after S consumed smem K; V still needed below —
        // so prefetch AFTER PV. Here: only issue after compute; see end of loop)

        // ---- softmax (online) ----
        const bool diag = (k0 == q0);
        const int row0 = q0 + w * 16 + gid;
        float mx0 = -1e30f, mx1 = -1e30f;
#pragma unroll
        for (int ni = 0; ni < 8; ni++) {
#pragma unroll
            for (int r = 0; r < 4; r++) {
                float v = s[ni][r] * scale;
                if (diag) {
                    int col = k0 + ni * 8 + tig * 2 + (r & 1);
                    int row = row0 + ((r >> 1) << 3);
                    if (col > row) v = -1e30f;
                }
                s[ni][r] = v;
                if (r < 2) mx0 = fmaxf(mx0, v); else mx1 = fmaxf(mx1, v);
            }
        }
        mx0 = fmaxf(mx0, __shfl_xor_sync(0xffffffffu, mx0, 1));
        mx0 = fmaxf(mx0, __shfl_xor_sync(0xffffffffu, mx0, 2));
        mx1 = fmaxf(mx1, __shfl_xor_sync(0xffffffffu, mx1, 1));
        mx1 = fmaxf(mx1, __shfl_xor_sync(0xffffffffu, mx1, 2));

        float mn0 = fmaxf(m0s, mx0), mn1 = fmaxf(m1s, mx1);
        float a0 = __expf(m0s - mn0), a1 = __expf(m1s - mn1);
        float ls0 = 0.f, ls1 = 0.f;
#pragma unroll
        for (int ni = 0; ni < 8; ni++) {
            s[ni][0] = __expf(s[ni][0] - mn0); ls0 += s[ni][0];
            s[ni][1] = __expf(s[ni][1] - mn0); ls0 += s[ni][1];
            s[ni][2] = __expf(s[ni][2] - mn1); ls1 += s[ni][2];
            s[ni][3] = __expf(s[ni][3] - mn1); ls1 += s[ni][3];
        }
        ls0 += __shfl_xor_sync(0xffffffffu, ls0, 1);
        ls0 += __shfl_xor_sync(0xffffffffu, ls0, 2);
        ls1 += __shfl_xor_sync(0xffffffffu, ls1, 1);
        ls1 += __shfl_xor_sync(0xffffffffu, ls1, 2);
        l0 = l0 * a0 + ls0; l1 = l1 * a1 + ls1;
        m0s = mn0; m1s = mn1;
#pragma unroll
        for (int nb = 0; nb < 16; nb++) {
            o[nb][0] *= a0; o[nb][1] *= a0; o[nb][2] *= a1; o[nb][3] *= a1;
        }

        // ---- P -> fp16 fragments ----
        uint32_t P[4][4];
#pragma unroll
        for (int j = 0; j < 4; j++) {
            P[j][0] = pack_h2(s[2*j][0],   s[2*j][1]);
            P[j][1] = pack_h2(s[2*j][2],   s[2*j][3]);
            P[j][2] = pack_h2(s[2*j+1][0], s[2*j+1][1]);
            P[j][3] = pack_h2(s[2*j+1][2], s[2*j+1][3]);
        }

        // ---- ctx += P * V  (fp16, hi + lo passes) ----
#pragma unroll
        for (int j = 0; j < 4; j++) {
#pragma unroll
            for (int p = 0; p < 8; p++) {
                uint32_t t4[4];
                ldmatrix_x4_t(t4, sb + FVH + fsw(j * 16 + vRowS, 2 * p + vChS));
                uint32_t b0[2] = {t4[0], t4[1]}, b1[2] = {t4[2], t4[3]};
                mma_f16(o[2*p],   P[j], b0);
                mma_f16(o[2*p+1], P[j], b1);
                ldmatrix_x4_t(t4, sb + FVL + fsw(j * 16 + vRowS, 2 * p + vChS));
                uint32_t c0[2] = {t4[0], t4[1]}, c1[2] = {t4[2], t4[3]};
                mma_f16(o[2*p],   P[j], c0);
                mma_f16(o[2*p+1], P[j], c1);
            }
        }

        // prefetch next KV tile
        if (kt + 1 < nt) {
            __syncthreads();          // everyone done reading this tile
            const int nk0 = (kt + 1) * 64;
#pragma unroll
            for (int j = 0; j < 8; j++) {
                int idx = tid + 128 * j; int row = idx >> 4; int ch = idx & 15;
                uint32_t so = fsw(row, ch);
                size_t gk = hbase + (size_t)(nk0 + row) * HEAD_DIM + ch * 8;
                cp16(sb + FKH + so, Kh + gk);
                cp16(sb + FKL + so, Kl + gk);
                cp16(sb + FVH + so, Vh + gk);
                cp16(sb + FVL + so, Vl + gk);
            }
            cp_commit();
        }
    }

    // ---- write ctx (fp16, token-major) ----
    float i0 = 1.0f / l0, i1 = 1.0f / l1;
    const int b = bh >> 4, h = bh & 15;
    size_t t0 = (size_t)(b * SEQ + q0 + w * 16 + gid) * D_MODEL + h * HEAD_DIM;
    size_t t1 = t0 + (size_t)8 * D_MODEL;
#pragma unroll
    for (int nb = 0; nb < 16; nb++) {
        int col = nb * 8 + tig * 2;
        *(__half2*)(Ctx + t0 + col) = __floats2half2_rn(o[nb][0] * i0, o[nb][1] * i0);
        *(__half2*)(Ctx + t1 + col) = __floats2half2_rn(o[nb][2] * i1, o[nb][3] * i1);
    }
}

// ============================================================================
// launch
// ============================================================================
extern "C" void kernel_launch(void* const* d_in, const int* in_sizes, int n_in,
                              void* d_out, int out_size)
{
    const float* x   = (const float*)d_in[0];
    const int*   pos = (const int*)  d_in[1];
    const float* Wq  = (const float*)d_in[2];
    const float* Wk  = (const float*)d_in[3];
    const float* Wv  = (const float*)d_in[4];
    const float* Wo  = (const float*)d_in[5];
    float* out = (float*)d_out;

    float *QKVb;
    __nv_bfloat16 *xh, *xl, *Wh, *Wl, *fQh, *fQl, *fKh, *fKl;
    __half *xf, *cf, *Wvf, *Wof, *fVh, *fVl;
    cudaGetSymbolAddress((void**)&QKVb, g_QKV);
    cudaGetSymbolAddress((void**)&xh, g_xh);
    cudaGetSymbolAddress((void**)&xl, g_xl);
    cudaGetSymbolAddress((void**)&Wh, g_Wh);
    cudaGetSymbolAddress((void**)&Wl, g_Wl);
    cudaGetSymbolAddress((void**)&xf, g_xf);
    cudaGetSymbolAddress((void**)&cf, g_cf);
    cudaGetSymbolAddress((void**)&Wvf, g_Wvf);
    cudaGetSymbolAddress((void**)&Wof, g_Wof);
    cudaGetSymbolAddress((void**)&fQh, g_fQh);
    cudaGetSymbolAddress((void**)&fQl, g_fQl);
    cudaGetSymbolAddress((void**)&fKh, g_fKh);
    cudaGetSymbolAddress((void**)&fKl, g_fKl);
    cudaGetSymbolAddress((void**)&fVh, g_fVh);
    cudaGetSymbolAddress((void**)&fVl, g_fVl);

    cudaFuncSetAttribute(mma_gemm3_kernel,
                         cudaFuncAttributeMaxDynamicSharedMemorySize, SMEM_G3);
    cudaFuncSetAttribute(mma_gemm1_kernel,
                         cudaFuncAttributeMaxDynamicSharedMemorySize, SMEM_G1);
    cudaFuncSetAttribute(flash2_kernel,
                         cudaFuncAttributeMaxDynamicSharedMemorySize, SMEM_FLASH);

    const int x_n4 = (M_TOT * D_MODEL) / 4;
    const int w_n4 = (D_MODEL * D_MODEL) / 4;

    // conversions
    cvt_kernel<<<(x_n4 + 255) / 256, 256>>>(x, xh, xl, x_n4);
    dim3 wGrid((w_n4 + 255) / 256, 2);
    cvt2_kernel<<<wGrid, 256>>>(Wq, Wk, Wh, Wl, w_n4);
    cvt_h_kernel<<<(x_n4 + 255) / 256, 256>>>(x, xf, x_n4);
    cvt_h_kernel<<<(w_n4 + 255) / 256, 256>>>(Wv, Wvf, w_n4);
    cvt_h_kernel<<<(w_n4 + 255) / 256, 256>>>(Wo, Wof, w_n4);

    // Q,K projection (bf16x3, fused N=4096) -> QKV cols [0,4096)
    dim3 qkGrid(N_QK / 128, M_TOT / 128);
    mma_gemm3_kernel<<<qkGrid, 256, SMEM_G3>>>(xh, xl, Wh, Wl, QKVb, N_QKV);

    // V projection (fp16) -> QKV cols [4096,6144)
    dim3 vGrid(D_MODEL / 128, M_TOT / 128);
    mma_gemm1_kernel<<<vGrid, 256, SMEM_G1>>>(xf, Wvf, QKVb + 2 * D_MODEL, N_QKV);

    // rope + head-major split conversion
    int rcTotal = BATCH * SEQ * N_HEADS * (HEAD_DIM / 2);
    rope_cvt_kernel<<<(rcTotal + 255) / 256, 256>>>(QKVb, pos,
                                                    fQh, fQl, fKh, fKl, fVh, fVl);

    // tensor-core flash attention -> fp16 ctx (token-major)
    dim3 fGrid(SEQ / 64, N_BH);          // (32, 32)
    flash2_kernel<<<fGrid, 128, SMEM_FLASH>>>(fQh, fQl, fKh, fKl, fVh, fVl, cf);

    // output projection (fp16)
    mma_gemm1_kernel<<<vGrid, 256, SMEM_G1>>>(cf, Wof, out, D_MODEL);
}

// round 13
// speedup vs baseline: 10.8803x; 1.0693x over previous
#include <cuda_runtime.h>
#include <cuda_bf16.h>
#include <cuda_fp16.h>
#include <cstdint>
#include <string.h>
#include <math.h>

// ---------------- problem constants ----------------
#define D_MODEL  2048
#define N_HEADS  16
#define HEAD_DIM 128
#define BATCH    2
#define SEQ      2048
#define M_TOT    (BATCH * SEQ)      // 4096 rows
#define N_QK     (2 * D_MODEL)      // 4096 fused QK width
#define N_BH     (BATCH * N_HEADS)  // 32 head-batches

// ---------------- scratch (alloc-free rule: __device__ globals) ----------------
// bf16 split operands (Q,K projections)
__device__ __nv_bfloat16 g_xh[M_TOT * D_MODEL];
__device__ __nv_bfloat16 g_xl[M_TOT * D_MODEL];
__device__ __nv_bfloat16 g_Wh[2 * D_MODEL * D_MODEL];   // [Wq;Wk]
__device__ __nv_bfloat16 g_Wl[2 * D_MODEL * D_MODEL];

// fp16 operands
__device__ __half g_xf [M_TOT * D_MODEL];
__device__ __half g_cf [M_TOT * D_MODEL];   // flash ctx output (fp16, token-major)
__device__ __half g_Wvf[D_MODEL * D_MODEL];
__device__ __half g_Wof[D_MODEL * D_MODEL];

// head-major flash operands [bh][seq][128]
__device__ __nv_bfloat16 g_fQh[N_BH * SEQ * HEAD_DIM];
__device__ __nv_bfloat16 g_fQl[N_BH * SEQ * HEAD_DIM];
__device__ __nv_bfloat16 g_fKh[N_BH * SEQ * HEAD_DIM];
__device__ __nv_bfloat16 g_fKl[N_BH * SEQ * HEAD_DIM];
__device__ __half        g_fVh[N_BH * SEQ * HEAD_DIM];

// rope table: [row 0..4095][i 0..63] -> (cos, sin)
__device__ float2 g_tab[M_TOT * 64];

// ============================================================================
// PTX helpers (compute_103-safe)
// ============================================================================
__device__ __forceinline__ uint32_t smem_u32(const void* p) {
    uint32_t a;
    asm("{ .reg .u64 t; cvta.to.shared.u64 t, %1; cvt.u32.u64 %0, t; }" : "=r"(a) : "l"(p));
    return a;
}
__device__ __forceinline__ void ldmatrix_x4(uint32_t* r, uint32_t addr) {
    asm volatile("ldmatrix.sync.aligned.m8n8.x4.shared.b16 {%0,%1,%2,%3}, [%4];"
                 : "=r"(r[0]), "=r"(r[1]), "=r"(r[2]), "=r"(r[3]) : "r"(addr));
}
__device__ __forceinline__ void ldmatrix_x4_t(uint32_t* r, uint32_t addr) {
    asm volatile("ldmatrix.sync.aligned.m8n8.x4.trans.shared.b16 {%0,%1,%2,%3}, [%4];"
                 : "=r"(r[0]), "=r"(r[1]), "=r"(r[2]), "=r"(r[3]) : "r"(addr));
}
__device__ __forceinline__ void mma_bf16(float* c, const uint32_t* a, const uint32_t* b) {
    asm volatile(
        "mma.sync.aligned.m16n8k16.row.col.f32.bf16.bf16.f32 "
        "{%0,%1,%2,%3}, {%4,%5,%6,%7}, {%8,%9}, {%0,%1,%2,%3};"
        : "+f"(c[0]), "+f"(c[1]), "+f"(c[2]), "+f"(c[3])
        : "r"(a[0]), "r"(a[1]), "r"(a[2]), "r"(a[3]), "r"(b[0]), "r"(b[1]));
}
__device__ __forceinline__ void mma_f16(float* c, const uint32_t* a, const uint32_t* b) {
    asm volatile(
        "mma.sync.aligned.m16n8k16.row.col.f32.f16.f16.f32 "
        "{%0,%1,%2,%3}, {%4,%5,%6,%7}, {%8,%9}, {%0,%1,%2,%3};"
        : "+f"(c[0]), "+f"(c[1]), "+f"(c[2]), "+f"(c[3])
        : "r"(a[0]), "r"(a[1]), "r"(a[2]), "r"(a[3]), "r"(b[0]), "r"(b[1]));
}
__device__ __forceinline__ void cp16(uint32_t s, const void* g) {
    asm volatile("cp.async.cg.shared.global [%0], [%1], 16;" :: "r"(s), "l"(g));
}
__device__ __forceinline__ void cp_commit() {
    asm volatile("cp.async.commit_group;" ::: "memory");
}
__device__ __forceinline__ void cp_wait_1() {
    asm volatile("cp.async.wait_group 1;" ::: "memory");
}
__device__ __forceinline__ void cp_wait_0() {
    asm volatile("cp.async.wait_group 0;" ::: "memory");
}
__device__ __forceinline__ uint32_t pack_h2(float a, float b) {
    __half2 h = __floats2half2_rn(a, b);
    uint32_t u; memcpy(&u, &h, 4);
    return u;
}
__device__ __forceinline__ __nv_bfloat162 bf2(float a, float b) {
    __nv_bfloat162 v; v.x = __float2bfloat16(a); v.y = __float2bfloat16(b);
    return v;
}

// ============================================================================
// conversions + rope table
// ============================================================================
__global__ void cvt_x_kernel(const float* __restrict__ in,
                             __nv_bfloat16* __restrict__ hi,
                             __nv_bfloat16* __restrict__ lo,
                             __half* __restrict__ hf, int n4)
{
    int i = blockIdx.x * blockDim.x + threadIdx.x;
    if (i >= n4) return;
    float4 v = ((const float4*)in)[i];
    __nv_bfloat16 h0 = __float2bfloat16(v.x), h1 = __float2bfloat16(v.y);
    __nv_bfloat16 h2 = __float2bfloat16(v.z), h3 = __float2bfloat16(v.w);
    __nv_bfloat162* hp = (__nv_bfloat162*)hi;
    __nv_bfloat162* lp = (__nv_bfloat162*)lo;
    __nv_bfloat162 a; a.x = h0; a.y = h1; hp[2*i] = a;
    __nv_bfloat162 b; b.x = h2; b.y = h3; hp[2*i+1] = b;
    lp[2*i]   = bf2(v.x - __bfloat162float(h0), v.y - __bfloat162float(h1));
    lp[2*i+1] = bf2(v.z - __bfloat162float(h2), v.w - __bfloat162float(h3));
    __half2* op = (__half2*)hf;
    op[2*i]   = __floats2half2_rn(v.x, v.y);
    op[2*i+1] = __floats2half2_rn(v.z, v.w);
}

__global__ void cvt2_kernel(const float* __restrict__ w0, const float* __restrict__ w1,
                            __nv_bfloat16* __restrict__ hi,
                            __nv_bfloat16* __restrict__ lo, int n4each)
{
    int i = blockIdx.x * blockDim.x + threadIdx.x;
    if (i >= n4each) return;
    const float* in = (blockIdx.y == 0) ? w0 : w1;
    size_t o4 = (size_t)blockIdx.y * n4each + i;
    float4 v = ((const float4*)in)[i];
    __nv_bfloat16 h0 = __float2bfloat16(v.x), h1 = __float2bfloat16(v.y);
    __nv_bfloat16 h2 = __float2bfloat16(v.z), h3 = __float2bfloat16(v.w);
    __nv_bfloat162* hp = (__nv_bfloat162*)hi;
    __nv_bfloat162* lp = (__nv_bfloat162*)lo;
    __nv_bfloat162 a; a.x = h0; a.y = h1; hp[2*o4] = a;
    __nv_bfloat162 b; b.x = h2; b.y = h3; hp[2*o4+1] = b;
    lp[2*o4]   = bf2(v.x - __bfloat162float(h0), v.y - __bfloat162float(h1));
    lp[2*o4+1] = bf2(v.z - __bfloat162float(h2), v.w - __bfloat162float(h3));
}

__global__ void cvt_h2_kernel(const float* __restrict__ w0, const float* __restrict__ w1,
                              __half* __restrict__ o0, __half* __restrict__ o1, int n4)
{
    int i = blockIdx.x * blockDim.x + threadIdx.x;
    if (i >= n4) return;
    const float* in = (blockIdx.y == 0) ? w0 : w1;
    __half* out = (blockIdx.y == 0) ? o0 : o1;
    float4 v = ((const float4*)in)[i];
    __half2* op = (__half2*)out;
    op[2*i]   = __floats2half2_rn(v.x, v.y);
    op[2*i+1] = __floats2half2_rn(v.z, v.w);
}

__global__ void rope_tab_kernel(const int* __restrict__ pos, float2* __restrict__ tab)
{
    int idx = blockIdx.x * blockDim.x + threadIdx.x;
    if (idx >= M_TOT * 64) return;
    int i   = idx & 63;
    int row = idx >> 6;
    int p   = pos[row];
    float inv_freq = powf(10000.0f, -(2.0f * (float)i) / 128.0f);
    float sn, cs;
    sincosf((float)p * inv_freq, &sn, &cs);
    tab[idx] = make_float2(cs, sn);
}

// ============================================================================
// GEMM geometry (verified R5..R10): CTA 128x128, 256 thr, warp tile 64x32,
// BK=32, 3-stage cp.async, one barrier/iter.
// ============================================================================
#define BK        32
#define NITER     (D_MODEL / BK)

__device__ __forceinline__ uint32_t sw_off(int row, int chunk) {
    return (uint32_t)(row * 64 + ((chunk ^ ((row >> 1) & 3)) << 4));
}

#define OFF_AH    0
#define OFF_AL    8192
#define OFF_BH    16384
#define OFF_BL    24576
#define STAGE_B3  32768
#define SMEM_G3   (3 * STAGE_B3 + 128)

__device__ __forceinline__ void issue_stage3(
    uint32_t stage,
    const __nv_bfloat16* __restrict__ Ah, const __nv_bfloat16* __restrict__ Al,
    const __nv_bfloat16* __restrict__ Bh, const __nv_bfloat16* __restrict__ Bl,
    int bm, int bn, int k0, int tid)
{
#pragma unroll
    for (int j = 0; j < 2; j++) {
        int idx = tid + 256 * j;
        int row = idx >> 2;
        int ch  = idx & 3;
        uint32_t so = sw_off(row, ch);
        size_t ga = (size_t)(bm + row) * D_MODEL + k0 + ch * 8;
        size_t gb = (size_t)(bn + row) * D_MODEL + k0 + ch * 8;
        cp16(stage + OFF_AH + so, Ah + ga);
        cp16(stage + OFF_AL + so, Al + ga);
        cp16(stage + OFF_BH + so, Bh + gb);
        cp16(stage + OFF_BL + so, Bl + gb);
    }
}

// QK projection with fused RoPE epilogue -> head-major bf16 hi/lo
__global__ void __launch_bounds__(256, 2) mma_gemmQK_kernel(
    const __nv_bfloat16* __restrict__ Ah, const __nv_bfloat16* __restrict__ Al,
    const __nv_bfloat16* __restrict__ Bh, const __nv_bfloat16* __restrict__ Bl,
    const float2* __restrict__ tab,
    __nv_bfloat16* __restrict__ Qh, __nv_bfloat16* __restrict__ Ql,
    __nv_bfloat16* __restrict__ Kh, __nv_bfloat16* __restrict__ Kl)
{
    extern __shared__ char sm_raw[];
    const uint32_t sbase = (smem_u32(sm_raw) + 127u) & ~127u;

    const int tid  = threadIdx.x;
    const int lane = tid & 31;
    const int w    = tid >> 5;
    const int wm   = (w & 1) * 64;
    const int wn   = (w >> 1) * 32;
    const int bm   = blockIdx.y * 128;
    const int bn   = blockIdx.x * 128;

    const int g  = lane >> 3;
    const int li = lane & 7;
    const int aRowL = li + ((g & 1) << 3);
    const int aChL  = g >> 1;
    const int bRowL = li + ((g >> 1) << 3);
    const int bChL  = g & 1;

    float acc[4][4][4];
#pragma unroll
    for (int mi = 0; mi < 4; mi++)
#pragma unroll
        for (int ni = 0; ni < 4; ni++)
#pragma unroll
            for (int r = 0; r < 4; r++) acc[mi][ni][r] = 0.f;

    issue_stage3(sbase + 0 * STAGE_B3, Ah, Al, Bh, Bl, bm, bn, 0, tid);
    cp_commit();
    issue_stage3(sbase + 1 * STAGE_B3, Ah, Al, Bh, Bl, bm, bn, BK, tid);
    cp_commit();

    int buf = 0, ibuf = 2;
    for (int c = 0; c < NITER; c++) {
        cp_wait_1();
        __syncthreads();
        if (c + 2 < NITER)
            issue_stage3(sbase + (uint32_t)ibuf * STAGE_B3, Ah, Al, Bh, Bl,
                         bm, bn, (c + 2) * BK, tid);
        cp_commit();

        const uint32_t st  = sbase + (uint32_t)buf * STAGE_B3;
        const uint32_t tAh = st + OFF_AH;
        const uint32_t tAl = st + OFF_AL;
        const uint32_t tBh = st + OFF_BH;
        const uint32_t tBl = st + OFF_BL;

#pragma unroll
        for (int ks = 0; ks < 2; ks++) {
            const int aCh = 2 * ks + aChL;
            const int bCh = 2 * ks + bChL;

            uint32_t ah[4][4], bh[4][2], bl[4][2];
#pragma unroll
            for (int mi = 0; mi < 4; mi++)
                ldmatrix_x4(ah[mi], tAh + sw_off(wm + mi * 16 + aRowL, aCh));
#pragma unroll
            for (int p = 0; p < 2; p++) {
                uint32_t t4[4];
                ldmatrix_x4(t4, tBh + sw_off(wn + p * 16 + bRowL, bCh));
                bh[2 * p][0] = t4[0]; bh[2 * p][1] = t4[1];
                bh[2 * p + 1][0] = t4[2]; bh[2 * p + 1][1] = t4[3];
                ldmatrix_x4(t4, tBl + sw_off(wn + p * 16 + bRowL, bCh));
                bl[2 * p][0] = t4[0]; bl[2 * p][1] = t4[1];
                bl[2 * p + 1][0] = t4[2]; bl[2 * p + 1][1] = t4[3];
            }

#pragma unroll
            for (int mi = 0; mi < 4; mi++)
#pragma unroll
                for (int ni = 0; ni < 4; ni++)
                    mma_bf16(acc[mi][ni], ah[mi], bh[ni]);
#pragma unroll
            for (int mi = 0; mi < 4; mi++)
#pragma unroll
                for (int ni = 0; ni < 4; ni++)
                    mma_bf16(acc[mi][ni], ah[mi], bl[ni]);

            uint32_t al[4][4];
#pragma unroll
            for (int mi = 0; mi < 4; mi++)
                ldmatrix_x4(al[mi], tAl + sw_off(wm + mi * 16 + aRowL, aCh));
#pragma unroll
            for (int mi = 0; mi < 4; mi++)
#pragma unroll
                for (int ni = 0; ni < 4; ni++)
                    mma_bf16(acc[mi][ni], al[mi], bh[ni]);
        }
        buf  = (buf == 2)  ? 0 : buf + 1;
        ibuf = (ibuf == 2) ? 0 : ibuf + 1;
    }

    // ---- epilogue: RoPE rotate register pairs, split bf16, head-major store ----
    const int gid = lane >> 2;
    const int tig = lane & 3;
#pragma unroll
    for (int mi = 0; mi < 4; mi++) {
        const int r0 = bm + wm + mi * 16 + gid;
        const int r1 = r0 + 8;
        const int b0 = r0 >> 11, s0 = r0 & 2047;
        const int b1 = r1 >> 11, s1 = r1 & 2047;
#pragma unroll
        for (int ni = 0; ni < 4; ni++) {
            int col = bn + wn + ni * 8 + tig * 2;      // even, in [0,4096)
            int cc  = col & 2047;
            int h   = cc >> 7;
            int d   = cc & 127;
            int i   = d >> 1;
            float2 cs0 = tab[r0 * 64 + i];
            float2 cs1 = tab[r1 * 64 + i];
            float e0 = acc[mi][ni][0] * cs0.x - acc[mi][ni][1] * cs0.y;
            float o0 = acc[mi][ni][0] * cs0.y + acc[mi][ni][1] * cs0.x;
            float e1 = acc[mi][ni][2] * cs1.x - acc[mi][ni][3] * cs1.y;
            float o1 = acc[mi][ni][2] * cs1.y + acc[mi][ni][3] * cs1.x;

            __nv_bfloat16 eh0 = __float2bfloat16(e0), oh0 = __float2bfloat16(o0);
            __nv_bfloat16 eh1 = __float2bfloat16(e1), oh1 = __float2bfloat16(o1);
            __nv_bfloat162 hv0; hv0.x = eh0; hv0.y = oh0;
            __nv_bfloat162 hv1; hv1.x = eh1; hv1.y = oh1;
            __nv_bfloat162 lv0 = bf2(e0 - __bfloat162float(eh0), o0 - __bfloat162float(oh0));
            __nv_bfloat162 lv1 = bf2(e1 - __bfloat162float(eh1), o1 - __bfloat162float(oh1));

            __nv_bfloat16* Hd;
            __nv_bfloat16* Ld;
            if (col < 2048) { Hd = Qh; Ld = Ql; } else { Hd = Kh; Ld = Kl; }
            size_t d0 = ((size_t)((b0 * N_HEADS + h) * SEQ + s0)) * HEAD_DIM + d;
            size_t d1 = ((size_t)((b1 * N_HEADS + h) * SEQ + s1)) * HEAD_DIM + d;
            *(__nv_bfloat162*)(Hd + d0) = hv0;
            *(__nv_bfloat162*)(Ld + d0) = lv0;
            *(__nv_bfloat162*)(Hd + d1) = hv1;
            *(__nv_bfloat162*)(Ld + d1) = lv1;
        }
    }
}

// ---------------------------------------------------------------------------
// fp16 single-pass GEMM. Two epilogues:
//   Vout != nullptr : write fp16 head-major (V projection)
//   else            : write fp32 token-major C (output projection)
// ---------------------------------------------------------------------------
#define OFF_A1    0
#define OFF_B1    8192
#define STAGE_B1  16384
#define SMEM_G1   (3 * STAGE_B1 + 128)

__device__ __forceinline__ void issue_stage1(
    uint32_t stage,
    const __half* __restrict__ A, const __half* __restrict__ B,
    int bm, int bn, int k0, int tid)
{
#pragma unroll
    for (int j = 0; j < 2; j++) {
        int idx = tid + 256 * j;
        int row = idx >> 2;
        int ch  = idx & 3;
        uint32_t so = sw_off(row, ch);
        cp16(stage + OFF_A1 + so, A + (size_t)(bm + row) * D_MODEL + k0 + ch * 8);
        cp16(stage + OFF_B1 + so, B + (size_t)(bn + row) * D_MODEL + k0 + ch * 8);
    }
}

__global__ void __launch_bounds__(256, 2) mma_gemm1_kernel(
    const __half* __restrict__ A, const __half* __restrict__ B,
    float* __restrict__ C, int ldc, __half* __restrict__ Vout)
{
    extern __shared__ char sm_raw[];
    const uint32_t sbase = (smem_u32(sm_raw) + 127u) & ~127u;

    const int tid  = threadIdx.x;
    const int lane = tid & 31;
    const int w    = tid >> 5;
    const int wm   = (w & 1) * 64;
    const int wn   = (w >> 1) * 32;
    const int bm   = blockIdx.y * 128;
    const int bn   = blockIdx.x * 128;

    const int g  = lane >> 3;
    const int li = lane & 7;
    const int aRowL = li + ((g & 1) << 3);
    const int aChL  = g >> 1;
    const int bRowL = li + ((g >> 1) << 3);
    const int bChL  = g & 1;

    float acc[4][4][4];
#pragma unroll
    for (int mi = 0; mi < 4; mi++)
#pragma unroll
        for (int ni = 0; ni < 4; ni++)
#pragma unroll
            for (int r = 0; r < 4; r++) acc[mi][ni][r] = 0.f;

    issue_stage1(sbase + 0 * STAGE_B1, A, B, bm, bn, 0, tid);
    cp_commit();
    issue_stage1(sbase + 1 * STAGE_B1, A, B, bm, bn, BK, tid);
    cp_commit();

    int buf = 0, ibuf = 2;
    for (int c = 0; c < NITER; c++) {
        cp_wait_1();
        __syncthreads();
        if (c + 2 < NITER)
            issue_stage1(sbase + (uint32_t)ibuf * STAGE_B1, A, B,
                         bm, bn, (c + 2) * BK, tid);
        cp_commit();

        const uint32_t st = sbase + (uint32_t)buf * STAGE_B1;
        const uint32_t tA = st + OFF_A1;
        const uint32_t tB = st + OFF_B1;

#pragma unroll
        for (int ks = 0; ks < 2; ks++) {
            const int aCh = 2 * ks + aChL;
            const int bCh = 2 * ks + bChL;

            uint32_t a4[4][4], b2[4][2];
#pragma unroll
            for (int mi = 0; mi < 4; mi++)
                ldmatrix_x4(a4[mi], tA + sw_off(wm + mi * 16 + aRowL, aCh));
#pragma unroll
            for (int p = 0; p < 2; p++) {
                uint32_t t4[4];
                ldmatrix_x4(t4, tB + sw_off(wn + p * 16 + bRowL, bCh));
                b2[2 * p][0] = t4[0]; b2[2 * p][1] = t4[1];
                b2[2 * p + 1][0] = t4[2]; b2[2 * p + 1][1] = t4[3];
            }
#pragma unroll
            for (int mi = 0; mi < 4; mi++)
#pragma unroll
                for (int ni = 0; ni < 4; ni++)
                    mma_f16(acc[mi][ni], a4[mi], b2[ni]);
        }
        buf  = (buf == 2)  ? 0 : buf + 1;
        ibuf = (ibuf == 2) ? 0 : ibuf + 1;
    }

    const int gid = lane >> 2;
    const int tig = lane & 3;
    if (Vout) {
        // V projection: fp16 head-major [bh][seq][128]
#pragma unroll
        for (int mi = 0; mi < 4; mi++) {
            const int r0 = bm + wm + mi * 16 + gid;
            const int r1 = r0 + 8;
            const int b0 = r0 >> 11, s0 = r0 & 2047;
            const int b1 = r1 >> 11, s1 = r1 & 2047;
#pragma unroll
            for (int ni = 0; ni < 4; ni++) {
                int col = bn + wn + ni * 8 + tig * 2;   // [0,2048)
                int h = col >> 7, d = col & 127;
                size_t d0 = ((size_t)((b0 * N_HEADS + h) * SEQ + s0)) * HEAD_DIM + d;
                size_t d1 = ((size_t)((b1 * N_HEADS + h) * SEQ + s1)) * HEAD_DIM + d;
                *(__half2*)(Vout + d0) = __floats2half2_rn(acc[mi][ni][0], acc[mi][ni][1]);
                *(__half2*)(Vout + d1) = __floats2half2_rn(acc[mi][ni][2], acc[mi][ni][3]);
            }
        }
    } else {
#pragma unroll
        for (int mi = 0; mi < 4; mi++) {
#pragma unroll
            for (int ni = 0; ni < 4; ni++) {
                int row = bm + wm + mi * 16 + gid;
                int col = bn + wn + ni * 8 + tig * 2;
                float2 v0 = make_float2(acc[mi][ni][0], acc[mi][ni][1]);
                float2 v1 = make_float2(acc[mi][ni][2], acc[mi][ni][3]);
                *(float2*)(C + (size_t)row * ldc + col) = v0;
                *(float2*)(C + (size_t)(row + 8) * ldc + col) = v1;
            }
        }
    }
}

// ============================================================================
// flash v3: tensor-core causal attention, V single fp16 pass.
// CTA: 64 queries x 1 head, 128 threads. smem: Qh,Ql,Kh,Kl bf16 + Vh fp16 = 80KB.
// Block order reversed so heavy (high-q0) CTAs schedule first.
// ============================================================================
#define FQH 0
#define FQL 16384
#define FKH 32768
#define FKL 49152
#define FVH 65536
#define SMEM_FLASH (81920 + 128)

__device__ __forceinline__ uint32_t fsw(int row, int ch) {
    return (uint32_t)(row * 256 + ((ch ^ (row & 7)) << 4));
}

__global__ void __launch_bounds__(128, 2) flash2_kernel(
    const __nv_bfloat16* __restrict__ Qh, const __nv_bfloat16* __restrict__ Ql,
    const __nv_bfloat16* __restrict__ Kh, const __nv_bfloat16* __restrict__ Kl,
    const __half* __restrict__ Vh,
    __half* __restrict__ Ctx)
{
    extern __shared__ char sm_raw[];
    const uint32_t sb = (smem_u32(sm_raw) + 127u) & ~127u;

    const int tid  = threadIdx.x;
    const int lane = tid & 31;
    const int w    = tid >> 5;
    const int bh   = blockIdx.y;
    const int q0   = (gridDim.x - 1 - blockIdx.x) * 64;   // heavy blocks first
    const size_t hbase = (size_t)bh * SEQ * HEAD_DIM;

    const int g2 = lane >> 3, li = lane & 7;
    const int aRow = w * 16 + ((g2 & 1) << 3) + li;
    const int aChS = g2 >> 1;
    const int bRowK = ((g2 >> 1) << 3) + li;
    const int bChK  = g2 & 1;
    const int vRowS = ((g2 & 1) << 3) + li;
    const int vChS  = g2 >> 1;
    const int gid = lane >> 2, tig = lane & 3;

    // prologue loads: Q tiles + KV tile 0
#pragma unroll
    for (int j = 0; j < 8; j++) {
        int idx = tid + 128 * j; int row = idx >> 4; int ch = idx & 15;
        uint32_t so = fsw(row, ch);
        size_t gq = hbase + (size_t)(q0 + row) * HEAD_DIM + ch * 8;
        cp16(sb + FQH + so, Qh + gq);
        cp16(sb + FQL + so, Ql + gq);
        size_t gk = hbase + (size_t)row * HEAD_DIM + ch * 8;
        cp16(sb + FKH + so, Kh + gk);
        cp16(sb + FKL + so, Kl + gk);
        cp16(sb + FVH + so, Vh + gk);
    }
    cp_commit();

    float o[16][4];
#pragma unroll
    for (int nb = 0; nb < 16; nb++)
#pragma unroll
        for (int r = 0; r < 4; r++) o[nb][r] = 0.f;
    float m0s = -1e30f, m1s = -1e30f, l0 = 0.f, l1 = 0.f;

    const float scale = 0.08838834764831845f;
    const int nt = q0 / 64 + 1;

    for (int kt = 0; kt < nt; kt++) {
        const int k0 = kt * 64;
        cp_wait_0();
        __syncthreads();

        // ---- S = Q K^T (bf16x3) ----
        float s[8][4];
#pragma unroll
        for (int ni = 0; ni < 8; ni++)
#pragma unroll
            for (int r = 0; r < 4; r++) s[ni][r] = 0.f;

#pragma unroll
        for (int kf = 0; kf < 8; kf++) {
            uint32_t ah[4], al4[4];
            ldmatrix_x4(ah,  sb + FQH + fsw(aRow, 2 * kf + aChS));
            ldmatrix_x4(al4, sb + FQL + fsw(aRow, 2 * kf + aChS));
            uint32_t kb[8][2];
#pragma unroll
            for (int p = 0; p < 4; p++) {
                uint32_t t4[4];
                ldmatrix_x4(t4, sb + FKH + fsw(p * 16 + bRowK, 2 * kf + bChK));
                kb[2*p][0] = t4[0]; kb[2*p][1] = t4[1];
                kb[2*p+1][0] = t4[2]; kb[2*p+1][1] = t4[3];
            }
#pragma unroll
            for (int ni = 0; ni < 8; ni++) mma_bf16(s[ni], ah, kb[ni]);
#pragma unroll
            for (int ni = 0; ni < 8; ni++) mma_bf16(s[ni], al4, kb[ni]);
#pragma unroll
            for (int p = 0; p < 4; p++) {
                uint32_t t4[4];
                ldmatrix_x4(t4, sb + FKL + fsw(p * 16 + bRowK, 2 * kf + bChK));
                kb[2*p][0] = t4[0]; kb[2*p][1] = t4[1];
                kb[2*p+1][0] = t4[2]; kb[2*p+1][1] = t4[3];
            }
#pragma unroll
            for (int ni = 0; ni < 8; ni++) mma_bf16(s[ni], ah, kb[ni]);
        }

        // ---- online softmax ----
        const bool diag = (k0 == q0);
        const int row0 = q0 + w * 16 + gid;
        float mx0 = -1e30f, mx1 = -1e30f;
#pragma unroll
        for (int ni = 0; ni < 8; ni++) {
#pragma unroll
            for (int r = 0; r < 4; r++) {
                float v = s[ni][r] * scale;
                if (diag) {
                    int col = k0 + ni * 8 + tig * 2 + (r & 1);
                    int row = row0 + ((r >> 1) << 3);
                    if (col > row) v = -1e30f;
                }
                s[ni][r] = v;
                if (r < 2) mx0 = fmaxf(mx0, v); else mx1 = fmaxf(mx1, v);
            }
        }
        mx0 = fmaxf(mx0, __shfl_xor_sync(0xffffffffu, mx0, 1));
        mx0 = fmaxf(mx0, __shfl_xor_sync(0xffffffffu, mx0, 2));
        mx1 = fmaxf(mx1, __shfl_xor_sync(0xffffffffu, mx1, 1));
        mx1 = fmaxf(mx1, __shfl_xor_sync(0xffffffffu, mx1, 2));

        float mn0 = fmaxf(m0s, mx0), mn1 = fmaxf(m1s, mx1);
        float a0 = __expf(m0s - mn0), a1 = __expf(m1s - mn1);
        float ls0 = 0.f, ls1 = 0.f;
#pragma unroll
        for (int ni = 0; ni < 8; ni++) {
            s[ni][0] = __expf(s[ni][0] - mn0); ls0 += s[ni][0];
            s[ni][1] = __expf(s[ni][1] - mn0); ls0 += s[ni][1];
            s[ni][2] = __expf(s[ni][2] - mn1); ls1 += s[ni][2];
            s[ni][3] = __expf(s[ni][3] - mn1); ls1 += s[ni][3];
        }
        ls0 += __shfl_xor_sync(0xffffffffu, ls0, 1);
        ls0 += __shfl_xor_sync(0xffffffffu, ls0, 2);
        ls1 += __shfl_xor_sync(0xffffffffu, ls1, 1);
        ls1 += __shfl_xor_sync(0xffffffffu, ls1, 2);
        l0 = l0 * a0 + ls0; l1 = l1 * a1 + ls1;
        m0s = mn0; m1s = mn1;
#pragma unroll
        for (int nb = 0; nb < 16; nb++) {
            o[nb][0] *= a0; o[nb][1] *= a0; o[nb][2] *= a1; o[nb][3] *= a1;
        }

        // ---- P -> fp16 fragments ----
        uint32_t P[4][4];
#pragma unroll
        for (int j = 0; j < 4; j++) {
            P[j][0] = pack_h2(s[2*j][0],   s[2*j][1]);
            P[j][1] = pack_h2(s[2*j][2],   s[2*j][3]);
            P[j][2] = pack_h2(s[2*j+1][0], s[2*j+1][1]);
            P[j][3] = pack_h2(s[2*j+1][2], s[2*j+1][3]);
        }

        // ---- ctx += P * V (single fp16 pass) ----
#pragma unroll
        for (int j = 0; j < 4; j++) {
#pragma unroll
            for (int p = 0; p < 8; p++) {
                uint32_t t4[4];
                ldmatrix_x4_t(t4, sb + FVH + fsw(j * 16 + vRowS, 2 * p + vChS));
                uint32_t b0[2] = {t4[0], t4[1]}, b1[2] = {t4[2], t4[3]};
                mma_f16(o[2*p],   P[j], b0);
                mma_f16(o[2*p+1], P[j], b1);
            }
        }

        // prefetch next KV tile
        if (kt + 1 < nt) {
            __syncthreads();
            const int nk0 = (kt + 1) * 64;
#pragma unroll
            for (int j = 0; j < 8; j++) {
                int idx = tid + 128 * j; int row = idx >> 4; int ch = idx & 15;
                uint32_t so = fsw(row, ch);
                size_t gk = hbase + (size_t)(nk0 + row) * HEAD_DIM + ch * 8;
                cp16(sb + FKH + so, Kh + gk);
                cp16(sb + FKL + so, Kl + gk);
                cp16(sb + FVH + so, Vh + gk);
            }
            cp_commit();
        }
    }

    // ---- write ctx (fp16, token-major) ----
    float i0 = 1.0f / l0, i1 = 1.0f / l1;
    const int b = bh >> 4, h = bh & 15;
    size_t t0 = (size_t)(b * SEQ + q0 + w * 16 + gid) * D_MODEL + h * HEAD_DIM;
    size_t t1 = t0 + (size_t)8 * D_MODEL;
#pragma unroll
    for (int nb = 0; nb < 16; nb++) {
        int col = nb * 8 + tig * 2;
        *(__half2*)(Ctx + t0 + col) = __floats2half2_rn(o[nb][0] * i0, o[nb][1] * i0);
        *(__half2*)(Ctx + t1 + col) = __floats2half2_rn(o[nb][2] * i1, o[nb][3] * i1);
    }
}

// ============================================================================
// launch
// ============================================================================
extern "C" void kernel_launch(void* const* d_in, const int* in_sizes, int n_in,
                              void* d_out, int out_size)
{
    const float* x   = (const float*)d_in[0];
    const int*   pos = (const int*)  d_in[1];
    const float* Wq  = (const float*)d_in[2];
    const float* Wk  = (const float*)d_in[3];
    const float* Wv  = (const float*)d_in[4];
    const float* Wo  = (const float*)d_in[5];
    float* out = (float*)d_out;

    __nv_bfloat16 *xh, *xl, *Wh, *Wl, *fQh, *fQl, *fKh, *fKl;
    __half *xf, *cf, *Wvf, *Wof, *fVh;
    float2* tab;
    cudaGetSymbolAddress((void**)&xh, g_xh);
    cudaGetSymbolAddress((void**)&xl, g_xl);
    cudaGetSymbolAddress((void**)&Wh, g_Wh);
    cudaGetSymbolAddress((void**)&Wl, g_Wl);
    cudaGetSymbolAddress((void**)&xf, g_xf);
    cudaGetSymbolAddress((void**)&cf, g_cf);
    cudaGetSymbolAddress((void**)&Wvf, g_Wvf);
    cudaGetSymbolAddress((void**)&Wof, g_Wof);
    cudaGetSymbolAddress((void**)&fQh, g_fQh);
    cudaGetSymbolAddress((void**)&fQl, g_fQl);
    cudaGetSymbolAddress((void**)&fKh, g_fKh);
    cudaGetSymbolAddress((void**)&fKl, g_fKl);
    cudaGetSymbolAddress((void**)&fVh, g_fVh);
    cudaGetSymbolAddress((void**)&tab, g_tab);

    cudaFuncSetAttribute(mma_gemmQK_kernel,
                         cudaFuncAttributeMaxDynamicSharedMemorySize, SMEM_G3);
    cudaFuncSetAttribute(mma_gemm1_kernel,
                         cudaFuncAttributeMaxDynamicSharedMemorySize, SMEM_G1);
    cudaFuncSetAttribute(flash2_kernel,
                         cudaFuncAttributeMaxDynamicSharedMemorySize, SMEM_FLASH);

    const int x_n4 = (M_TOT * D_MODEL) / 4;
    const int w_n4 = (D_MODEL * D_MODEL) / 4;

    // conversions + rope table
    cvt_x_kernel<<<(x_n4 + 255) / 256, 256>>>(x, xh, xl, xf, x_n4);
    dim3 wGrid((w_n4 + 255) / 256, 2);
    cvt2_kernel<<<wGrid, 256>>>(Wq, Wk, Wh, Wl, w_n4);
    cvt_h2_kernel<<<wGrid, 256>>>(Wv, Wo, Wvf, Wof, w_n4);
    rope_tab_kernel<<<(M_TOT * 64 + 255) / 256, 256>>>(pos, tab);

    // Q,K projection (bf16x3) with fused RoPE epilogue -> head-major bf16 hi/lo
    dim3 qkGrid(N_QK / 128, M_TOT / 128);       // (32, 32)
    mma_gemmQK_kernel<<<qkGrid, 256, SMEM_G3>>>(xh, xl, Wh, Wl, tab,
                                                fQh, fQl, fKh, fKl);

    // V projection (fp16) -> head-major fp16
    dim3 vGrid(D_MODEL / 128, M_TOT / 128);     // (16, 32)
    mma_gemm1_kernel<<<vGrid, 256, SMEM_G1>>>(xf, Wvf, nullptr, 0, fVh);

    // tensor-core flash attention -> fp16 ctx (token-major)
    dim3 fGrid(SEQ / 64, N_BH);                 // (32, 32)
    flash2_kernel<<<fGrid, 128, SMEM_FLASH>>>(fQh, fQl, fKh, fKl, fVh, cf);

    // output projection (fp16) -> fp32 out
    mma_gemm1_kernel<<<vGrid, 256, SMEM_G1>>>(cf, Wof, out, D_MODEL, nullptr);
}

// round 14
// speedup vs baseline: 15.7921x; 1.4514x over previous
#include <cuda_runtime.h>
#include <cuda_bf16.h>
#include <cuda_fp16.h>
#include <cstdint>
#include <string.h>
#include <math.h>

// ---------------- problem constants ----------------
#define D_MODEL  2048
#define N_HEADS  16
#define HEAD_DIM 128
#define BATCH    2
#define SEQ      2048
#define M_TOT    (BATCH * SEQ)      // 4096 rows
#define N_QK     (2 * D_MODEL)      // 4096 fused QK width
#define N_BH     (BATCH * N_HEADS)  // 32 head-batches

// ---------------- scratch (alloc-free rule: __device__ globals) ----------------
__device__ __half g_xf  [M_TOT * D_MODEL];          // x in fp16
__device__ __half g_cf  [M_TOT * D_MODEL];          // flash ctx (fp16, token-major)
__device__ __half g_Wqkf[2 * D_MODEL * D_MODEL];    // [Wq;Wk] fp16
__device__ __half g_Wvf [D_MODEL * D_MODEL];
__device__ __half g_Wof [D_MODEL * D_MODEL];

// head-major flash operands [bh][seq][128]
__device__ __nv_bfloat16 g_fQh[N_BH * SEQ * HEAD_DIM];
__device__ __nv_bfloat16 g_fQl[N_BH * SEQ * HEAD_DIM];
__device__ __nv_bfloat16 g_fKh[N_BH * SEQ * HEAD_DIM];
__device__ __nv_bfloat16 g_fKl[N_BH * SEQ * HEAD_DIM];
__device__ __half        g_fVh[N_BH * SEQ * HEAD_DIM];

// rope table: [row 0..4095][i 0..63] -> (cos, sin)
__device__ float2 g_tab[M_TOT * 64];

// ============================================================================
// PTX helpers (compute_103-safe)
// ============================================================================
__device__ __forceinline__ uint32_t smem_u32(const void* p) {
    uint32_t a;
    asm("{ .reg .u64 t; cvta.to.shared.u64 t, %1; cvt.u32.u64 %0, t; }" : "=r"(a) : "l"(p));
    return a;
}
__device__ __forceinline__ void ldmatrix_x4(uint32_t* r, uint32_t addr) {
    asm volatile("ldmatrix.sync.aligned.m8n8.x4.shared.b16 {%0,%1,%2,%3}, [%4];"
                 : "=r"(r[0]), "=r"(r[1]), "=r"(r[2]), "=r"(r[3]) : "r"(addr));
}
__device__ __forceinline__ void ldmatrix_x4_t(uint32_t* r, uint32_t addr) {
    asm volatile("ldmatrix.sync.aligned.m8n8.x4.trans.shared.b16 {%0,%1,%2,%3}, [%4];"
                 : "=r"(r[0]), "=r"(r[1]), "=r"(r[2]), "=r"(r[3]) : "r"(addr));
}
__device__ __forceinline__ void mma_bf16(float* c, const uint32_t* a, const uint32_t* b) {
    asm volatile(
        "mma.sync.aligned.m16n8k16.row.col.f32.bf16.bf16.f32 "
        "{%0,%1,%2,%3}, {%4,%5,%6,%7}, {%8,%9}, {%0,%1,%2,%3};"
        : "+f"(c[0]), "+f"(c[1]), "+f"(c[2]), "+f"(c[3])
        : "r"(a[0]), "r"(a[1]), "r"(a[2]), "r"(a[3]), "r"(b[0]), "r"(b[1]));
}
__device__ __forceinline__ void mma_f16(float* c, const uint32_t* a, const uint32_t* b) {
    asm volatile(
        "mma.sync.aligned.m16n8k16.row.col.f32.f16.f16.f32 "
        "{%0,%1,%2,%3}, {%4,%5,%6,%7}, {%8,%9}, {%0,%1,%2,%3};"
        : "+f"(c[0]), "+f"(c[1]), "+f"(c[2]), "+f"(c[3])
        : "r"(a[0]), "r"(a[1]), "r"(a[2]), "r"(a[3]), "r"(b[0]), "r"(b[1]));
}
__device__ __forceinline__ void cp16(uint32_t s, const void* g) {
    asm volatile("cp.async.cg.shared.global [%0], [%1], 16;" :: "r"(s), "l"(g));
}
__device__ __forceinline__ void cp_commit() {
    asm volatile("cp.async.commit_group;" ::: "memory");
}
__device__ __forceinline__ void cp_wait_1() {
    asm volatile("cp.async.wait_group 1;" ::: "memory");
}
__device__ __forceinline__ void cp_wait_0() {
    asm volatile("cp.async.wait_group 0;" ::: "memory");
}
__device__ __forceinline__ uint32_t pack_h2(float a, float b) {
    __half2 h = __floats2half2_rn(a, b);
    uint32_t u; memcpy(&u, &h, 4);
    return u;
}
__device__ __forceinline__ __nv_bfloat162 bf2(float a, float b) {
    __nv_bfloat162 v; v.x = __float2bfloat16(a); v.y = __float2bfloat16(b);
    return v;
}

// ============================================================================
// conversions + rope table
// ============================================================================
__global__ void cvt_h_kernel(const float* __restrict__ in,
                             __half* __restrict__ out, int n4)
{
    int i = blockIdx.x * blockDim.x + threadIdx.x;
    if (i >= n4) return;
    float4 v = ((const float4*)in)[i];
    __half2* op = (__half2*)out;
    op[2*i]   = __floats2half2_rn(v.x, v.y);
    op[2*i+1] = __floats2half2_rn(v.z, v.w);
}

// all 4 weight matrices -> fp16 in one launch
__global__ void cvt_w4_kernel(const float* __restrict__ wq, const float* __restrict__ wk,
                              const float* __restrict__ wv, const float* __restrict__ wo,
                              __half* __restrict__ qk, __half* __restrict__ v,
                              __half* __restrict__ o, int n4each)
{
    int i = blockIdx.x * blockDim.x + threadIdx.x;
    if (i >= n4each) return;
    const float* in;
    __half* out;
    switch (blockIdx.y) {
        case 0: in = wq; out = qk; break;
        case 1: in = wk; out = qk + (size_t)D_MODEL * D_MODEL; break;
        case 2: in = wv; out = v; break;
        default: in = wo; out = o; break;
    }
    float4 vv = ((const float4*)in)[i];
    __half2* op = (__half2*)out;
    op[2*i]   = __floats2half2_rn(vv.x, vv.y);
    op[2*i+1] = __floats2half2_rn(vv.z, vv.w);
}

__global__ void rope_tab_kernel(const int* __restrict__ pos, float2* __restrict__ tab)
{
    int idx = blockIdx.x * blockDim.x + threadIdx.x;
    if (idx >= M_TOT * 64) return;
    int i   = idx & 63;
    int row = idx >> 6;
    int p   = pos[row];
    float inv_freq = powf(10000.0f, -(2.0f * (float)i) / 128.0f);
    float sn, cs;
    sincosf((float)p * inv_freq, &sn, &cs);
    tab[idx] = make_float2(cs, sn);
}

// ============================================================================
// GEMM geometry (verified R5..R13): CTA 128x128, 256 thr, warp tile 64x32,
// BK=32, 3-stage cp.async, one barrier/iter. fp16 single-pass.
// ============================================================================
#define BK        32
#define NITER     (D_MODEL / BK)

__device__ __forceinline__ uint32_t sw_off(int row, int chunk) {
    return (uint32_t)(row * 64 + ((chunk ^ ((row >> 1) & 3)) << 4));
}

#define OFF_A1    0
#define OFF_B1    8192
#define STAGE_B1  16384
#define SMEM_G1   (3 * STAGE_B1 + 128)

__device__ __forceinline__ void issue_stage1(
    uint32_t stage,
    const __half* __restrict__ A, const __half* __restrict__ B,
    int bm, int bn, int k0, int tid)
{
#pragma unroll
    for (int j = 0; j < 2; j++) {
        int idx = tid + 256 * j;
        int row = idx >> 2;
        int ch  = idx & 3;
        uint32_t so = sw_off(row, ch);
        cp16(stage + OFF_A1 + so, A + (size_t)(bm + row) * D_MODEL + k0 + ch * 8);
        cp16(stage + OFF_B1 + so, B + (size_t)(bn + row) * D_MODEL + k0 + ch * 8);
    }
}

// shared mainloop producing acc[4][4][4]
#define GEMM1_MAINLOOP(A, B)                                                  \
    float acc[4][4][4];                                                       \
    _Pragma("unroll")                                                         \
    for (int mi = 0; mi < 4; mi++)                                            \
        _Pragma("unroll")                                                     \
        for (int ni = 0; ni < 4; ni++)                                        \
            _Pragma("unroll")                                                 \
            for (int r = 0; r < 4; r++) acc[mi][ni][r] = 0.f;                 \
    issue_stage1(sbase + 0 * STAGE_B1, A, B, bm, bn, 0, tid);                 \
    cp_commit();                                                              \
    issue_stage1(sbase + 1 * STAGE_B1, A, B, bm, bn, BK, tid);                \
    cp_commit();                                                              \
    int buf = 0, ibuf = 2;                                                    \
    for (int c = 0; c < NITER; c++) {                                         \
        cp_wait_1();                                                          \
        __syncthreads();                                                      \
        if (c + 2 < NITER)                                                    \
            issue_stage1(sbase + (uint32_t)ibuf * STAGE_B1, A, B,             \
                         bm, bn, (c + 2) * BK, tid);                          \
        cp_commit();                                                          \
        const uint32_t st = sbase + (uint32_t)buf * STAGE_B1;                 \
        const uint32_t tA = st + OFF_A1;                                      \
        const uint32_t tB = st + OFF_B1;                                      \
        _Pragma("unroll")                                                     \
        for (int ks = 0; ks < 2; ks++) {                                      \
            const int aCh = 2 * ks + aChL;                                    \
            const int bCh = 2 * ks + bChL;                                    \
            uint32_t a4[4][4], b2[4][2];                                      \
            _Pragma("unroll")                                                 \
            for (int mi = 0; mi < 4; mi++)                                    \
                ldmatrix_x4(a4[mi], tA + sw_off(wm + mi * 16 + aRowL, aCh));  \
            _Pragma("unroll")                                                 \
            for (int p = 0; p < 2; p++) {                                     \
                uint32_t t4[4];                                               \
                ldmatrix_x4(t4, tB + sw_off(wn + p * 16 + bRowL, bCh));       \
                b2[2 * p][0] = t4[0]; b2[2 * p][1] = t4[1];                   \
                b2[2 * p + 1][0] = t4[2]; b2[2 * p + 1][1] = t4[3];           \
            }                                                                 \
            _Pragma("unroll")                                                 \
            for (int mi = 0; mi < 4; mi++)                                    \
                _Pragma("unroll")                                             \
                for (int ni = 0; ni < 4; ni++)                                \
                    mma_f16(acc[mi][ni], a4[mi], b2[ni]);                     \
        }                                                                     \
        buf  = (buf == 2)  ? 0 : buf + 1;                                     \
        ibuf = (ibuf == 2) ? 0 : ibuf + 1;                                    \
    }

// QK projection (fp16 single pass) with fused RoPE epilogue -> bf16 hi/lo head-major
__global__ void __launch_bounds__(256, 2) mma_gemmQK_kernel(
    const __half* __restrict__ A, const __half* __restrict__ B,
    const float2* __restrict__ tab,
    __nv_bfloat16* __restrict__ Qh, __nv_bfloat16* __restrict__ Ql,
    __nv_bfloat16* __restrict__ Kh, __nv_bfloat16* __restrict__ Kl)
{
    extern __shared__ char sm_raw[];
    const uint32_t sbase = (smem_u32(sm_raw) + 127u) & ~127u;

    const int tid  = threadIdx.x;
    const int lane = tid & 31;
    const int w    = tid >> 5;
    const int wm   = (w & 1) * 64;
    const int wn   = (w >> 1) * 32;
    const int bm   = blockIdx.y * 128;
    const int bn   = blockIdx.x * 128;

    const int g  = lane >> 3;
    const int li = lane & 7;
    const int aRowL = li + ((g & 1) << 3);
    const int aChL  = g >> 1;
    const int bRowL = li + ((g >> 1) << 3);
    const int bChL  = g & 1;

    GEMM1_MAINLOOP(A, B)

    // ---- epilogue: RoPE rotate register pairs, split bf16, head-major store ----
    const int gid = lane >> 2;
    const int tig = lane & 3;
#pragma unroll
    for (int mi = 0; mi < 4; mi++) {
        const int r0 = bm + wm + mi * 16 + gid;
        const int r1 = r0 + 8;
        const int b0 = r0 >> 11, s0 = r0 & 2047;
        const int b1 = r1 >> 11, s1 = r1 & 2047;
#pragma unroll
        for (int ni = 0; ni < 4; ni++) {
            int col = bn + wn + ni * 8 + tig * 2;      // even, in [0,4096)
            int cc  = col & 2047;
            int h   = cc >> 7;
            int d   = cc & 127;
            int i   = d >> 1;
            float2 cs0 = tab[r0 * 64 + i];
            float2 cs1 = tab[r1 * 64 + i];
            float e0 = acc[mi][ni][0] * cs0.x - acc[mi][ni][1] * cs0.y;
            float o0 = acc[mi][ni][0] * cs0.y + acc[mi][ni][1] * cs0.x;
            float e1 = acc[mi][ni][2] * cs1.x - acc[mi][ni][3] * cs1.y;
            float o1 = acc[mi][ni][2] * cs1.y + acc[mi][ni][3] * cs1.x;

            __nv_bfloat16 eh0 = __float2bfloat16(e0), oh0 = __float2bfloat16(o0);
            __nv_bfloat16 eh1 = __float2bfloat16(e1), oh1 = __float2bfloat16(o1);
            __nv_bfloat162 hv0; hv0.x = eh0; hv0.y = oh0;
            __nv_bfloat162 hv1; hv1.x = eh1; hv1.y = oh1;
            __nv_bfloat162 lv0 = bf2(e0 - __bfloat162float(eh0), o0 - __bfloat162float(oh0));
            __nv_bfloat162 lv1 = bf2(e1 - __bfloat162float(eh1), o1 - __bfloat162float(oh1));

            __nv_bfloat16* Hd;
            __nv_bfloat16* Ld;
            if (col < 2048) { Hd = Qh; Ld = Ql; } else { Hd = Kh; Ld = Kl; }
            size_t d0 = ((size_t)((b0 * N_HEADS + h) * SEQ + s0)) * HEAD_DIM + d;
            size_t d1 = ((size_t)((b1 * N_HEADS + h) * SEQ + s1)) * HEAD_DIM + d;
            *(__nv_bfloat162*)(Hd + d0) = hv0;
            *(__nv_bfloat162*)(Ld + d0) = lv0;
            *(__nv_bfloat162*)(Hd + d1) = hv1;
            *(__nv_bfloat162*)(Ld + d1) = lv1;
        }
    }
}

// fp16 GEMM, two epilogues: Vout -> fp16 head-major; else fp32 token-major.
__global__ void __launch_bounds__(256, 2) mma_gemm1_kernel(
    const __half* __restrict__ A, const __half* __restrict__ B,
    float* __restrict__ C, int ldc, __half* __restrict__ Vout)
{
    extern __shared__ char sm_raw[];
    const uint32_t sbase = (smem_u32(sm_raw) + 127u) & ~127u;

    const int tid  = threadIdx.x;
    const int lane = tid & 31;
    const int w    = tid >> 5;
    const int wm   = (w & 1) * 64;
    const int wn   = (w >> 1) * 32;
    const int bm   = blockIdx.y * 128;
    const int bn   = blockIdx.x * 128;

    const int g  = lane >> 3;
    const int li = lane & 7;
    const int aRowL = li + ((g & 1) << 3);
    const int aChL  = g >> 1;
    const int bRowL = li + ((g >> 1) << 3);
    const int bChL  = g & 1;

    GEMM1_MAINLOOP(A, B)

    const int gid = lane >> 2;
    const int tig = lane & 3;
    if (Vout) {
#pragma unroll
        for (int mi = 0; mi < 4; mi++) {
            const int r0 = bm + wm + mi * 16 + gid;
            const int r1 = r0 + 8;
            const int b0 = r0 >> 11, s0 = r0 & 2047;
            const int b1 = r1 >> 11, s1 = r1 & 2047;
#pragma unroll
            for (int ni = 0; ni < 4; ni++) {
                int col = bn + wn + ni * 8 + tig * 2;   // [0,2048)
                int h = col >> 7, d = col & 127;
                size_t d0 = ((size_t)((b0 * N_HEADS + h) * SEQ + s0)) * HEAD_DIM + d;
                size_t d1 = ((size_t)((b1 * N_HEADS + h) * SEQ + s1)) * HEAD_DIM + d;
                *(__half2*)(Vout + d0) = __floats2half2_rn(acc[mi][ni][0], acc[mi][ni][1]);
                *(__half2*)(Vout + d1) = __floats2half2_rn(acc[mi][ni][2], acc[mi][ni][3]);
            }
        }
    } else {
#pragma unroll
        for (int mi = 0; mi < 4; mi++) {
#pragma unroll
            for (int ni = 0; ni < 4; ni++) {
                int row = bm + wm + mi * 16 + gid;
                int col = bn + wn + ni * 8 + tig * 2;
                float2 v0 = make_float2(acc[mi][ni][0], acc[mi][ni][1]);
                float2 v1 = make_float2(acc[mi][ni][2], acc[mi][ni][3]);
                *(float2*)(C + (size_t)row * ldc + col) = v0;
                *(float2*)(C + (size_t)(row + 8) * ldc + col) = v1;
            }
        }
    }
}

// ============================================================================
// flash v3 (verified R13): tensor-core causal attention, V single fp16 pass.
// ============================================================================
#define FQH 0
#define FQL 16384
#define FKH 32768
#define FKL 49152
#define FVH 65536
#define SMEM_FLASH (81920 + 128)

__device__ __forceinline__ uint32_t fsw(int row, int ch) {
    return (uint32_t)(row * 256 + ((ch ^ (row & 7)) << 4));
}

__global__ void __launch_bounds__(128, 2) flash2_kernel(
    const __nv_bfloat16* __restrict__ Qh, const __nv_bfloat16* __restrict__ Ql,
    const __nv_bfloat16* __restrict__ Kh, const __nv_bfloat16* __restrict__ Kl,
    const __half* __restrict__ Vh,
    __half* __restrict__ Ctx)
{
    extern __shared__ char sm_raw[];
    const uint32_t sb = (smem_u32(sm_raw) + 127u) & ~127u;

    const int tid  = threadIdx.x;
    const int lane = tid & 31;
    const int w    = tid >> 5;
    const int bh   = blockIdx.y;
    const int q0   = (gridDim.x - 1 - blockIdx.x) * 64;
    const size_t hbase = (size_t)bh * SEQ * HEAD_DIM;

    const int g2 = lane >> 3, li = lane & 7;
    const int aRow = w * 16 + ((g2 & 1) << 3) + li;
    const int aChS = g2 >> 1;
    const int bRowK = ((g2 >> 1) << 3) + li;
    const int bChK  = g2 & 1;
    const int vRowS = ((g2 & 1) << 3) + li;
    const int vChS  = g2 >> 1;
    const int gid = lane >> 2, tig = lane & 3;

#pragma unroll
    for (int j = 0; j < 8; j++) {
        int idx = tid + 128 * j; int row = idx >> 4; int ch = idx & 15;
        uint32_t so = fsw(row, ch);
        size_t gq = hbase + (size_t)(q0 + row) * HEAD_DIM + ch * 8;
        cp16(sb + FQH + so, Qh + gq);
        cp16(sb + FQL + so, Ql + gq);
        size_t gk = hbase + (size_t)row * HEAD_DIM + ch * 8;
        cp16(sb + FKH + so, Kh + gk);
        cp16(sb + FKL + so, Kl + gk);
        cp16(sb + FVH + so, Vh + gk);
    }
    cp_commit();

    float o[16][4];
#pragma unroll
    for (int nb = 0; nb < 16; nb++)
#pragma unroll
        for (int r = 0; r < 4; r++) o[nb][r] = 0.f;
    float m0s = -1e30f, m1s = -1e30f, l0 = 0.f, l1 = 0.f;

    const float scale = 0.08838834764831845f;
    const int nt = q0 / 64 + 1;

    for (int kt = 0; kt < nt; kt++) {
        const int k0 = kt * 64;
        cp_wait_0();
        __syncthreads();

        float s[8][4];
#pragma unroll
        for (int ni = 0; ni < 8; ni++)
#pragma unroll
            for (int r = 0; r < 4; r++) s[ni][r] = 0.f;

#pragma unroll
        for (int kf = 0; kf < 8; kf++) {
            uint32_t ah[4], al4[4];
            ldmatrix_x4(ah,  sb + FQH + fsw(aRow, 2 * kf + aChS));
            ldmatrix_x4(al4, sb + FQL + fsw(aRow, 2 * kf + aChS));
            uint32_t kb[8][2];
#pragma unroll
            for (int p = 0; p < 4; p++) {
                uint32_t t4[4];
                ldmatrix_x4(t4, sb + FKH + fsw(p * 16 + bRowK, 2 * kf + bChK));
                kb[2*p][0] = t4[0]; kb[2*p][1] = t4[1];
                kb[2*p+1][0] = t4[2]; kb[2*p+1][1] = t4[3];
            }
#pragma unroll
            for (int ni = 0; ni < 8; ni++) mma_bf16(s[ni], ah, kb[ni]);
#pragma unroll
            for (int ni = 0; ni < 8; ni++) mma_bf16(s[ni], al4, kb[ni]);
#pragma unroll
            for (int p = 0; p < 4; p++) {
                uint32_t t4[4];
                ldmatrix_x4(t4, sb + FKL + fsw(p * 16 + bRowK, 2 * kf + bChK));
                kb[2*p][0] = t4[0]; kb[2*p][1] = t4[1];
                kb[2*p+1][0] = t4[2]; kb[2*p+1][1] = t4[3];
            }
#pragma unroll
            for (int ni = 0; ni < 8; ni++) mma_bf16(s[ni], ah, kb[ni]);
        }

        const bool diag = (k0 == q0);
        const int row0 = q0 + w * 16 + gid;
        float mx0 = -1e30f, mx1 = -1e30f;
#pragma unroll
        for (int ni = 0; ni < 8; ni++) {
#pragma unroll
            for (int r = 0; r < 4; r++) {
                float v = s[ni][r] * scale;
                if (diag) {
                    int col = k0 + ni * 8 + tig * 2 + (r & 1);
                    int row = row0 + ((r >> 1) << 3);
                    if (col > row) v = -1e30f;
                }
                s[ni][r] = v;
                if (r < 2) mx0 = fmaxf(mx0, v); else mx1 = fmaxf(mx1, v);
            }
        }
        mx0 = fmaxf(mx0, __shfl_xor_sync(0xffffffffu, mx0, 1));
        mx0 = fmaxf(mx0, __shfl_xor_sync(0xffffffffu, mx0, 2));
        mx1 = fmaxf(mx1, __shfl_xor_sync(0xffffffffu, mx1, 1));
        mx1 = fmaxf(mx1, __shfl_xor_sync(0xffffffffu, mx1, 2));

        float mn0 = fmaxf(m0s, mx0), mn1 = fmaxf(m1s, mx1);
        float a0 = __expf(m0s - mn0), a1 = __expf(m1s - mn1);
        float ls0 = 0.f, ls1 = 0.f;
#pragma unroll
        for (int ni = 0; ni < 8; ni++) {
            s[ni][0] = __expf(s[ni][0] - mn0); ls0 += s[ni][0];
            s[ni][1] = __expf(s[ni][1] - mn0); ls0 += s[ni][1];
            s[ni][2] = __expf(s[ni][2] - mn1); ls1 += s[ni][2];
            s[ni][3] = __expf(s[ni][3] - mn1); ls1 += s[ni][3];
        }
        ls0 += __shfl_xor_sync(0xffffffffu, ls0, 1);
        ls0 += __shfl_xor_sync(0xffffffffu, ls0, 2);
        ls1 += __shfl_xor_sync(0xffffffffu, ls1, 1);
        ls1 += __shfl_xor_sync(0xffffffffu, ls1, 2);
        l0 = l0 * a0 + ls0; l1 = l1 * a1 + ls1;
        m0s = mn0; m1s = mn1;
#pragma unroll
        for (int nb = 0; nb < 16; nb++) {
            o[nb][0] *= a0; o[nb][1] *= a0; o[nb][2] *= a1; o[nb][3] *= a1;
        }

        uint32_t P[4][4];
#pragma unroll
        for (int j = 0; j < 4; j++) {
            P[j][0] = pack_h2(s[2*j][0],   s[2*j][1]);
            P[j][1] = pack_h2(s[2*j][2],   s[2*j][3]);
            P[j][2] = pack_h2(s[2*j+1][0], s[2*j+1][1]);
            P[j][3] = pack_h2(s[2*j+1][2], s[2*j+1][3]);
        }

#pragma unroll
        for (int j = 0; j < 4; j++) {
#pragma unroll
            for (int p = 0; p < 8; p++) {
                uint32_t t4[4];
                ldmatrix_x4_t(t4, sb + FVH + fsw(j * 16 + vRowS, 2 * p + vChS));
                uint32_t b0[2] = {t4[0], t4[1]}, b1[2] = {t4[2], t4[3]};
                mma_f16(o[2*p],   P[j], b0);
                mma_f16(o[2*p+1], P[j], b1);
            }
        }

        if (kt + 1 < nt) {
            __syncthreads();
            const int nk0 = (kt + 1) * 64;
#pragma unroll
            for (int j = 0; j < 8; j++) {
                int idx = tid + 128 * j; int row = idx >> 4; int ch = idx & 15;
                uint32_t so = fsw(row, ch);
                size_t gk = hbase + (size_t)(nk0 + row) * HEAD_DIM + ch * 8;
                cp16(sb + FKH + so, Kh + gk);
                cp16(sb + FKL + so, Kl + gk);
                cp16(sb + FVH + so, Vh + gk);
            }
            cp_commit();
        }
    }

    float i0 = 1.0f / l0, i1 = 1.0f / l1;
    const int b = bh >> 4, h = bh & 15;
    size_t t0 = (size_t)(b * SEQ + q0 + w * 16 + gid) * D_MODEL + h * HEAD_DIM;
    size_t t1 = t0 + (size_t)8 * D_MODEL;
#pragma unroll
    for (int nb = 0; nb < 16; nb++) {
        int col = nb * 8 + tig * 2;
        *(__half2*)(Ctx + t0 + col) = __floats2half2_rn(o[nb][0] * i0, o[nb][1] * i0);
        *(__half2*)(Ctx + t1 + col) = __floats2half2_rn(o[nb][2] * i1, o[nb][3] * i1);
    }
}

// ============================================================================
// launch
// ============================================================================
extern "C" void kernel_launch(void* const* d_in, const int* in_sizes, int n_in,
                              void* d_out, int out_size)
{
    const float* x   = (const float*)d_in[0];
    const int*   pos = (const int*)  d_in[1];
    const float* Wq  = (const float*)d_in[2];
    const float* Wk  = (const float*)d_in[3];
    const float* Wv  = (const float*)d_in[4];
    const float* Wo  = (const float*)d_in[5];
    float* out = (float*)d_out;

    __nv_bfloat16 *fQh, *fQl, *fKh, *fKl;
    __half *xf, *cf, *Wqkf, *Wvf, *Wof, *fVh;
    float2* tab;
    cudaGetSymbolAddress((void**)&xf, g_xf);
    cudaGetSymbolAddress((void**)&cf, g_cf);
    cudaGetSymbolAddress((void**)&Wqkf, g_Wqkf);
    cudaGetSymbolAddress((void**)&Wvf, g_Wvf);
    cudaGetSymbolAddress((void**)&Wof, g_Wof);
    cudaGetSymbolAddress((void**)&fQh, g_fQh);
    cudaGetSymbolAddress((void**)&fQl, g_fQl);
    cudaGetSymbolAddress((void**)&fKh, g_fKh);
    cudaGetSymbolAddress((void**)&fKl, g_fKl);
    cudaGetSymbolAddress((void**)&fVh, g_fVh);
    cudaGetSymbolAddress((void**)&tab, g_tab);

    cudaFuncSetAttribute(mma_gemmQK_kernel,
                         cudaFuncAttributeMaxDynamicSharedMemorySize, SMEM_G1);
    cudaFuncSetAttribute(mma_gemm1_kernel,
                         cudaFuncAttributeMaxDynamicSharedMemorySize, SMEM_G1);
    cudaFuncSetAttribute(flash2_kernel,
                         cudaFuncAttributeMaxDynamicSharedMemorySize, SMEM_FLASH);

    const int x_n4 = (M_TOT * D_MODEL) / 4;
    const int w_n4 = (D_MODEL * D_MODEL) / 4;

    // conversions + rope table
    cvt_h_kernel<<<(x_n4 + 255) / 256, 256>>>(x, xf, x_n4);
    dim3 wGrid((w_n4 + 255) / 256, 4);
    cvt_w4_kernel<<<wGrid, 256>>>(Wq, Wk, Wv, Wo, Wqkf, Wvf, Wof, w_n4);
    rope_tab_kernel<<<(M_TOT * 64 + 255) / 256, 256>>>(pos, tab);

    // Q,K projection (fp16 single pass, fused N=4096) + RoPE epilogue
    dim3 qkGrid(N_QK / 128, M_TOT / 128);       // (32, 32)
    mma_gemmQK_kernel<<<qkGrid, 256, SMEM_G1>>>(xf, Wqkf, tab, fQh, fQl, fKh, fKl);

    // V projection (fp16) -> head-major fp16
    dim3 vGrid(D_MODEL / 128, M_TOT / 128);     // (16, 32)
    mma_gemm1_kernel<<<vGrid, 256, SMEM_G1>>>(xf, Wvf, nullptr, 0, fVh);

    // tensor-core flash attention -> fp16 ctx (token-major)
    dim3 fGrid(SEQ / 64, N_BH);                 // (32, 32)
    flash2_kernel<<<fGrid, 128, SMEM_FLASH>>>(fQh, fQl, fKh, fKl, fVh, cf);

    // output projection (fp16) -> fp32 out
    mma_gemm1_kernel<<<vGrid, 256, SMEM_G1>>>(cf, Wof, out, D_MODEL, nullptr);
}

// round 15
// speedup vs baseline: 18.1954x; 1.1522x over previous
#include <cuda_runtime.h>
#include <cuda_bf16.h>
#include <cuda_fp16.h>
#include <cstdint>
#include <string.h>
#include <math.h>

// ---------------- problem constants ----------------
#define D_MODEL  2048
#define N_HEADS  16
#define HEAD_DIM 128
#define BATCH    2
#define SEQ      2048
#define M_TOT    (BATCH * SEQ)      // 4096 rows
#define N_QKV    (3 * D_MODEL)      // 6144 fused QKV width
#define N_BH     (BATCH * N_HEADS)  // 32 head-batches

// ---------------- scratch (alloc-free rule: __device__ globals) ----------------
__device__ __half g_xf   [M_TOT * D_MODEL];         // x in fp16
__device__ __half g_cf   [M_TOT * D_MODEL];         // flash ctx (fp16, token-major)
__device__ __half g_Wqkvf[3 * D_MODEL * D_MODEL];   // [Wq;Wk;Wv] fp16
__device__ __half g_Wof  [D_MODEL * D_MODEL];

// head-major flash operands [bh][seq][128], all fp16
__device__ __half g_fQ[N_BH * SEQ * HEAD_DIM];
__device__ __half g_fK[N_BH * SEQ * HEAD_DIM];
__device__ __half g_fV[N_BH * SEQ * HEAD_DIM];

// rope table: [row 0..4095][i 0..63] -> (cos, sin)
__device__ float2 g_tab[M_TOT * 64];

// ============================================================================
// PTX helpers (compute_103-safe)
// ============================================================================
__device__ __forceinline__ uint32_t smem_u32(const void* p) {
    uint32_t a;
    asm("{ .reg .u64 t; cvta.to.shared.u64 t, %1; cvt.u32.u64 %0, t; }" : "=r"(a) : "l"(p));
    return a;
}
__device__ __forceinline__ void ldmatrix_x4(uint32_t* r, uint32_t addr) {
    asm volatile("ldmatrix.sync.aligned.m8n8.x4.shared.b16 {%0,%1,%2,%3}, [%4];"
                 : "=r"(r[0]), "=r"(r[1]), "=r"(r[2]), "=r"(r[3]) : "r"(addr));
}
__device__ __forceinline__ void ldmatrix_x4_t(uint32_t* r, uint32_t addr) {
    asm volatile("ldmatrix.sync.aligned.m8n8.x4.trans.shared.b16 {%0,%1,%2,%3}, [%4];"
                 : "=r"(r[0]), "=r"(r[1]), "=r"(r[2]), "=r"(r[3]) : "r"(addr));
}
__device__ __forceinline__ void mma_f16(float* c, const uint32_t* a, const uint32_t* b) {
    asm volatile(
        "mma.sync.aligned.m16n8k16.row.col.f32.f16.f16.f32 "
        "{%0,%1,%2,%3}, {%4,%5,%6,%7}, {%8,%9}, {%0,%1,%2,%3};"
        : "+f"(c[0]), "+f"(c[1]), "+f"(c[2]), "+f"(c[3])
        : "r"(a[0]), "r"(a[1]), "r"(a[2]), "r"(a[3]), "r"(b[0]), "r"(b[1]));
}
__device__ __forceinline__ void cp16(uint32_t s, const void* g) {
    asm volatile("cp.async.cg.shared.global [%0], [%1], 16;" :: "r"(s), "l"(g));
}
__device__ __forceinline__ void cp_commit() {
    asm volatile("cp.async.commit_group;" ::: "memory");
}
__device__ __forceinline__ void cp_wait_1() {
    asm volatile("cp.async.wait_group 1;" ::: "memory");
}
__device__ __forceinline__ void cp_wait_0() {
    asm volatile("cp.async.wait_group 0;" ::: "memory");
}
__device__ __forceinline__ uint32_t pack_h2(float a, float b) {
    __half2 h = __floats2half2_rn(a, b);
    uint32_t u; memcpy(&u, &h, 4);
    return u;
}

// ============================================================================
// conversions + rope table
// ============================================================================
__global__ void cvt_h_kernel(const float* __restrict__ in,
                             __half* __restrict__ out, int n4)
{
    int i = blockIdx.x * blockDim.x + threadIdx.x;
    if (i >= n4) return;
    float4 v = ((const float4*)in)[i];
    __half2* op = (__half2*)out;
    op[2*i]   = __floats2half2_rn(v.x, v.y);
    op[2*i+1] = __floats2half2_rn(v.z, v.w);
}

// all 4 weight matrices -> fp16 in one launch ([Wq;Wk;Wv] packed, Wo separate)
__global__ void cvt_w4_kernel(const float* __restrict__ wq, const float* __restrict__ wk,
                              const float* __restrict__ wv, const float* __restrict__ wo,
                              __half* __restrict__ qkv, __half* __restrict__ o, int n4each)
{
    int i = blockIdx.x * blockDim.x + threadIdx.x;
    if (i >= n4each) return;
    const float* in;
    __half* out;
    switch (blockIdx.y) {
        case 0: in = wq; out = qkv; break;
        case 1: in = wk; out = qkv + 1 * (size_t)D_MODEL * D_MODEL; break;
        case 2: in = wv; out = qkv + 2 * (size_t)D_MODEL * D_MODEL; break;
        default: in = wo; out = o; break;
    }
    float4 vv = ((const float4*)in)[i];
    __half2* op = (__half2*)out;
    op[2*i]   = __floats2half2_rn(vv.x, vv.y);
    op[2*i+1] = __floats2half2_rn(vv.z, vv.w);
}

__global__ void rope_tab_kernel(const int* __restrict__ pos, float2* __restrict__ tab)
{
    int idx = blockIdx.x * blockDim.x + threadIdx.x;
    if (idx >= M_TOT * 64) return;
    int i   = idx & 63;
    int row = idx >> 6;
    int p   = pos[row];
    float inv_freq = powf(10000.0f, -(2.0f * (float)i) / 128.0f);
    float sn, cs;
    sincosf((float)p * inv_freq, &sn, &cs);
    tab[idx] = make_float2(cs, sn);
}

// ============================================================================
// GEMM geometry (verified R5..R14): CTA 128x128, 256 thr, warp tile 64x32,
// BK=32, 3-stage cp.async, one barrier/iter, fp16 single-pass.
// ============================================================================
#define BK        32
#define NITER     (D_MODEL / BK)

__device__ __forceinline__ uint32_t sw_off(int row, int chunk) {
    return (uint32_t)(row * 64 + ((chunk ^ ((row >> 1) & 3)) << 4));
}

#define OFF_A1    0
#define OFF_B1    8192
#define STAGE_B1  16384
#define SMEM_G1   (3 * STAGE_B1 + 128)

__device__ __forceinline__ void issue_stage1(
    uint32_t stage,
    const __half* __restrict__ A, const __half* __restrict__ B,
    int bm, int bn, int k0, int tid)
{
#pragma unroll
    for (int j = 0; j < 2; j++) {
        int idx = tid + 256 * j;
        int row = idx >> 2;
        int ch  = idx & 3;
        uint32_t so = sw_off(row, ch);
        cp16(stage + OFF_A1 + so, A + (size_t)(bm + row) * D_MODEL + k0 + ch * 8);
        cp16(stage + OFF_B1 + so, B + (size_t)(bn + row) * D_MODEL + k0 + ch * 8);
    }
}

#define GEMM1_MAINLOOP(A, B)                                                  \
    float acc[4][4][4];                                                       \
    _Pragma("unroll")                                                         \
    for (int mi = 0; mi < 4; mi++)                                            \
        _Pragma("unroll")                                                     \
        for (int ni = 0; ni < 4; ni++)                                        \
            _Pragma("unroll")                                                 \
            for (int r = 0; r < 4; r++) acc[mi][ni][r] = 0.f;                 \
    issue_stage1(sbase + 0 * STAGE_B1, A, B, bm, bn, 0, tid);                 \
    cp_commit();                                                              \
    issue_stage1(sbase + 1 * STAGE_B1, A, B, bm, bn, BK, tid);                \
    cp_commit();                                                              \
    int buf = 0, ibuf = 2;                                                    \
    for (int c = 0; c < NITER; c++) {                                         \
        cp_wait_1();                                                          \
        __syncthreads();                                                      \
        if (c + 2 < NITER)                                                    \
            issue_stage1(sbase + (uint32_t)ibuf * STAGE_B1, A, B,             \
                         bm, bn, (c + 2) * BK, tid);                          \
        cp_commit();                                                          \
        const uint32_t st = sbase + (uint32_t)buf * STAGE_B1;                 \
        const uint32_t tA = st + OFF_A1;                                      \
        const uint32_t tB = st + OFF_B1;                                      \
        _Pragma("unroll")                                                     \
        for (int ks = 0; ks < 2; ks++) {                                      \
            const int aCh = 2 * ks + aChL;                                    \
            const int bCh = 2 * ks + bChL;                                    \
            uint32_t a4[4][4], b2[4][2];                                      \
            _Pragma("unroll")                                                 \
            for (int mi = 0; mi < 4; mi++)                                    \
                ldmatrix_x4(a4[mi], tA + sw_off(wm + mi * 16 + aRowL, aCh));  \
            _Pragma("unroll")                                                 \
            for (int p = 0; p < 2; p++) {                                     \
                uint32_t t4[4];                                               \
                ldmatrix_x4(t4, tB + sw_off(wn + p * 16 + bRowL, bCh));       \
                b2[2 * p][0] = t4[0]; b2[2 * p][1] = t4[1];                   \
                b2[2 * p + 1][0] = t4[2]; b2[2 * p + 1][1] = t4[3];           \
            }                                                                 \
            _Pragma("unroll")                                                 \
            for (int mi = 0; mi < 4; mi++)                                    \
                _Pragma("unroll")                                             \
                for (int ni = 0; ni < 4; ni++)                                \
                    mma_f16(acc[mi][ni], a4[mi], b2[ni]);                     \
        }                                                                     \
        buf  = (buf == 2)  ? 0 : buf + 1;                                     \
        ibuf = (ibuf == 2) ? 0 : ibuf + 1;                                    \
    }

// Fused QKV projection (fp16 single pass, N=6144).
// Epilogue per region: Q/K -> RoPE rotate -> fp16 head-major; V -> fp16 head-major.
__global__ void __launch_bounds__(256, 2) mma_gemmQKV_kernel(
    const __half* __restrict__ A, const __half* __restrict__ B,
    const float2* __restrict__ tab,
    __half* __restrict__ Qo, __half* __restrict__ Ko, __half* __restrict__ Vo)
{
    extern __shared__ char sm_raw[];
    const uint32_t sbase = (smem_u32(sm_raw) + 127u) & ~127u;

    const int tid  = threadIdx.x;
    const int lane = tid & 31;
    const int w    = tid >> 5;
    const int wm   = (w & 1) * 64;
    const int wn   = (w >> 1) * 32;
    const int bm   = blockIdx.y * 128;
    const int bn   = blockIdx.x * 128;     // [0, 6144)

    const int g  = lane >> 3;
    const int li = lane & 7;
    const int aRowL = li + ((g & 1) << 3);
    const int aChL  = g >> 1;
    const int bRowL = li + ((g >> 1) << 3);
    const int bChL  = g & 1;

    GEMM1_MAINLOOP(A, B)

    const int gid = lane >> 2;
    const int tig = lane & 3;
    const int region = bn >> 11;           // 0=Q, 1=K, 2=V (CTA spans one region)
    __half* Out = (region == 0) ? Qo : (region == 1) ? Ko : Vo;
    const bool doRope = (region < 2);

#pragma unroll
    for (int mi = 0; mi < 4; mi++) {
        const int r0 = bm + wm + mi * 16 + gid;
        const int r1 = r0 + 8;
        const int b0 = r0 >> 11, s0 = r0 & 2047;
        const int b1 = r1 >> 11, s1 = r1 & 2047;
#pragma unroll
        for (int ni = 0; ni < 4; ni++) {
            int col = bn + wn + ni * 8 + tig * 2;
            int cc  = col & 2047;
            int h   = cc >> 7;
            int d   = cc & 127;
            float e0 = acc[mi][ni][0], o0 = acc[mi][ni][1];
            float e1 = acc[mi][ni][2], o1 = acc[mi][ni][3];
            if (doRope) {
                int i = d >> 1;
                float2 cs0 = tab[r0 * 64 + i];
                float2 cs1 = tab[r1 * 64 + i];
                float t;
                t  = e0 * cs0.x - o0 * cs0.y;
                o0 = e0 * cs0.y + o0 * cs0.x; e0 = t;
                t  = e1 * cs1.x - o1 * cs1.y;
                o1 = e1 * cs1.y + o1 * cs1.x; e1 = t;
            }
            size_t d0 = ((size_t)((b0 * N_HEADS + h) * SEQ + s0)) * HEAD_DIM + d;
            size_t d1 = ((size_t)((b1 * N_HEADS + h) * SEQ + s1)) * HEAD_DIM + d;
            *(__half2*)(Out + d0) = __floats2half2_rn(e0, o0);
            *(__half2*)(Out + d1) = __floats2half2_rn(e1, o1);
        }
    }
}

// fp16 GEMM, fp32 token-major epilogue (output projection)
__global__ void __launch_bounds__(256, 2) mma_gemm1_kernel(
    const __half* __restrict__ A, const __half* __restrict__ B,
    float* __restrict__ C, int ldc)
{
    extern __shared__ char sm_raw[];
    const uint32_t sbase = (smem_u32(sm_raw) + 127u) & ~127u;

    const int tid  = threadIdx.x;
    const int lane = tid & 31;
    const int w    = tid >> 5;
    const int wm   = (w & 1) * 64;
    const int wn   = (w >> 1) * 32;
    const int bm   = blockIdx.y * 128;
    const int bn   = blockIdx.x * 128;

    const int g  = lane >> 3;
    const int li = lane & 7;
    const int aRowL = li + ((g & 1) << 3);
    const int aChL  = g >> 1;
    const int bRowL = li + ((g >> 1) << 3);
    const int bChL  = g & 1;

    GEMM1_MAINLOOP(A, B)

    const int gid = lane >> 2;
    const int tig = lane & 3;
#pragma unroll
    for (int mi = 0; mi < 4; mi++) {
#pragma unroll
        for (int ni = 0; ni < 4; ni++) {
            int row = bm + wm + mi * 16 + gid;
            int col = bn + wn + ni * 8 + tig * 2;
            float2 v0 = make_float2(acc[mi][ni][0], acc[mi][ni][1]);
            float2 v1 = make_float2(acc[mi][ni][2], acc[mi][ni][3]);
            *(float2*)(C + (size_t)row * ldc + col) = v0;
            *(float2*)(C + (size_t)(row + 8) * ldc + col) = v1;
        }
    }
}

// ============================================================================
// flash v4: all-fp16 tensor-core causal attention.
// CTA: 64 queries x 1 head, 128 threads (4 warps x 16 q-rows).
// QK^T single fp16 pass; PV single fp16 pass. smem: Q,K,V fp16 = 48KB -> 3 CTAs/SM.
// ============================================================================
#define FQ 0
#define FK 16384
#define FV 32768
#define SMEM_FLASH (49152 + 128)

__device__ __forceinline__ uint32_t fsw(int row, int ch) {
    return (uint32_t)(row * 256 + ((ch ^ (row & 7)) << 4));
}

__global__ void __launch_bounds__(128, 3) flash2_kernel(
    const __half* __restrict__ Q, const __half* __restrict__ K,
    const __half* __restrict__ V,
    __half* __restrict__ Ctx)
{
    extern __shared__ char sm_raw[];
    const uint32_t sb = (smem_u32(sm_raw) + 127u) & ~127u;

    const int tid  = threadIdx.x;
    const int lane = tid & 31;
    const int w    = tid >> 5;
    const int bh   = blockIdx.y;
    const int q0   = (gridDim.x - 1 - blockIdx.x) * 64;   // heavy blocks first
    const size_t hbase = (size_t)bh * SEQ * HEAD_DIM;

    const int g2 = lane >> 3, li = lane & 7;
    const int aRow = w * 16 + ((g2 & 1) << 3) + li;
    const int aChS = g2 >> 1;
    const int bRowK = ((g2 >> 1) << 3) + li;
    const int bChK  = g2 & 1;
    const int vRowS = ((g2 & 1) << 3) + li;
    const int vChS  = g2 >> 1;
    const int gid = lane >> 2, tig = lane & 3;

    // prologue loads: Q tile + KV tile 0
#pragma unroll
    for (int j = 0; j < 8; j++) {
        int idx = tid + 128 * j; int row = idx >> 4; int ch = idx & 15;
        uint32_t so = fsw(row, ch);
        size_t gq = hbase + (size_t)(q0 + row) * HEAD_DIM + ch * 8;
        cp16(sb + FQ + so, Q + gq);
        size_t gk = hbase + (size_t)row * HEAD_DIM + ch * 8;   // k0 = 0
        cp16(sb + FK + so, K + gk);
        cp16(sb + FV + so, V + gk);
    }
    cp_commit();

    float o[16][4];
#pragma unroll
    for (int nb = 0; nb < 16; nb++)
#pragma unroll
        for (int r = 0; r < 4; r++) o[nb][r] = 0.f;
    float m0s = -1e30f, m1s = -1e30f, l0 = 0.f, l1 = 0.f;

    const float scale = 0.08838834764831845f;
    const int nt = q0 / 64 + 1;

    for (int kt = 0; kt < nt; kt++) {
        const int k0 = kt * 64;
        cp_wait_0();
        __syncthreads();

        // ---- S = Q K^T (single fp16 pass) ----
        float s[8][4];
#pragma unroll
        for (int ni = 0; ni < 8; ni++)
#pragma unroll
            for (int r = 0; r < 4; r++) s[ni][r] = 0.f;

#pragma unroll
        for (int kf = 0; kf < 8; kf++) {
            uint32_t aq[4];
            ldmatrix_x4(aq, sb + FQ + fsw(aRow, 2 * kf + aChS));
            uint32_t kb[8][2];
#pragma unroll
            for (int p = 0; p < 4; p++) {
                uint32_t t4[4];
                ldmatrix_x4(t4, sb + FK + fsw(p * 16 + bRowK, 2 * kf + bChK));
                kb[2*p][0] = t4[0]; kb[2*p][1] = t4[1];
                kb[2*p+1][0] = t4[2]; kb[2*p+1][1] = t4[3];
            }
#pragma unroll
            for (int ni = 0; ni < 8; ni++) mma_f16(s[ni], aq, kb[ni]);
        }

        // ---- online softmax ----
        const bool diag = (k0 == q0);
        const int row0 = q0 + w * 16 + gid;
        float mx0 = -1e30f, mx1 = -1e30f;
#pragma unroll
        for (int ni = 0; ni < 8; ni++) {
#pragma unroll
            for (int r = 0; r < 4; r++) {
                float v = s[ni][r] * scale;
                if (diag) {
                    int col = k0 + ni * 8 + tig * 2 + (r & 1);
                    int row = row0 + ((r >> 1) << 3);
                    if (col > row) v = -1e30f;
                }
                s[ni][r] = v;
                if (r < 2) mx0 = fmaxf(mx0, v); else mx1 = fmaxf(mx1, v);
            }
        }
        mx0 = fmaxf(mx0, __shfl_xor_sync(0xffffffffu, mx0, 1));
        mx0 = fmaxf(mx0, __shfl_xor_sync(0xffffffffu, mx0, 2));
        mx1 = fmaxf(mx1, __shfl_xor_sync(0xffffffffu, mx1, 1));
        mx1 = fmaxf(mx1, __shfl_xor_sync(0xffffffffu, mx1, 2));

        float mn0 = fmaxf(m0s, mx0), mn1 = fmaxf(m1s, mx1);
        float a0 = __expf(m0s - mn0), a1 = __expf(m1s - mn1);
        float ls0 = 0.f, ls1 = 0.f;
#pragma unroll
        for (int ni = 0; ni < 8; ni++) {
            s[ni][0] = __expf(s[ni][0] - mn0); ls0 += s[ni][0];
            s[ni][1] = __expf(s[ni][1] - mn0); ls0 += s[ni][1];
            s[ni][2] = __expf(s[ni][2] - mn1); ls1 += s[ni][2];
            s[ni][3] = __expf(s[ni][3] - mn1); ls1 += s[ni][3];
        }
        ls0 += __shfl_xor_sync(0xffffffffu, ls0, 1);
        ls0 += __shfl_xor_sync(0xffffffffu, ls0, 2);
        ls1 += __shfl_xor_sync(0xffffffffu, ls1, 1);
        ls1 += __shfl_xor_sync(0xffffffffu, ls1, 2);
        l0 = l0 * a0 + ls0; l1 = l1 * a1 + ls1;
        m0s = mn0; m1s = mn1;
#pragma unroll
        for (int nb = 0; nb < 16; nb++) {
            o[nb][0] *= a0; o[nb][1] *= a0; o[nb][2] *= a1; o[nb][3] *= a1;
        }

        // ---- P -> fp16 fragments ----
        uint32_t P[4][4];
#pragma unroll
        for (int j = 0; j < 4; j++) {
            P[j][0] = pack_h2(s[2*j][0],   s[2*j][1]);
            P[j][1] = pack_h2(s[2*j][2],   s[2*j][3]);
            P[j][2] = pack_h2(s[2*j+1][0], s[2*j+1][1]);
            P[j][3] = pack_h2(s[2*j+1][2], s[2*j+1][3]);
        }

        // ---- ctx += P * V (single fp16 pass) ----
#pragma unroll
        for (int j = 0; j < 4; j++) {
#pragma unroll
            for (int p = 0; p < 8; p++) {
                uint32_t t4[4];
                ldmatrix_x4_t(t4, sb + FV + fsw(j * 16 + vRowS, 2 * p + vChS));
                uint32_t b0[2] = {t4[0], t4[1]}, b1[2] = {t4[2], t4[3]};
                mma_f16(o[2*p],   P[j], b0);
                mma_f16(o[2*p+1], P[j], b1);
            }
        }

        // prefetch next KV tile
        if (kt + 1 < nt) {
            __syncthreads();
            const int nk0 = (kt + 1) * 64;
#pragma unroll
            for (int j = 0; j < 8; j++) {
                int idx = tid + 128 * j; int row = idx >> 4; int ch = idx & 15;
                uint32_t so = fsw(row, ch);
                size_t gk = hbase + (size_t)(nk0 + row) * HEAD_DIM + ch * 8;
                cp16(sb + FK + so, K + gk);
                cp16(sb + FV + so, V + gk);
            }
            cp_commit();
        }
    }

    // ---- write ctx (fp16, token-major) ----
    float i0 = 1.0f / l0, i1 = 1.0f / l1;
    const int b = bh >> 4, h = bh & 15;
    size_t t0 = (size_t)(b * SEQ + q0 + w * 16 + gid) * D_MODEL + h * HEAD_DIM;
    size_t t1 = t0 + (size_t)8 * D_MODEL;
#pragma unroll
    for (int nb = 0; nb < 16; nb++) {
        int col = nb * 8 + tig * 2;
        *(__half2*)(Ctx + t0 + col) = __floats2half2_rn(o[nb][0] * i0, o[nb][1] * i0);
        *(__half2*)(Ctx + t1 + col) = __floats2half2_rn(o[nb][2] * i1, o[nb][3] * i1);
    }
}

// ============================================================================
// launch
// ============================================================================
extern "C" void kernel_launch(void* const* d_in, const int* in_sizes, int n_in,
                              void* d_out, int out_size)
{
    const float* x   = (const float*)d_in[0];
    const int*   pos = (const int*)  d_in[1];
    const float* Wq  = (const float*)d_in[2];
    const float* Wk  = (const float*)d_in[3];
    const float* Wv  = (const float*)d_in[4];
    const float* Wo  = (const float*)d_in[5];
    float* out = (float*)d_out;

    __half *xf, *cf, *Wqkvf, *Wof, *fQ, *fK, *fV;
    float2* tab;
    cudaGetSymbolAddress((void**)&xf, g_xf);
    cudaGetSymbolAddress((void**)&cf, g_cf);
    cudaGetSymbolAddress((void**)&Wqkvf, g_Wqkvf);
    cudaGetSymbolAddress((void**)&Wof, g_Wof);
    cudaGetSymbolAddress((void**)&fQ, g_fQ);
    cudaGetSymbolAddress((void**)&fK, g_fK);
    cudaGetSymbolAddress((void**)&fV, g_fV);
    cudaGetSymbolAddress((void**)&tab, g_tab);

    cudaFuncSetAttribute(mma_gemmQKV_kernel,
                         cudaFuncAttributeMaxDynamicSharedMemorySize, SMEM_G1);
    cudaFuncSetAttribute(mma_gemm1_kernel,
                         cudaFuncAttributeMaxDynamicSharedMemorySize, SMEM_G1);
    cudaFuncSetAttribute(flash2_kernel,
                         cudaFuncAttributeMaxDynamicSharedMemorySize, SMEM_FLASH);

    const int x_n4 = (M_TOT * D_MODEL) / 4;
    const int w_n4 = (D_MODEL * D_MODEL) / 4;

    // conversions + rope table
    cvt_h_kernel<<<(x_n4 + 255) / 256, 256>>>(x, xf, x_n4);
    dim3 wGrid((w_n4 + 255) / 256, 4);
    cvt_w4_kernel<<<wGrid, 256>>>(Wq, Wk, Wv, Wo, Wqkvf, Wof, w_n4);
    rope_tab_kernel<<<(M_TOT * 64 + 255) / 256, 256>>>(pos, tab);

    // fused QKV projection (fp16 single pass, N=6144) + RoPE epilogue -> fp16 head-major
    dim3 qkvGrid(N_QKV / 128, M_TOT / 128);     // (48, 32)
    mma_gemmQKV_kernel<<<qkvGrid, 256, SMEM_G1>>>(xf, Wqkvf, tab, fQ, fK, fV);

    // all-fp16 tensor-core flash attention -> fp16 ctx (token-major)
    dim3 fGrid(SEQ / 64, N_BH);                 // (32, 32)
    flash2_kernel<<<fGrid, 128, SMEM_FLASH>>>(fQ, fK, fV, cf);

    // output projection (fp16) -> fp32 out
    dim3 oGrid(D_MODEL / 128, M_TOT / 128);     // (16, 32)
    mma_gemm1_kernel<<<oGrid, 256, SMEM_G1>>>(cf, Wof, out, D_MODEL);
}

// round 16
// speedup vs baseline: 19.1925x; 1.0548x over previous
#include <cuda_runtime.h>
#include <cuda_bf16.h>
#include <cuda_fp16.h>
#include <cstdint>
#include <string.h>
#include <math.h>

// ---------------- problem constants ----------------
#define D_MODEL  2048
#define N_HEADS  16
#define HEAD_DIM 128
#define BATCH    2
#define SEQ      2048
#define M_TOT    (BATCH * SEQ)      // 4096 rows
#define N_QKV    (3 * D_MODEL)      // 6144 fused QKV width
#define N_BH     (BATCH * N_HEADS)  // 32 head-batches

// ---------------- scratch (alloc-free rule: __device__ globals) ----------------
__device__ __half g_xf   [M_TOT * D_MODEL];         // x in fp16
__device__ __half g_cf   [M_TOT * D_MODEL];         // flash ctx (fp16, token-major)
__device__ __half g_Wqkvf[3 * D_MODEL * D_MODEL];   // [Wq;Wk;Wv] fp16
__device__ __half g_Wof  [D_MODEL * D_MODEL];

// head-major flash operands [bh][seq][128], all fp16
__device__ __half g_fQ[N_BH * SEQ * HEAD_DIM];
__device__ __half g_fK[N_BH * SEQ * HEAD_DIM];
__device__ __half g_fV[N_BH * SEQ * HEAD_DIM];

// rope table: [row 0..4095][i 0..63] -> (cos, sin)
__device__ float2 g_tab[M_TOT * 64];

// ============================================================================
// PTX helpers (compute_103-safe)
// ============================================================================
__device__ __forceinline__ uint32_t smem_u32(const void* p) {
    uint32_t a;
    asm("{ .reg .u64 t; cvta.to.shared.u64 t, %1; cvt.u32.u64 %0, t; }" : "=r"(a) : "l"(p));
    return a;
}
__device__ __forceinline__ void ldmatrix_x4(uint32_t* r, uint32_t addr) {
    asm volatile("ldmatrix.sync.aligned.m8n8.x4.shared.b16 {%0,%1,%2,%3}, [%4];"
                 : "=r"(r[0]), "=r"(r[1]), "=r"(r[2]), "=r"(r[3]) : "r"(addr));
}
__device__ __forceinline__ void ldmatrix_x4_t(uint32_t* r, uint32_t addr) {
    asm volatile("ldmatrix.sync.aligned.m8n8.x4.trans.shared.b16 {%0,%1,%2,%3}, [%4];"
                 : "=r"(r[0]), "=r"(r[1]), "=r"(r[2]), "=r"(r[3]) : "r"(addr));
}
__device__ __forceinline__ void mma_f16(float* c, const uint32_t* a, const uint32_t* b) {
    asm volatile(
        "mma.sync.aligned.m16n8k16.row.col.f32.f16.f16.f32 "
        "{%0,%1,%2,%3}, {%4,%5,%6,%7}, {%8,%9}, {%0,%1,%2,%3};"
        : "+f"(c[0]), "+f"(c[1]), "+f"(c[2]), "+f"(c[3])
        : "r"(a[0]), "r"(a[1]), "r"(a[2]), "r"(a[3]), "r"(b[0]), "r"(b[1]));
}
__device__ __forceinline__ void cp16(uint32_t s, const void* g) {
    asm volatile("cp.async.cg.shared.global [%0], [%1], 16;" :: "r"(s), "l"(g));
}
__device__ __forceinline__ void cp_commit() {
    asm volatile("cp.async.commit_group;" ::: "memory");
}
__device__ __forceinline__ void cp_wait_1() {
    asm volatile("cp.async.wait_group 1;" ::: "memory");
}
__device__ __forceinline__ void cp_wait_0() {
    asm volatile("cp.async.wait_group 0;" ::: "memory");
}
__device__ __forceinline__ uint32_t pack_h2(float a, float b) {
    __half2 h = __floats2half2_rn(a, b);
    uint32_t u; memcpy(&u, &h, 4);
    return u;
}

// ============================================================================
// conversions + rope table
// ============================================================================
__global__ void cvt_h_kernel(const float* __restrict__ in,
                             __half* __restrict__ out, int n4)
{
    int i = blockIdx.x * blockDim.x + threadIdx.x;
    if (i >= n4) return;
    float4 v = ((const float4*)in)[i];
    __half2* op = (__half2*)out;
    op[2*i]   = __floats2half2_rn(v.x, v.y);
    op[2*i+1] = __floats2half2_rn(v.z, v.w);
}

__global__ void cvt_w4_kernel(const float* __restrict__ wq, const float* __restrict__ wk,
                              const float* __restrict__ wv, const float* __restrict__ wo,
                              __half* __restrict__ qkv, __half* __restrict__ o, int n4each)
{
    int i = blockIdx.x * blockDim.x + threadIdx.x;
    if (i >= n4each) return;
    const float* in;
    __half* out;
    switch (blockIdx.y) {
        case 0: in = wq; out = qkv; break;
        case 1: in = wk; out = qkv + 1 * (size_t)D_MODEL * D_MODEL; break;
        case 2: in = wv; out = qkv + 2 * (size_t)D_MODEL * D_MODEL; break;
        default: in = wo; out = o; break;
    }
    float4 vv = ((const float4*)in)[i];
    __half2* op = (__half2*)out;
    op[2*i]   = __floats2half2_rn(vv.x, vv.y);
    op[2*i+1] = __floats2half2_rn(vv.z, vv.w);
}

__global__ void rope_tab_kernel(const int* __restrict__ pos, float2* __restrict__ tab)
{
    int idx = blockIdx.x * blockDim.x + threadIdx.x;
    if (idx >= M_TOT * 64) return;
    int i   = idx & 63;
    int row = idx >> 6;
    int p   = pos[row];
    float inv_freq = powf(10000.0f, -(2.0f * (float)i) / 128.0f);
    float sn, cs;
    sincosf((float)p * inv_freq, &sn, &cs);
    tab[idx] = make_float2(cs, sn);
}

// ============================================================================
// GEMM v2: CTA 128x128, 256 thr, warp tile 64x32, BK=64 (4 k16-steps/stage),
// 3-stage cp.async (32KB/stage, 96KB), one barrier per BK, register-level
// fragment double-buffer across k16 steps.
// SMEM tile rows are 128B (64 halves), swizzle ch ^= row&7 (8-period).
// ============================================================================
#define BK64      64
#define NIT64     (D_MODEL / BK64)        // 32

__device__ __forceinline__ uint32_t sw64(int row, int ch) {
    return (uint32_t)(row * 128 + ((ch ^ (row & 7)) << 4));
}

#define T_A64     0
#define T_B64     16384
#define STAGE64   32768                   // 32 KB per stage
#define SMEM_G64  (3 * STAGE64 + 128)

__device__ __forceinline__ void issue_stage64(
    uint32_t stage,
    const __half* __restrict__ A, const __half* __restrict__ B,
    int bm, int bn, int k0, int tid)
{
#pragma unroll
    for (int j = 0; j < 4; j++) {
        int idx = tid + 256 * j;            // 0..1023
        int row = idx >> 3;                 // 0..127
        int ch  = idx & 7;                  // 16B chunk in 128B row
        uint32_t so = sw64(row, ch);
        cp16(stage + T_A64 + so, A + (size_t)(bm + row) * D_MODEL + k0 + ch * 8);
        cp16(stage + T_B64 + so, B + (size_t)(bn + row) * D_MODEL + k0 + ch * 8);
    }
}

// fragment load helpers (warp tile 64x32)
#define LOAD_AFRAG(dst, tA, ks)                                               \
    _Pragma("unroll")                                                         \
    for (int mi = 0; mi < 4; mi++)                                            \
        ldmatrix_x4((dst)[mi], (tA) + sw64(wm + mi * 16 + aRowL, 2*(ks) + aChL));

#define LOAD_BFRAG(dst, tB, ks)                                               \
    _Pragma("unroll")                                                         \
    for (int p = 0; p < 2; p++) {                                             \
        uint32_t t4[4];                                                       \
        ldmatrix_x4(t4, (tB) + sw64(wn + p * 16 + bRowL, 2*(ks) + bChL));     \
        (dst)[2*p][0] = t4[0]; (dst)[2*p][1] = t4[1];                         \
        (dst)[2*p+1][0] = t4[2]; (dst)[2*p+1][1] = t4[3];                     \
    }

#define GEMM64_MAINLOOP(A, B)                                                 \
    float acc[4][4][4];                                                       \
    _Pragma("unroll")                                                         \
    for (int mi = 0; mi < 4; mi++)                                            \
        _Pragma("unroll")                                                     \
        for (int ni = 0; ni < 4; ni++)                                        \
            _Pragma("unroll")                                                 \
            for (int r = 0; r < 4; r++) acc[mi][ni][r] = 0.f;                 \
    issue_stage64(sbase + 0 * STAGE64, A, B, bm, bn, 0, tid);                 \
    cp_commit();                                                              \
    issue_stage64(sbase + 1 * STAGE64, A, B, bm, bn, BK64, tid);              \
    cp_commit();                                                              \
    int buf = 0, ibuf = 2;                                                    \
    for (int c = 0; c < NIT64; c++) {                                         \
        cp_wait_1();                                                          \
        __syncthreads();                                                      \
        if (c + 2 < NIT64)                                                    \
            issue_stage64(sbase + (uint32_t)ibuf * STAGE64, A, B,             \
                          bm, bn, (c + 2) * BK64, tid);                       \
        cp_commit();                                                          \
        const uint32_t tA = sbase + (uint32_t)buf * STAGE64 + T_A64;          \
        const uint32_t tB = sbase + (uint32_t)buf * STAGE64 + T_B64;          \
        uint32_t aF[2][4][4], bF[2][4][2];                                    \
        LOAD_AFRAG(aF[0], tA, 0)                                              \
        LOAD_BFRAG(bF[0], tB, 0)                                              \
        _Pragma("unroll")                                                     \
        for (int ks = 0; ks < 4; ks++) {                                      \
            const int cur = ks & 1, nxt = cur ^ 1;                            \
            if (ks < 3) {                                                     \
                LOAD_AFRAG(aF[nxt], tA, ks + 1)                               \
                LOAD_BFRAG(bF[nxt], tB, ks + 1)                               \
            }                                                                 \
            _Pragma("unroll")                                                 \
            for (int mi = 0; mi < 4; mi++)                                    \
                _Pragma("unroll")                                             \
                for (int ni = 0; ni < 4; ni++)                                \
                    mma_f16(acc[mi][ni], aF[cur][mi], bF[cur][ni]);           \
        }                                                                     \
        buf  = (buf == 2)  ? 0 : buf + 1;                                     \
        ibuf = (ibuf == 2) ? 0 : ibuf + 1;                                    \
    }

// Fused QKV projection (fp16 single pass, N=6144).
// Epilogue per region: Q/K -> RoPE rotate -> fp16 head-major; V -> fp16 head-major.
__global__ void __launch_bounds__(256, 2) mma_gemmQKV_kernel(
    const __half* __restrict__ A, const __half* __restrict__ B,
    const float2* __restrict__ tab,
    __half* __restrict__ Qo, __half* __restrict__ Ko, __half* __restrict__ Vo)
{
    extern __shared__ char sm_raw[];
    const uint32_t sbase = (smem_u32(sm_raw) + 127u) & ~127u;

    const int tid  = threadIdx.x;
    const int lane = tid & 31;
    const int w    = tid >> 5;
    const int wm   = (w & 1) * 64;
    const int wn   = (w >> 1) * 32;
    const int bm   = blockIdx.y * 128;
    const int bn   = blockIdx.x * 128;     // [0, 6144)

    const int g  = lane >> 3;
    const int li = lane & 7;
    const int aRowL = li + ((g & 1) << 3);
    const int aChL  = g >> 1;
    const int bRowL = li + ((g >> 1) << 3);
    const int bChL  = g & 1;

    GEMM64_MAINLOOP(A, B)

    const int gid = lane >> 2;
    const int tig = lane & 3;
    const int region = bn >> 11;           // 0=Q, 1=K, 2=V
    __half* Out = (region == 0) ? Qo : (region == 1) ? Ko : Vo;
    const bool doRope = (region < 2);

#pragma unroll
    for (int mi = 0; mi < 4; mi++) {
        const int r0 = bm + wm + mi * 16 + gid;
        const int r1 = r0 + 8;
        const int b0 = r0 >> 11, s0 = r0 & 2047;
        const int b1 = r1 >> 11, s1 = r1 & 2047;
#pragma unroll
        for (int ni = 0; ni < 4; ni++) {
            int col = bn + wn + ni * 8 + tig * 2;
            int cc  = col & 2047;
            int h   = cc >> 7;
            int d   = cc & 127;
            float e0 = acc[mi][ni][0], o0 = acc[mi][ni][1];
            float e1 = acc[mi][ni][2], o1 = acc[mi][ni][3];
            if (doRope) {
                int i = d >> 1;
                float2 cs0 = tab[r0 * 64 + i];
                float2 cs1 = tab[r1 * 64 + i];
                float t;
                t  = e0 * cs0.x - o0 * cs0.y;
                o0 = e0 * cs0.y + o0 * cs0.x; e0 = t;
                t  = e1 * cs1.x - o1 * cs1.y;
                o1 = e1 * cs1.y + o1 * cs1.x; e1 = t;
            }
            size_t d0 = ((size_t)((b0 * N_HEADS + h) * SEQ + s0)) * HEAD_DIM + d;
            size_t d1 = ((size_t)((b1 * N_HEADS + h) * SEQ + s1)) * HEAD_DIM + d;
            *(__half2*)(Out + d0) = __floats2half2_rn(e0, o0);
            *(__half2*)(Out + d1) = __floats2half2_rn(e1, o1);
        }
    }
}

// fp16 GEMM, fp32 token-major epilogue (output projection)
__global__ void __launch_bounds__(256, 2) mma_gemm1_kernel(
    const __half* __restrict__ A, const __half* __restrict__ B,
    float* __restrict__ C, int ldc)
{
    extern __shared__ char sm_raw[];
    const uint32_t sbase = (smem_u32(sm_raw) + 127u) & ~127u;

    const int tid  = threadIdx.x;
    const int lane = tid & 31;
    const int w    = tid >> 5;
    const int wm   = (w & 1) * 64;
    const int wn   = (w >> 1) * 32;
    const int bm   = blockIdx.y * 128;
    const int bn   = blockIdx.x * 128;

    const int g  = lane >> 3;
    const int li = lane & 7;
    const int aRowL = li + ((g & 1) << 3);
    const int aChL  = g >> 1;
    const int bRowL = li + ((g >> 1) << 3);
    const int bChL  = g & 1;

    GEMM64_MAINLOOP(A, B)

    const int gid = lane >> 2;
    const int tig = lane & 3;
#pragma unroll
    for (int mi = 0; mi < 4; mi++) {
#pragma unroll
        for (int ni = 0; ni < 4; ni++) {
            int row = bm + wm + mi * 16 + gid;
            int col = bn + wn + ni * 8 + tig * 2;
            float2 v0 = make_float2(acc[mi][ni][0], acc[mi][ni][1]);
            float2 v1 = make_float2(acc[mi][ni][2], acc[mi][ni][3]);
            *(float2*)(C + (size_t)row * ldc + col) = v0;
            *(float2*)(C + (size_t)(row + 8) * ldc + col) = v1;
        }
    }
}

// ============================================================================
// flash v4 (verified R15): all-fp16 tensor-core causal attention.
// CTA: 64 queries x 1 head, 128 threads, 48KB smem -> 3 CTAs/SM.
// ============================================================================
#define FQ 0
#define FK 16384
#define FV 32768
#define SMEM_FLASH (49152 + 128)

__device__ __forceinline__ uint32_t fsw(int row, int ch) {
    return (uint32_t)(row * 256 + ((ch ^ (row & 7)) << 4));
}

__global__ void __launch_bounds__(128, 3) flash2_kernel(
    const __half* __restrict__ Q, const __half* __restrict__ K,
    const __half* __restrict__ V,
    __half* __restrict__ Ctx)
{
    extern __shared__ char sm_raw[];
    const uint32_t sb = (smem_u32(sm_raw) + 127u) & ~127u;

    const int tid  = threadIdx.x;
    const int lane = tid & 31;
    const int w    = tid >> 5;
    const int bh   = blockIdx.y;
    const int q0   = (gridDim.x - 1 - blockIdx.x) * 64;
    const size_t hbase = (size_t)bh * SEQ * HEAD_DIM;

    const int g2 = lane >> 3, li = lane & 7;
    const int aRow = w * 16 + ((g2 & 1) << 3) + li;
    const int aChS = g2 >> 1;
    const int bRowK = ((g2 >> 1) << 3) + li;
    const int bChK  = g2 & 1;
    const int vRowS = ((g2 & 1) << 3) + li;
    const int vChS  = g2 >> 1;
    const int gid = lane >> 2, tig = lane & 3;

#pragma unroll
    for (int j = 0; j < 8; j++) {
        int idx = tid + 128 * j; int row = idx >> 4; int ch = idx & 15;
        uint32_t so = fsw(row, ch);
        size_t gq = hbase + (size_t)(q0 + row) * HEAD_DIM + ch * 8;
        cp16(sb + FQ + so, Q + gq);
        size_t gk = hbase + (size_t)row * HEAD_DIM + ch * 8;
        cp16(sb + FK + so, K + gk);
        cp16(sb + FV + so, V + gk);
    }
    cp_commit();

    float o[16][4];
#pragma unroll
    for (int nb = 0; nb < 16; nb++)
#pragma unroll
        for (int r = 0; r < 4; r++) o[nb][r] = 0.f;
    float m0s = -1e30f, m1s = -1e30f, l0 = 0.f, l1 = 0.f;

    const float scale = 0.08838834764831845f;
    const int nt = q0 / 64 + 1;

    for (int kt = 0; kt < nt; kt++) {
        const int k0 = kt * 64;
        cp_wait_0();
        __syncthreads();

        float s[8][4];
#pragma unroll
        for (int ni = 0; ni < 8; ni++)
#pragma unroll
            for (int r = 0; r < 4; r++) s[ni][r] = 0.f;

#pragma unroll
        for (int kf = 0; kf < 8; kf++) {
            uint32_t aq[4];
            ldmatrix_x4(aq, sb + FQ + fsw(aRow, 2 * kf + aChS));
            uint32_t kb[8][2];
#pragma unroll
            for (int p = 0; p < 4; p++) {
                uint32_t t4[4];
                ldmatrix_x4(t4, sb + FK + fsw(p * 16 + bRowK, 2 * kf + bChK));
                kb[2*p][0] = t4[0]; kb[2*p][1] = t4[1];
                kb[2*p+1][0] = t4[2]; kb[2*p+1][1] = t4[3];
            }
#pragma unroll
            for (int ni = 0; ni < 8; ni++) mma_f16(s[ni], aq, kb[ni]);
        }

        const bool diag = (k0 == q0);
        const int row0 = q0 + w * 16 + gid;
        float mx0 = -1e30f, mx1 = -1e30f;
#pragma unroll
        for (int ni = 0; ni < 8; ni++) {
#pragma unroll
            for (int r = 0; r < 4; r++) {
                float v = s[ni][r] * scale;
                if (diag) {
                    int col = k0 + ni * 8 + tig * 2 + (r & 1);
                    int row = row0 + ((r >> 1) << 3);
                    if (col > row) v = -1e30f;
                }
                s[ni][r] = v;
                if (r < 2) mx0 = fmaxf(mx0, v); else mx1 = fmaxf(mx1, v);
            }
        }
        mx0 = fmaxf(mx0, __shfl_xor_sync(0xffffffffu, mx0, 1));
        mx0 = fmaxf(mx0, __shfl_xor_sync(0xffffffffu, mx0, 2));
        mx1 = fmaxf(mx1, __shfl_xor_sync(0xffffffffu, mx1, 1));
        mx1 = fmaxf(mx1, __shfl_xor_sync(0xffffffffu, mx1, 2));

        float mn0 = fmaxf(m0s, mx0), mn1 = fmaxf(m1s, mx1);
        float a0 = __expf(m0s - mn0), a1 = __expf(m1s - mn1);
        float ls0 = 0.f, ls1 = 0.f;
#pragma unroll
        for (int ni = 0; ni < 8; ni++) {
            s[ni][0] = __expf(s[ni][0] - mn0); ls0 += s[ni][0];
            s[ni][1] = __expf(s[ni][1] - mn0); ls0 += s[ni][1];
            s[ni][2] = __expf(s[ni][2] - mn1); ls1 += s[ni][2];
            s[ni][3] = __expf(s[ni][3] - mn1); ls1 += s[ni][3];
        }
        ls0 += __shfl_xor_sync(0xffffffffu, ls0, 1);
        ls0 += __shfl_xor_sync(0xffffffffu, ls0, 2);
        ls1 += __shfl_xor_sync(0xffffffffu, ls1, 1);
        ls1 += __shfl_xor_sync(0xffffffffu, ls1, 2);
        l0 = l0 * a0 + ls0; l1 = l1 * a1 + ls1;
        m0s = mn0; m1s = mn1;
#pragma unroll
        for (int nb = 0; nb < 16; nb++) {
            o[nb][0] *= a0; o[nb][1] *= a0; o[nb][2] *= a1; o[nb][3] *= a1;
        }

        uint32_t P[4][4];
#pragma unroll
        for (int j = 0; j < 4; j++) {
            P[j][0] = pack_h2(s[2*j][0],   s[2*j][1]);
            P[j][1] = pack_h2(s[2*j][2],   s[2*j][3]);
            P[j][2] = pack_h2(s[2*j+1][0], s[2*j+1][1]);
            P[j][3] = pack_h2(s[2*j+1][2], s[2*j+1][3]);
        }

#pragma unroll
        for (int j = 0; j < 4; j++) {
#pragma unroll
            for (int p = 0; p < 8; p++) {
                uint32_t t4[4];
                ldmatrix_x4_t(t4, sb + FV + fsw(j * 16 + vRowS, 2 * p + vChS));
                uint32_t b0[2] = {t4[0], t4[1]}, b1[2] = {t4[2], t4[3]};
                mma_f16(o[2*p],   P[j], b0);
                mma_f16(o[2*p+1], P[j], b1);
            }
        }

        if (kt + 1 < nt) {
            __syncthreads();
            const int nk0 = (kt + 1) * 64;
#pragma unroll
            for (int j = 0; j < 8; j++) {
                int idx = tid + 128 * j; int row = idx >> 4; int ch = idx & 15;
                uint32_t so = fsw(row, ch);
                size_t gk = hbase + (size_t)(nk0 + row) * HEAD_DIM + ch * 8;
                cp16(sb + FK + so, K + gk);
                cp16(sb + FV + so, V + gk);
            }
            cp_commit();
        }
    }

    float i0 = 1.0f / l0, i1 = 1.0f / l1;
    const int b = bh >> 4, h = bh & 15;
    size_t t0 = (size_t)(b * SEQ + q0 + w * 16 + gid) * D_MODEL + h * HEAD_DIM;
    size_t t1 = t0 + (size_t)8 * D_MODEL;
#pragma unroll
    for (int nb = 0; nb < 16; nb++) {
        int col = nb * 8 + tig * 2;
        *(__half2*)(Ctx + t0 + col) = __floats2half2_rn(o[nb][0] * i0, o[nb][1] * i0);
        *(__half2*)(Ctx + t1 + col) = __floats2half2_rn(o[nb][2] * i1, o[nb][3] * i1);
    }
}

// ============================================================================
// launch
// ============================================================================
extern "C" void kernel_launch(void* const* d_in, const int* in_sizes, int n_in,
                              void* d_out, int out_size)
{
    const float* x   = (const float*)d_in[0];
    const int*   pos = (const int*)  d_in[1];
    const float* Wq  = (const float*)d_in[2];
    const float* Wk  = (const float*)d_in[3];
    const float* Wv  = (const float*)d_in[4];
    const float* Wo  = (const float*)d_in[5];
    float* out = (float*)d_out;

    __half *xf, *cf, *Wqkvf, *Wof, *fQ, *fK, *fV;
    float2* tab;
    cudaGetSymbolAddress((void**)&xf, g_xf);
    cudaGetSymbolAddress((void**)&cf, g_cf);
    cudaGetSymbolAddress((void**)&Wqkvf, g_Wqkvf);
    cudaGetSymbolAddress((void**)&Wof, g_Wof);
    cudaGetSymbolAddress((void**)&fQ, g_fQ);
    cudaGetSymbolAddress((void**)&fK, g_fK);
    cudaGetSymbolAddress((void**)&fV, g_fV);
    cudaGetSymbolAddress((void**)&tab, g_tab);

    cudaFuncSetAttribute(mma_gemmQKV_kernel,
                         cudaFuncAttributeMaxDynamicSharedMemorySize, SMEM_G64);
    cudaFuncSetAttribute(mma_gemm1_kernel,
                         cudaFuncAttributeMaxDynamicSharedMemorySize, SMEM_G64);
    cudaFuncSetAttribute(flash2_kernel,
                         cudaFuncAttributeMaxDynamicSharedMemorySize, SMEM_FLASH);

    const int x_n4 = (M_TOT * D_MODEL) / 4;
    const int w_n4 = (D_MODEL * D_MODEL) / 4;

    // conversions + rope table
    cvt_h_kernel<<<(x_n4 + 255) / 256, 256>>>(x, xf, x_n4);
    dim3 wGrid((w_n4 + 255) / 256, 4);
    cvt_w4_kernel<<<wGrid, 256>>>(Wq, Wk, Wv, Wo, Wqkvf, Wof, w_n4);
    rope_tab_kernel<<<(M_TOT * 64 + 255) / 256, 256>>>(pos, tab);

    // fused QKV projection (fp16, BK=64 pipelined) + RoPE epilogue -> fp16 head-major
    dim3 qkvGrid(N_QKV / 128, M_TOT / 128);     // (48, 32)
    mma_gemmQKV_kernel<<<qkvGrid, 256, SMEM_G64>>>(xf, Wqkvf, tab, fQ, fK, fV);

    // all-fp16 tensor-core flash attention -> fp16 ctx (token-major)
    dim3 fGrid(SEQ / 64, N_BH);                 // (32, 32)
    flash2_kernel<<<fGrid, 128, SMEM_FLASH>>>(fQ, fK, fV, cf);

    // output projection (fp16) -> fp32 out
    dim3 oGrid(D_MODEL / 128, M_TOT / 128);     // (16, 32)
    mma_gemm1_kernel<<<oGrid, 256, SMEM_G64>>>(cf, Wof, out, D_MODEL);
}